// round 9
// baseline (speedup 1.0000x reference)
#include <cuda_runtime.h>
#include <cuda_bf16.h>
#include <math.h>
#include <stdint.h>

// Problem constants
#define Bc   8
#define Sc   512
#define Dc   1024
#define Hc   16
#define DHc  64
#define Mc   1024
#define DFc  4096
#define Vc   32000
#define Lc   6

typedef __nv_bfloat16 bf16;

// ---------------------------------------------------------------------------
// Scratch (device globals)
// ---------------------------------------------------------------------------
__device__ float g_x[Bc * Sc * Dc];        // residual stream fp32
__device__ float g_q[Bc * Sc * Dc];
__device__ float g_k[Bc * Mc * Dc];
__device__ float g_v[Bc * Mc * Dc];
__device__ float g_o[Bc * Sc * Dc];
// hi/lo bf16 activation mirrors (GEMM A-side inputs)
__device__ bf16 g_xhi[Bc * Sc * Dc],  g_xlo[Bc * Sc * Dc];
__device__ bf16 g_ahi[Bc * Sc * Dc],  g_alo[Bc * Sc * Dc];
__device__ bf16 g_fhi[Bc * Sc * DFc], g_flo[Bc * Sc * DFc];
__device__ bf16 g_ehi[Bc * Mc * Dc],  g_elo[Bc * Mc * Dc];

// Pre-converted weights: [N,K] bf16 hi/lo.
#define WOFF_LAYER 16777216ull
#define WOFF_W1    8388608ull
#define WOFF_W2    12582912ull
#define EOFF       100663296ull
#define WTOTAL     133431296ull
__device__ bf16 g_whi[WTOTAL];
__device__ bf16 g_wlo[WTOTAL];

// ===========================================================================
// helpers
// ===========================================================================
__device__ __forceinline__ uint32_t smem_u32(const void* p) {
    uint32_t a;
    asm("{ .reg .u64 t; cvta.to.shared.u64 t, %1; cvt.u32.u64 %0, t; }"
        : "=r"(a) : "l"(p));
    return a;
}

__device__ __forceinline__ void mma_bf16(float* d, const uint32_t* a, const uint32_t* b) {
    asm volatile(
        "mma.sync.aligned.m16n8k16.row.col.f32.bf16.bf16.f32 "
        "{%0,%1,%2,%3}, {%4,%5,%6,%7}, {%8,%9}, {%0,%1,%2,%3};"
        : "+f"(d[0]), "+f"(d[1]), "+f"(d[2]), "+f"(d[3])
        : "r"(a[0]), "r"(a[1]), "r"(a[2]), "r"(a[3]), "r"(b[0]), "r"(b[1]));
}

#define CP_ASYNC16(dst, src) \
    asm volatile("cp.async.cg.shared.global [%0], [%1], 16;" :: "r"(dst), "l"(src))
#define CP_COMMIT()  asm volatile("cp.async.commit_group;" ::: "memory")
#define CP_WAIT1()   asm volatile("cp.async.wait_group 1;" ::: "memory")
#define CP_WAIT0()   asm volatile("cp.async.wait_group 0;" ::: "memory")

// split one float into hi/lo bf16
__device__ __forceinline__ void split1(float v, bf16& h, bf16& l) {
    h = __float2bfloat16(v);
    l = __float2bfloat16(v - __bfloat162float(h));
}

// ---- packed f32x2 ops (B300: FFMA2 via PTX fma.rn.f32x2) ----
__device__ __forceinline__ uint64_t pk2(float lo, float hi) {
    uint64_t r;
    asm("mov.b64 %0, {%1, %2};" : "=l"(r) : "f"(lo), "f"(hi));
    return r;
}
__device__ __forceinline__ void upk2(uint64_t v, float& lo, float& hi) {
    asm("mov.b64 {%0, %1}, %2;" : "=f"(lo), "=f"(hi) : "l"(v));
}
__device__ __forceinline__ uint64_t fma2(uint64_t a, uint64_t b, uint64_t c) {
    uint64_t d;
    asm("fma.rn.f32x2 %0, %1, %2, %3;" : "=l"(d) : "l"(a), "l"(b), "l"(c));
    return d;
}

// ===========================================================================
// Conversion kernels — 2 launches total (so tc_gemm is eager launch #3)
// ===========================================================================
// All transposing weight conversions in one launch.
// grid (4096, 1, 60): z<48 square [1024,1024] (layer=z>>3, j=z&7);
// z 48..53 W1 [1024,4096]; z 54..59 W2 [4096,1024].
__global__ void convT_all(const float* __restrict__ Wq, const float* __restrict__ Wk,
                          const float* __restrict__ Wv, const float* __restrict__ Wo,
                          const float* __restrict__ Wqc, const float* __restrict__ Wkc,
                          const float* __restrict__ Wvc, const float* __restrict__ Woc,
                          const float* __restrict__ W1, const float* __restrict__ W2,
                          bf16* __restrict__ hi, bf16* __restrict__ lo)
{
    __shared__ float ts[32][33];
    const int z = blockIdx.z;
    const int t = blockIdx.x;

    const float* src;
    bf16 *ho, *lo_;
    int K, N, k0, n0;

    if (z < 48) {
        if (t >= 1024) return;
        const int layer = z >> 3;
        const int j     = z & 7;
        const float* srcs[8] = { Wq, Wk, Wv, Wo, Wqc, Wkc, Wvc, Woc };
        src = srcs[j] + (size_t)layer * Dc * Dc;
        ho  = hi + (size_t)layer * WOFF_LAYER + (size_t)j * 1048576;
        lo_ = lo + (size_t)layer * WOFF_LAYER + (size_t)j * 1048576;
        K = Dc; N = Dc;
        k0 = (t >> 5) * 32;
        n0 = (t & 31) * 32;
    } else if (z < 54) {
        const int layer = z - 48;
        src = W1 + (size_t)layer * Dc * DFc;
        ho  = hi + (size_t)layer * WOFF_LAYER + WOFF_W1;
        lo_ = lo + (size_t)layer * WOFF_LAYER + WOFF_W1;
        K = Dc; N = DFc;
        n0 = (t & 127) * 32;
        k0 = (t >> 7) * 32;
    } else {
        const int layer = z - 54;
        src = W2 + (size_t)layer * DFc * Dc;
        ho  = hi + (size_t)layer * WOFF_LAYER + WOFF_W2;
        lo_ = lo + (size_t)layer * WOFF_LAYER + WOFF_W2;
        K = DFc; N = Dc;
        n0 = (t & 31) * 32;
        k0 = (t >> 5) * 32;
    }

    const int tx = threadIdx.x, ty = threadIdx.y;
#pragma unroll
    for (int j = 0; j < 4; j++)
        ts[ty + j * 8][tx] = src[(size_t)(k0 + ty + j * 8) * N + n0 + tx];
    __syncthreads();
#pragma unroll
    for (int j = 0; j < 4; j++) {
        int n = ty + j * 8;
        float v = ts[tx][n];
        size_t o = (size_t)(n0 + n) * K + k0 + tx;
        split1(v, ho[o], lo_[o]);
    }
}

// Straight (already [N,K]) conversions: output_embed (z=0) + encoded (z=1).
__global__ void conv_all(const float4* __restrict__ outemb, const float4* __restrict__ enc,
                         __nv_bfloat162* __restrict__ ehi_w, __nv_bfloat162* __restrict__ elo_w,
                         __nv_bfloat162* __restrict__ ehi_e, __nv_bfloat162* __restrict__ elo_e)
{
    const int z = blockIdx.z;
    if (z == 1 && blockIdx.x >= (Bc * Mc)) return;
    const float4* src = (z == 0) ? outemb : enc;
    __nv_bfloat162* hi = (z == 0) ? ehi_w : ehi_e;
    __nv_bfloat162* lo = (z == 0) ? elo_w : elo_e;

    size_t i = (size_t)blockIdx.x * blockDim.x + threadIdx.x;
    float4 v = src[i];
    __nv_bfloat162 h0 = __floats2bfloat162_rn(v.x, v.y);
    __nv_bfloat162 h1 = __floats2bfloat162_rn(v.z, v.w);
    float rx = v.x - __low2float(h0), ry = v.y - __high2float(h0);
    float rz = v.z - __low2float(h1), rw = v.w - __high2float(h1);
    hi[i * 2]     = h0;
    hi[i * 2 + 1] = h1;
    lo[i * 2]     = __floats2bfloat162_rn(rx, ry);
    lo[i * 2 + 1] = __floats2bfloat162_rn(rz, rw);
}

// ===========================================================================
// Tensor-core GEMM (R8 v2, unchanged): all-bf16 via cp.async, 2 CTAs/SM.
// ===========================================================================
#define PROWB  144
#define TILEB  (64 * PROWB)
#define STAGEB (4 * TILEB)
#define GEMM_SMEM (2 * STAGEB)
#define ROWOFF(r) (((r) & 63) * PROWB + ((r) >> 6) * 64)

template <bool BIAS, bool RELU, bool OUTSPLIT>
__global__ void __launch_bounds__(256, 2)
tc_gemm(const bf16* __restrict__ Ahi_g, const bf16* __restrict__ Alo_g,
        const bf16* __restrict__ Bhi_g, const bf16* __restrict__ Blo_g,
        const float* __restrict__ bias, float* __restrict__ C,
        bf16* __restrict__ Chi, bf16* __restrict__ Clo,
        int M, int N, int K)
{
    extern __shared__ char smem[];
    const int tid  = threadIdx.x;
    const int wid  = tid >> 5;
    const int lane = tid & 31;
    const int g    = lane >> 2;
    const int t    = lane & 3;
    const int wm   = wid & 1;
    const int wn   = wid >> 1;
    const int m0   = blockIdx.y * 128;
    const int n0   = blockIdx.x * 128;

    float acc[4][4][4];
#pragma unroll
    for (int i = 0; i < 4; i++)
#pragma unroll
        for (int j = 0; j < 4; j++)
#pragma unroll
            for (int c = 0; c < 4; c++) acc[i][j][c] = 0.f;

    const int S = K >> 5;

    auto cp_stage = [&](int s, int b) {
        const int k0 = s << 5;
        char* base = smem + b * STAGEB;
#pragma unroll
        for (int i = 0; i < 8; i++) {
            const int sel  = i >> 1;
            const int idx2 = tid + (i & 1) * 256;
            const int r    = idx2 >> 2;
            const int c    = idx2 & 3;
            const bf16* srcs[4] = { Ahi_g, Alo_g, Bhi_g, Blo_g };
            const int   rg  = (sel < 2 ? m0 : n0) + r;
            const bf16* src = srcs[sel] + (size_t)rg * K + k0 + c * 8;
            uint32_t dst = smem_u32(base + sel * TILEB + ROWOFF(r) + c * 16);
            CP_ASYNC16(dst, src);
        }
    };

    auto compute = [&](int b) {
        const char* base = smem + b * STAGEB;
        const char* Ah = base;
        const char* Al = base + TILEB;
        const char* Bh = base + 2 * TILEB;
        const char* Bl = base + 3 * TILEB;
        const int aoff = wm * 64;
        const int boff = (wn >> 1) * 64;
        const int brow = (wn & 1) * 32;
#pragma unroll
        for (int ks = 0; ks < 2; ks++) {
            const int kb = ks * 16 + t * 2;
            uint32_t ah[4][4], al[4][4], bh[4][2], bl[4][2];
#pragma unroll
            for (int mt = 0; mt < 4; mt++) {
                const char* p = Ah + (mt * 16 + g) * PROWB + aoff + kb * 2;
                ah[mt][0] = *reinterpret_cast<const uint32_t*>(p);
                ah[mt][1] = *reinterpret_cast<const uint32_t*>(p + 8 * PROWB);
                ah[mt][2] = *reinterpret_cast<const uint32_t*>(p + 16);
                ah[mt][3] = *reinterpret_cast<const uint32_t*>(p + 8 * PROWB + 16);
            }
#pragma unroll
            for (int nt = 0; nt < 4; nt++) {
                const char* p = Bh + (brow + nt * 8 + g) * PROWB + boff + kb * 2;
                bh[nt][0] = *reinterpret_cast<const uint32_t*>(p);
                bh[nt][1] = *reinterpret_cast<const uint32_t*>(p + 16);
            }
#pragma unroll
            for (int mt = 0; mt < 4; mt++)
#pragma unroll
                for (int nt = 0; nt < 4; nt++)
                    mma_bf16(acc[mt][nt], ah[mt], bh[nt]);
#pragma unroll
            for (int nt = 0; nt < 4; nt++) {
                const char* p = Bl + (brow + nt * 8 + g) * PROWB + boff + kb * 2;
                bl[nt][0] = *reinterpret_cast<const uint32_t*>(p);
                bl[nt][1] = *reinterpret_cast<const uint32_t*>(p + 16);
            }
#pragma unroll
            for (int mt = 0; mt < 4; mt++)
#pragma unroll
                for (int nt = 0; nt < 4; nt++)
                    mma_bf16(acc[mt][nt], ah[mt], bl[nt]);
#pragma unroll
            for (int mt = 0; mt < 4; mt++) {
                const char* p = Al + (mt * 16 + g) * PROWB + aoff + kb * 2;
                al[mt][0] = *reinterpret_cast<const uint32_t*>(p);
                al[mt][1] = *reinterpret_cast<const uint32_t*>(p + 8 * PROWB);
                al[mt][2] = *reinterpret_cast<const uint32_t*>(p + 16);
                al[mt][3] = *reinterpret_cast<const uint32_t*>(p + 8 * PROWB + 16);
            }
#pragma unroll
            for (int mt = 0; mt < 4; mt++)
#pragma unroll
                for (int nt = 0; nt < 4; nt++)
                    mma_bf16(acc[mt][nt], al[mt], bh[nt]);
        }
    };

    cp_stage(0, 0);
    CP_COMMIT();
    for (int s = 0; s < S; s++) {
        const int b = s & 1;
        if (s + 1 < S) { cp_stage(s + 1, b ^ 1); CP_COMMIT(); CP_WAIT1(); }
        else           { CP_WAIT0(); }
        __syncthreads();
        compute(b);
        __syncthreads();
    }

    float* stage = reinterpret_cast<float*>(smem);
#pragma unroll
    for (int mt = 0; mt < 4; mt++) {
#pragma unroll
        for (int nt = 0; nt < 4; nt++) {
            int row = wm * 64 + mt * 16 + g;
            int col = wn * 32 + nt * 8 + t * 2;
            *reinterpret_cast<float2*>(&stage[row * 132 + col]) =
                make_float2(acc[mt][nt][0], acc[mt][nt][1]);
            *reinterpret_cast<float2*>(&stage[(row + 8) * 132 + col]) =
                make_float2(acc[mt][nt][2], acc[mt][nt][3]);
        }
    }
    __syncthreads();

#pragma unroll
    for (int i = 0; i < 16; i++) {
        int f   = i * 256 + tid;
        int row = f >> 5;
        int c4  = f & 31;
        float4 v = *reinterpret_cast<float4*>(&stage[row * 132 + c4 * 4]);
        if (BIAS) {
            float4 bv = *reinterpret_cast<const float4*>(bias + n0 + c4 * 4);
            v.x += bv.x; v.y += bv.y; v.z += bv.z; v.w += bv.w;
        }
        if (RELU) {
            v.x = fmaxf(v.x, 0.f); v.y = fmaxf(v.y, 0.f);
            v.z = fmaxf(v.z, 0.f); v.w = fmaxf(v.w, 0.f);
        }
        size_t oidx = (size_t)(m0 + row) * N + n0 + c4 * 4;
        if (OUTSPLIT) {
            __nv_bfloat162 h0 = __floats2bfloat162_rn(v.x, v.y);
            __nv_bfloat162 h1 = __floats2bfloat162_rn(v.z, v.w);
            float rx = v.x - __low2float(h0), ry = v.y - __high2float(h0);
            float rz = v.z - __low2float(h1), rw = v.w - __high2float(h1);
            *reinterpret_cast<__nv_bfloat162*>(Chi + oidx)     = h0;
            *reinterpret_cast<__nv_bfloat162*>(Chi + oidx + 2) = h1;
            *reinterpret_cast<__nv_bfloat162*>(Clo + oidx)     = __floats2bfloat162_rn(rx, ry);
            *reinterpret_cast<__nv_bfloat162*>(Clo + oidx + 2) = __floats2bfloat162_rn(rz, rw);
        } else {
            *reinterpret_cast<float4*>(C + oidx) = v;
        }
    }
}

// ===========================================================================
// Fused attention v4: R4 layout (4 warps x 8 rows, 32-key tiles), but:
//  - packed fma.rn.f32x2 for QK (row pairs) and PV (column pairs)
//  - Q stored transposed [d][row], prescaled by 1/8 (pairs load as b64)
//  - P stored duplicated (p,p) for mov-free PV operands
//  - NO online max (scores bounded; softmax shift-invariant), per-lane l
// ===========================================================================
template <bool CAUSAL>
__global__ void __launch_bounds__(128)
attn_kernel(const float* __restrict__ Q, const float* __restrict__ K,
            const float* __restrict__ V, bf16* __restrict__ Ohi,
            bf16* __restrict__ Olo, int Lk)
{
    __shared__ float Qs2f[64 * 32];     // [d][row], prescaled
    __shared__ float Kst[64 * 33];      // [d][key-lane]
    __shared__ float Vs[32 * 68];       // [key][col]
    __shared__ float Ps2f[32 * 64];     // [row][key] duplicated (p,p)

    const int b    = blockIdx.z;
    const int h    = blockIdx.y;
    const int q0   = blockIdx.x * 32;
    const int tid  = threadIdx.x;
    const int lane = tid & 31;
    const int w    = tid >> 5;
    const int r0   = w * 8;

    // Q tile -> transposed smem, prescaled (lane = row: conflict-free stores)
#pragma unroll
    for (int s = tid; s < 512; s += 128) {
        int r  = s & 31;
        int c4 = s >> 5;    // accumulates 0..15 over the 4 iterations
        float4 v = *reinterpret_cast<const float4*>(
            Q + (size_t)(b * Sc + q0 + r) * Dc + h * 64 + c4 * 4);
        Qs2f[(c4 * 4 + 0) * 32 + r] = v.x * 0.125f;
        Qs2f[(c4 * 4 + 1) * 32 + r] = v.y * 0.125f;
        Qs2f[(c4 * 4 + 2) * 32 + r] = v.z * 0.125f;
        Qs2f[(c4 * 4 + 3) * 32 + r] = v.w * 0.125f;
    }

    uint64_t o2[8];
    float lsum[8];
#pragma unroll
    for (int r = 0; r < 8; r++) { o2[r] = 0ull; lsum[r] = 0.f; }

    const int nkt = CAUSAL ? (blockIdx.x + 1) : (Lk >> 5);

    for (int kt = 0; kt < nkt; kt++) {
        const int k0 = kt * 32;
        __syncthreads();
#pragma unroll
        for (int s = tid; s < 512; s += 128) {
            int r  = s >> 4;
            int c4 = s & 15;
            size_t base = (size_t)(b * Lk + k0 + r) * Dc + h * 64 + c4 * 4;
            float4 kv = *reinterpret_cast<const float4*>(K + base);
            Kst[(c4 * 4 + 0) * 33 + r] = kv.x;
            Kst[(c4 * 4 + 1) * 33 + r] = kv.y;
            Kst[(c4 * 4 + 2) * 33 + r] = kv.z;
            Kst[(c4 * 4 + 3) * 33 + r] = kv.w;
            float4 vv = *reinterpret_cast<const float4*>(V + base);
            *reinterpret_cast<float4*>(&Vs[r * 68 + c4 * 4]) = vv;
        }
        __syncthreads();

        // ---- QK: packed over row pairs; lane owns key k0+lane ----
        uint64_t acc2[4];
#pragma unroll
        for (int i = 0; i < 4; i++) acc2[i] = 0ull;
#pragma unroll 8
        for (int d = 0; d < 64; d++) {
            float kd = Kst[d * 33 + lane];
            uint64_t kk = pk2(kd, kd);
            ulonglong2 qA = *reinterpret_cast<const ulonglong2*>(&Qs2f[d * 32 + w * 8]);
            ulonglong2 qB = *reinterpret_cast<const ulonglong2*>(&Qs2f[d * 32 + w * 8 + 4]);
            acc2[0] = fma2(qA.x, kk, acc2[0]);
            acc2[1] = fma2(qA.y, kk, acc2[1]);
            acc2[2] = fma2(qB.x, kk, acc2[2]);
            acc2[3] = fma2(qB.y, kk, acc2[3]);
        }
        float sc[8];
#pragma unroll
        for (int i = 0; i < 4; i++) upk2(acc2[i], sc[2 * i], sc[2 * i + 1]);

        // ---- softmax weights (no max subtraction; scores bounded) ----
#pragma unroll
        for (int r = 0; r < 8; r++) {
            float p;
            if (CAUSAL && (k0 + lane) > (q0 + r0 + r)) p = 0.f;
            else p = __expf(sc[r]);
            lsum[r] += p;
            *reinterpret_cast<uint64_t*>(&Ps2f[(r0 + r) * 64 + lane * 2]) = pk2(p, p);
        }
        __syncwarp();

        // ---- PV: packed over output columns (lane, lane+32) ----
#pragma unroll
        for (int j2 = 0; j2 < 16; j2++) {
            uint64_t va = pk2(Vs[(2 * j2) * 68 + lane],     Vs[(2 * j2) * 68 + 32 + lane]);
            uint64_t vb = pk2(Vs[(2 * j2 + 1) * 68 + lane], Vs[(2 * j2 + 1) * 68 + 32 + lane]);
#pragma unroll
            for (int r = 0; r < 8; r++) {
                ulonglong2 pp = *reinterpret_cast<const ulonglong2*>(
                    &Ps2f[(r0 + r) * 64 + j2 * 4]);
                o2[r] = fma2(pp.x, va, o2[r]);
                o2[r] = fma2(pp.y, vb, o2[r]);
            }
        }
        __syncwarp();
    }

    // final per-row l reduce + normalize + hi/lo store
#pragma unroll
    for (int r = 0; r < 8; r++) {
        float l = lsum[r];
#pragma unroll
        for (int off = 16; off > 0; off >>= 1)
            l += __shfl_xor_sync(0xffffffffu, l, off);
        float inv = 1.f / l;
        float v0, v1;
        upk2(o2[r], v0, v1);
        v0 *= inv; v1 *= inv;
        size_t base = (size_t)(b * Sc + q0 + r0 + r) * Dc + h * 64;
        bf16 h0, l0, h1, l1;
        split1(v0, h0, l0);
        split1(v1, h1, l1);
        Ohi[base + lane]      = h0;
        Olo[base + lane]      = l0;
        Ohi[base + 32 + lane] = h1;
        Olo[base + 32 + lane] = l1;
    }
}

// ---------------------------------------------------------------------------
// Residual + LayerNorm; writes fp32 + hi/lo bf16 mirrors
// ---------------------------------------------------------------------------
__global__ void __launch_bounds__(256)
ln_kernel(const float* __restrict__ x, const float* __restrict__ add,
          const float* __restrict__ s, const float* __restrict__ b,
          float* __restrict__ out, bf16* __restrict__ ohi, bf16* __restrict__ olo)
{
    const int row = blockIdx.x;
    const int tid = threadIdx.x;
    const size_t base = (size_t)row * Dc;

    float v[4];
    float sum = 0.f, sq = 0.f;
#pragma unroll
    for (int i = 0; i < 4; i++) {
        int c = tid + i * 256;
        float val = x[base + c];
        if (add) val += add[base + c];
        v[i] = val;
        sum += val;
        sq  += val * val;
    }
#pragma unroll
    for (int off = 16; off > 0; off >>= 1) {
        sum += __shfl_xor_sync(0xffffffffu, sum, off);
        sq  += __shfl_xor_sync(0xffffffffu, sq, off);
    }
    __shared__ float s1[8], s2[8];
    __shared__ float mu_s, inv_s;
    int lane = tid & 31, wid = tid >> 5;
    if (lane == 0) { s1[wid] = sum; s2[wid] = sq; }
    __syncthreads();
    if (tid == 0) {
        float ts = 0.f, tq = 0.f;
#pragma unroll
        for (int i = 0; i < 8; i++) { ts += s1[i]; tq += s2[i]; }
        float mu  = ts * (1.f / Dc);
        float var = tq * (1.f / Dc) - mu * mu;
        mu_s  = mu;
        inv_s = rsqrtf(var + 1e-5f);
    }
    __syncthreads();
    float mu = mu_s, inv = inv_s;
#pragma unroll
    for (int i = 0; i < 4; i++) {
        int c = tid + i * 256;
        float r = (v[i] - mu) * inv * s[c] + b[c];
        out[base + c] = r;
        bf16 h, l;
        split1(r, h, l);
        ohi[base + c] = h;
        olo[base + c] = l;
    }
}

// ---------------------------------------------------------------------------
// Embedding gather + positional add; writes fp32 + hi/lo
// ---------------------------------------------------------------------------
__global__ void __launch_bounds__(256)
embed_kernel(const int* __restrict__ seq, const float* __restrict__ emb,
             const float* __restrict__ pos, float* __restrict__ x,
             bf16* __restrict__ xhi, bf16* __restrict__ xlo)
{
    const int row  = blockIdx.x;
    const int sidx = row & (Sc - 1);
    const int tok  = seq[row];
    const int tid  = threadIdx.x;
#pragma unroll
    for (int i = 0; i < 4; i++) {
        int c = tid + i * 256;
        float r = emb[(size_t)tok * Dc + c] + pos[(size_t)sidx * Dc + c];
        size_t o = (size_t)row * Dc + c;
        x[o] = r;
        bf16 h, l;
        split1(r, h, l);
        xhi[o] = h;
        xlo[o] = l;
    }
}

// ---------------------------------------------------------------------------
// Host orchestration
// ---------------------------------------------------------------------------
template <bool BIAS, bool RELU, bool OUTSPLIT>
static void launch_gemm(const bf16* ahi, const bf16* alo,
                        const bf16* bhi, const bf16* blo,
                        const float* bias, float* C, bf16* chi, bf16* clo,
                        int M, int N, int K)
{
    cudaFuncSetAttribute(tc_gemm<BIAS, RELU, OUTSPLIT>,
                         cudaFuncAttributeMaxDynamicSharedMemorySize, GEMM_SMEM);
    dim3 grid(N / 128, M / 128);
    tc_gemm<BIAS, RELU, OUTSPLIT><<<grid, 256, GEMM_SMEM>>>(
        ahi, alo, bhi, blo, bias, C, chi, clo, M, N, K);
}

extern "C" void kernel_launch(void* const* d_in, const int* in_sizes, int n_in,
                              void* d_out, int out_size)
{
    (void)in_sizes; (void)n_in; (void)out_size;

    const float* encoded      = (const float*)d_in[0];
    const int*   seq          = (const int*)  d_in[1];
    const float* input_embed  = (const float*)d_in[2];
    const float* output_embed = (const float*)d_in[3];
    const float* output_bias  = (const float*)d_in[4];
    const float* pos_embed    = (const float*)d_in[5];
    const float* Wq  = (const float*)d_in[6];
    const float* Wk  = (const float*)d_in[7];
    const float* Wv  = (const float*)d_in[8];
    const float* Wo  = (const float*)d_in[9];
    const float* Wqc = (const float*)d_in[10];
    const float* Wkc = (const float*)d_in[11];
    const float* Wvc = (const float*)d_in[12];
    const float* Woc = (const float*)d_in[13];
    const float* W1  = (const float*)d_in[14];
    const float* b1  = (const float*)d_in[15];
    const float* W2  = (const float*)d_in[16];
    const float* b2  = (const float*)d_in[17];
    const float* ln1s = (const float*)d_in[18];
    const float* ln1b = (const float*)d_in[19];
    const float* ln2s = (const float*)d_in[20];
    const float* ln2b = (const float*)d_in[21];
    const float* ln3s = (const float*)d_in[22];
    const float* ln3b = (const float*)d_in[23];
    const float* lnfs = (const float*)d_in[24];
    const float* lnfb = (const float*)d_in[25];

    float *x, *q, *k, *v, *o;
    cudaGetSymbolAddress((void**)&x, g_x);
    cudaGetSymbolAddress((void**)&q, g_q);
    cudaGetSymbolAddress((void**)&k, g_k);
    cudaGetSymbolAddress((void**)&v, g_v);
    cudaGetSymbolAddress((void**)&o, g_o);
    bf16 *whi, *wlo, *xhi, *xlo, *ahi, *alo, *fhi, *flo, *ehi, *elo;
    cudaGetSymbolAddress((void**)&whi, g_whi);
    cudaGetSymbolAddress((void**)&wlo, g_wlo);
    cudaGetSymbolAddress((void**)&xhi, g_xhi);
    cudaGetSymbolAddress((void**)&xlo, g_xlo);
    cudaGetSymbolAddress((void**)&ahi, g_ahi);
    cudaGetSymbolAddress((void**)&alo, g_alo);
    cudaGetSymbolAddress((void**)&fhi, g_fhi);
    cudaGetSymbolAddress((void**)&flo, g_flo);
    cudaGetSymbolAddress((void**)&ehi, g_ehi);
    cudaGetSymbolAddress((void**)&elo, g_elo);

    // ---- conversions: 2 launches ----
    convT_all<<<dim3(4096, 1, 60), dim3(32, 8)>>>(Wq, Wk, Wv, Wo, Wqc, Wkc, Wvc, Woc,
                                                  W1, W2, whi, wlo);
    conv_all<<<dim3(Vc, 1, 2), 256>>>((const float4*)output_embed, (const float4*)encoded,
                                      (__nv_bfloat162*)(whi + EOFF),
                                      (__nv_bfloat162*)(wlo + EOFF),
                                      (__nv_bfloat162*)ehi, (__nv_bfloat162*)elo);

    const int NR  = Bc * Sc;   // 4096
    const int NRE = Bc * Mc;   // 8192

    embed_kernel<<<NR, 256>>>(seq, input_embed, pos_embed, x, xhi, xlo);

    const dim3 agrid(Sc / 32, Hc, Bc);   // (16, 16, 8)

    for (int i = 0; i < Lc; i++) {
        const size_t lb = (size_t)i * WOFF_LAYER;
        const bf16* wq = whi + lb;
        const bf16* lq = wlo + lb;

        // ---- self attention ----  (layer 0's q-GEMM is eager launch #3)
        launch_gemm<false, false, false>(xhi, xlo, wq + 0 * 1048576, lq + 0 * 1048576,
                                         nullptr, q, nullptr, nullptr, NR, Dc, Dc);
        launch_gemm<false, false, false>(xhi, xlo, wq + 1 * 1048576, lq + 1 * 1048576,
                                         nullptr, k, nullptr, nullptr, NR, Dc, Dc);
        launch_gemm<false, false, false>(xhi, xlo, wq + 2 * 1048576, lq + 2 * 1048576,
                                         nullptr, v, nullptr, nullptr, NR, Dc, Dc);
        attn_kernel<true><<<agrid, 128>>>(q, k, v, ahi, alo, Sc);
        launch_gemm<false, false, false>(ahi, alo, wq + 3 * 1048576, lq + 3 * 1048576,
                                         nullptr, o, nullptr, nullptr, NR, Dc, Dc);
        ln_kernel<<<NR, 256>>>(x, o, ln1s + (size_t)i * Dc, ln1b + (size_t)i * Dc,
                               x, xhi, xlo);

        // ---- cross attention ----
        launch_gemm<false, false, false>(xhi, xlo, wq + 4 * 1048576, lq + 4 * 1048576,
                                         nullptr, q, nullptr, nullptr, NR, Dc, Dc);
        launch_gemm<false, false, false>(ehi, elo, wq + 5 * 1048576, lq + 5 * 1048576,
                                         nullptr, k, nullptr, nullptr, NRE, Dc, Dc);
        launch_gemm<false, false, false>(ehi, elo, wq + 6 * 1048576, lq + 6 * 1048576,
                                         nullptr, v, nullptr, nullptr, NRE, Dc, Dc);
        attn_kernel<false><<<agrid, 128>>>(q, k, v, ahi, alo, Mc);
        launch_gemm<false, false, false>(ahi, alo, wq + 7 * 1048576, lq + 7 * 1048576,
                                         nullptr, o, nullptr, nullptr, NR, Dc, Dc);
        ln_kernel<<<NR, 256>>>(x, o, ln2s + (size_t)i * Dc, ln2b + (size_t)i * Dc,
                               x, xhi, xlo);

        // ---- FFN ----
        launch_gemm<true, true, true>(xhi, xlo, wq + WOFF_W1, lq + WOFF_W1,
                                      b1 + (size_t)i * DFc, nullptr, fhi, flo,
                                      NR, DFc, Dc);
        launch_gemm<true, false, false>(fhi, flo, wq + WOFF_W2, lq + WOFF_W2,
                                        b2 + (size_t)i * Dc, o, nullptr, nullptr,
                                        NR, Dc, DFc);
        ln_kernel<<<NR, 256>>>(x, o, ln3s + (size_t)i * Dc, ln3b + (size_t)i * Dc,
                               x, xhi, xlo);
    }

    // final norm + logits
    ln_kernel<<<NR, 256>>>(x, nullptr, lnfs, lnfb, x, xhi, xlo);
    launch_gemm<true, false, false>(xhi, xlo, whi + EOFF, wlo + EOFF,
                                    output_bias, (float*)d_out, nullptr, nullptr,
                                    NR, Vc, Dc);
}

// round 10
// speedup vs baseline: 1.0511x; 1.0511x over previous
#include <cuda_runtime.h>
#include <cuda_bf16.h>
#include <math.h>
#include <stdint.h>

// Problem constants
#define Bc   8
#define Sc   512
#define Dc   1024
#define Hc   16
#define DHc  64
#define Mc   1024
#define DFc  4096
#define Vc   32000
#define Lc   6

typedef __nv_bfloat16 bf16;

// ---------------------------------------------------------------------------
// Scratch (device globals)
// ---------------------------------------------------------------------------
__device__ float g_x[Bc * Sc * Dc];        // residual stream fp32
__device__ float g_q[Bc * Sc * Dc];
__device__ float g_k[Bc * Mc * Dc];
__device__ float g_v[Bc * Mc * Dc];
__device__ float g_o[Bc * Sc * Dc];
// hi/lo bf16 activation mirrors (GEMM A-side inputs)
__device__ bf16 g_xhi[Bc * Sc * Dc],  g_xlo[Bc * Sc * Dc];
__device__ bf16 g_ahi[Bc * Sc * Dc],  g_alo[Bc * Sc * Dc];
__device__ bf16 g_fhi[Bc * Sc * DFc], g_flo[Bc * Sc * DFc];
__device__ bf16 g_ehi[Bc * Mc * Dc],  g_elo[Bc * Mc * Dc];

// Pre-converted weights: [N,K] bf16 hi/lo.
#define WOFF_LAYER 16777216ull
#define WOFF_W1    8388608ull
#define WOFF_W2    12582912ull
#define EOFF       100663296ull
#define WTOTAL     133431296ull
__device__ bf16 g_whi[WTOTAL];
__device__ bf16 g_wlo[WTOTAL];

// ===========================================================================
// helpers
// ===========================================================================
__device__ __forceinline__ uint32_t smem_u32(const void* p) {
    uint32_t a;
    asm("{ .reg .u64 t; cvta.to.shared.u64 t, %1; cvt.u32.u64 %0, t; }"
        : "=r"(a) : "l"(p));
    return a;
}

__device__ __forceinline__ void mma_bf16(float* d, const uint32_t* a, const uint32_t* b) {
    asm volatile(
        "mma.sync.aligned.m16n8k16.row.col.f32.bf16.bf16.f32 "
        "{%0,%1,%2,%3}, {%4,%5,%6,%7}, {%8,%9}, {%0,%1,%2,%3};"
        : "+f"(d[0]), "+f"(d[1]), "+f"(d[2]), "+f"(d[3])
        : "r"(a[0]), "r"(a[1]), "r"(a[2]), "r"(a[3]), "r"(b[0]), "r"(b[1]));
}

#define LDSM_X4(r, addr) \
    asm volatile("ldmatrix.sync.aligned.m8n8.x4.shared.b16 {%0,%1,%2,%3}, [%4];" \
        : "=r"((r)[0]), "=r"((r)[1]), "=r"((r)[2]), "=r"((r)[3]) : "r"(addr))

#define CP_ASYNC16(dst, src) \
    asm volatile("cp.async.cg.shared.global [%0], [%1], 16;" :: "r"(dst), "l"(src))
#define CP_COMMIT()  asm volatile("cp.async.commit_group;" ::: "memory")
#define CP_WAIT1()   asm volatile("cp.async.wait_group 1;" ::: "memory")
#define CP_WAIT0()   asm volatile("cp.async.wait_group 0;" ::: "memory")

// split one float into hi/lo bf16
__device__ __forceinline__ void split1(float v, bf16& h, bf16& l) {
    h = __float2bfloat16(v);
    l = __float2bfloat16(v - __bfloat162float(h));
}

// ===========================================================================
// Conversion kernels — 2 launches total
// ===========================================================================
__global__ void convT_all(const float* __restrict__ Wq, const float* __restrict__ Wk,
                          const float* __restrict__ Wv, const float* __restrict__ Wo,
                          const float* __restrict__ Wqc, const float* __restrict__ Wkc,
                          const float* __restrict__ Wvc, const float* __restrict__ Woc,
                          const float* __restrict__ W1, const float* __restrict__ W2,
                          bf16* __restrict__ hi, bf16* __restrict__ lo)
{
    __shared__ float ts[32][33];
    const int z = blockIdx.z;
    const int t = blockIdx.x;

    const float* src;
    bf16 *ho, *lo_;
    int K, N, k0, n0;

    if (z < 48) {
        if (t >= 1024) return;
        const int layer = z >> 3;
        const int j     = z & 7;
        const float* srcs[8] = { Wq, Wk, Wv, Wo, Wqc, Wkc, Wvc, Woc };
        src = srcs[j] + (size_t)layer * Dc * Dc;
        ho  = hi + (size_t)layer * WOFF_LAYER + (size_t)j * 1048576;
        lo_ = lo + (size_t)layer * WOFF_LAYER + (size_t)j * 1048576;
        K = Dc; N = Dc;
        k0 = (t >> 5) * 32;
        n0 = (t & 31) * 32;
    } else if (z < 54) {
        const int layer = z - 48;
        src = W1 + (size_t)layer * Dc * DFc;
        ho  = hi + (size_t)layer * WOFF_LAYER + WOFF_W1;
        lo_ = lo + (size_t)layer * WOFF_LAYER + WOFF_W1;
        K = Dc; N = DFc;
        n0 = (t & 127) * 32;
        k0 = (t >> 7) * 32;
    } else {
        const int layer = z - 54;
        src = W2 + (size_t)layer * DFc * Dc;
        ho  = hi + (size_t)layer * WOFF_LAYER + WOFF_W2;
        lo_ = lo + (size_t)layer * WOFF_LAYER + WOFF_W2;
        K = DFc; N = Dc;
        n0 = (t & 31) * 32;
        k0 = (t >> 5) * 32;
    }

    const int tx = threadIdx.x, ty = threadIdx.y;
#pragma unroll
    for (int j = 0; j < 4; j++)
        ts[ty + j * 8][tx] = src[(size_t)(k0 + ty + j * 8) * N + n0 + tx];
    __syncthreads();
#pragma unroll
    for (int j = 0; j < 4; j++) {
        int n = ty + j * 8;
        float v = ts[tx][n];
        size_t o = (size_t)(n0 + n) * K + k0 + tx;
        split1(v, ho[o], lo_[o]);
    }
}

__global__ void conv_all(const float4* __restrict__ outemb, const float4* __restrict__ enc,
                         __nv_bfloat162* __restrict__ ehi_w, __nv_bfloat162* __restrict__ elo_w,
                         __nv_bfloat162* __restrict__ ehi_e, __nv_bfloat162* __restrict__ elo_e)
{
    const int z = blockIdx.z;
    if (z == 1 && blockIdx.x >= (Bc * Mc)) return;
    const float4* src = (z == 0) ? outemb : enc;
    __nv_bfloat162* hi = (z == 0) ? ehi_w : ehi_e;
    __nv_bfloat162* lo = (z == 0) ? elo_w : elo_e;

    size_t i = (size_t)blockIdx.x * blockDim.x + threadIdx.x;
    float4 v = src[i];
    __nv_bfloat162 h0 = __floats2bfloat162_rn(v.x, v.y);
    __nv_bfloat162 h1 = __floats2bfloat162_rn(v.z, v.w);
    float rx = v.x - __low2float(h0), ry = v.y - __high2float(h0);
    float rz = v.z - __low2float(h1), rw = v.w - __high2float(h1);
    hi[i * 2]     = h0;
    hi[i * 2 + 1] = h1;
    lo[i * 2]     = __floats2bfloat162_rn(rx, ry);
    lo[i * 2 + 1] = __floats2bfloat162_rn(rz, rw);
}

// ===========================================================================
// Tensor-core GEMM v3: all-bf16 via cp.async, 2 CTAs/SM, ldmatrix fragments
// with DIRECT operand-order register mapping (no repacks).
// ===========================================================================
#define PROWB  144
#define TILEB  (64 * PROWB)
#define STAGEB (4 * TILEB)
#define GEMM_SMEM (2 * STAGEB)
#define ROWOFF(r) (((r) & 63) * PROWB + ((r) >> 6) * 64)

template <bool BIAS, bool RELU, bool OUTSPLIT>
__global__ void __launch_bounds__(256, 2)
tc_gemm(const bf16* __restrict__ Ahi_g, const bf16* __restrict__ Alo_g,
        const bf16* __restrict__ Bhi_g, const bf16* __restrict__ Blo_g,
        const float* __restrict__ bias, float* __restrict__ C,
        bf16* __restrict__ Chi, bf16* __restrict__ Clo,
        int M, int N, int K)
{
    extern __shared__ char smem[];
    const int tid  = threadIdx.x;
    const int wid  = tid >> 5;
    const int lane = tid & 31;
    const int g    = lane >> 2;
    const int t    = lane & 3;
    const int wm   = wid & 1;
    const int wn   = wid >> 1;
    const int m0   = blockIdx.y * 128;
    const int n0   = blockIdx.x * 128;

    const uint32_t smem0 = smem_u32(smem);

    // ---- ldmatrix per-lane address offsets (direct operand-order) ----
    // A x4: M0=(rows g..g+7? formally rows0-7,k0-7) M1=(rows8-15,k0-7)
    //       M2=(rows0-7,k8-15) M3=(rows8-15,k8-15)  -> r0..r3 = a0..a3
    const int arow_l = (lane & 7) + ((lane >> 3) & 1) * 8;   // 0..15
    const uint32_t aoffL =
        (uint32_t)(arow_l * PROWB + wm * 64 + (lane >> 4) * 16);
    // B x4 (two n-tiles per LDSM): M0=(nt0 rows,k0-7) M1=(nt0,k8-15)
    //       M2=(nt1 rows,k0-7) M3=(nt1,k8-15) -> {b0,b1,b0',b1'}
    const int brow_l = ((lane >> 4) & 1) * 8 + (lane & 7);   // 0..15
    const uint32_t boffL =
        (uint32_t)(((wn & 1) * 32 + brow_l) * PROWB + (wn >> 1) * 64 +
                   ((lane >> 3) & 1) * 16);

    float acc[4][4][4];
#pragma unroll
    for (int i = 0; i < 4; i++)
#pragma unroll
        for (int j = 0; j < 4; j++)
#pragma unroll
            for (int c = 0; c < 4; c++) acc[i][j][c] = 0.f;

    const int S = K >> 5;

    auto cp_stage = [&](int s, int b) {
        const int k0 = s << 5;
        char* base = smem + b * STAGEB;
#pragma unroll
        for (int i = 0; i < 8; i++) {
            const int sel  = i >> 1;
            const int idx2 = tid + (i & 1) * 256;
            const int r    = idx2 >> 2;
            const int c    = idx2 & 3;
            const bf16* srcs[4] = { Ahi_g, Alo_g, Bhi_g, Blo_g };
            const int   rg  = (sel < 2 ? m0 : n0) + r;
            const bf16* src = srcs[sel] + (size_t)rg * K + k0 + c * 8;
            uint32_t dst = smem_u32(base + sel * TILEB + ROWOFF(r) + c * 16);
            CP_ASYNC16(dst, src);
        }
    };

    auto compute = [&](int b) {
        const uint32_t base = smem0 + b * STAGEB;
        const uint32_t Ah = base + aoffL;
        const uint32_t Al = base + TILEB + aoffL;
        const uint32_t Bh = base + 2 * TILEB + boffL;
        const uint32_t Bl = base + 3 * TILEB + boffL;
#pragma unroll
        for (int ks = 0; ks < 2; ks++) {
            const uint32_t kb = ks * 32;           // 16 bf16 = 32 bytes
            uint32_t ah[4][4], al[4][4], bh[2][4], bl[2][4];
#pragma unroll
            for (int mt = 0; mt < 4; mt++)
                LDSM_X4(ah[mt], Ah + mt * (16 * PROWB) + kb);
#pragma unroll
            for (int j = 0; j < 2; j++)
                LDSM_X4(bh[j], Bh + j * (16 * PROWB) + kb);
#pragma unroll
            for (int mt = 0; mt < 4; mt++)
#pragma unroll
                for (int nt = 0; nt < 4; nt++)
                    mma_bf16(acc[mt][nt], ah[mt], &bh[nt >> 1][(nt & 1) * 2]);
#pragma unroll
            for (int j = 0; j < 2; j++)
                LDSM_X4(bl[j], Bl + j * (16 * PROWB) + kb);
#pragma unroll
            for (int mt = 0; mt < 4; mt++)
#pragma unroll
                for (int nt = 0; nt < 4; nt++)
                    mma_bf16(acc[mt][nt], ah[mt], &bl[nt >> 1][(nt & 1) * 2]);
#pragma unroll
            for (int mt = 0; mt < 4; mt++)
                LDSM_X4(al[mt], Al + mt * (16 * PROWB) + kb);
#pragma unroll
            for (int mt = 0; mt < 4; mt++)
#pragma unroll
                for (int nt = 0; nt < 4; nt++)
                    mma_bf16(acc[mt][nt], al[mt], &bh[nt >> 1][(nt & 1) * 2]);
        }
    };

    cp_stage(0, 0);
    CP_COMMIT();
    for (int s = 0; s < S; s++) {
        const int b = s & 1;
        if (s + 1 < S) { cp_stage(s + 1, b ^ 1); CP_COMMIT(); CP_WAIT1(); }
        else           { CP_WAIT0(); }
        __syncthreads();
        compute(b);
        __syncthreads();
    }

    // ---- epilogue ----
    float* stage = reinterpret_cast<float*>(smem);
#pragma unroll
    for (int mt = 0; mt < 4; mt++) {
#pragma unroll
        for (int nt = 0; nt < 4; nt++) {
            int row = wm * 64 + mt * 16 + g;
            int col = wn * 32 + nt * 8 + t * 2;
            *reinterpret_cast<float2*>(&stage[row * 132 + col]) =
                make_float2(acc[mt][nt][0], acc[mt][nt][1]);
            *reinterpret_cast<float2*>(&stage[(row + 8) * 132 + col]) =
                make_float2(acc[mt][nt][2], acc[mt][nt][3]);
        }
    }
    __syncthreads();

#pragma unroll
    for (int i = 0; i < 16; i++) {
        int f   = i * 256 + tid;
        int row = f >> 5;
        int c4  = f & 31;
        float4 v = *reinterpret_cast<float4*>(&stage[row * 132 + c4 * 4]);
        if (BIAS) {
            float4 bv = *reinterpret_cast<const float4*>(bias + n0 + c4 * 4);
            v.x += bv.x; v.y += bv.y; v.z += bv.z; v.w += bv.w;
        }
        if (RELU) {
            v.x = fmaxf(v.x, 0.f); v.y = fmaxf(v.y, 0.f);
            v.z = fmaxf(v.z, 0.f); v.w = fmaxf(v.w, 0.f);
        }
        size_t oidx = (size_t)(m0 + row) * N + n0 + c4 * 4;
        if (OUTSPLIT) {
            __nv_bfloat162 h0 = __floats2bfloat162_rn(v.x, v.y);
            __nv_bfloat162 h1 = __floats2bfloat162_rn(v.z, v.w);
            float rx = v.x - __low2float(h0), ry = v.y - __high2float(h0);
            float rz = v.z - __low2float(h1), rw = v.w - __high2float(h1);
            *reinterpret_cast<__nv_bfloat162*>(Chi + oidx)     = h0;
            *reinterpret_cast<__nv_bfloat162*>(Chi + oidx + 2) = h1;
            *reinterpret_cast<__nv_bfloat162*>(Clo + oidx)     = __floats2bfloat162_rn(rx, ry);
            *reinterpret_cast<__nv_bfloat162*>(Clo + oidx + 2) = __floats2bfloat162_rn(rz, rw);
        } else {
            *reinterpret_cast<float4*>(C + oidx) = v;
        }
    }
}

// ---------------------------------------------------------------------------
// Fused attention (R8-proven: R4 layout, hi/lo bf16 output)
// ---------------------------------------------------------------------------
template <bool CAUSAL>
__global__ void __launch_bounds__(128)
attn_kernel(const float* __restrict__ Q, const float* __restrict__ K,
            const float* __restrict__ V, bf16* __restrict__ Ohi,
            bf16* __restrict__ Olo, int Lk)
{
    __shared__ float Qs[32 * 64];
    __shared__ float Kst[64 * 33];
    __shared__ float Vs[32 * 68];
    __shared__ float Ps[32 * 32];

    const int b    = blockIdx.z;
    const int h    = blockIdx.y;
    const int q0   = blockIdx.x * 32;
    const int tid  = threadIdx.x;
    const int lane = tid & 31;
    const int w    = tid >> 5;
    const int r0   = w * 8;

#pragma unroll
    for (int s = tid; s < 512; s += 128) {
        int r  = s >> 4;
        int c4 = s & 15;
        float4 v = *reinterpret_cast<const float4*>(
            Q + (size_t)(b * Sc + q0 + r) * Dc + h * 64 + c4 * 4);
        *reinterpret_cast<float4*>(&Qs[r * 64 + c4 * 4]) = v;
    }

    float m_run[8], l_run[8], o0[8], o1[8];
#pragma unroll
    for (int r = 0; r < 8; r++) { m_run[r] = -1e30f; l_run[r] = 0.f; o0[r] = 0.f; o1[r] = 0.f; }

    const int nkt = CAUSAL ? (blockIdx.x + 1) : (Lk >> 5);

    for (int kt = 0; kt < nkt; kt++) {
        const int k0 = kt * 32;
        __syncthreads();
#pragma unroll
        for (int s = tid; s < 512; s += 128) {
            int r  = s >> 4;
            int c4 = s & 15;
            size_t base = (size_t)(b * Lk + k0 + r) * Dc + h * 64 + c4 * 4;
            float4 kv = *reinterpret_cast<const float4*>(K + base);
            Kst[(c4 * 4 + 0) * 33 + r] = kv.x;
            Kst[(c4 * 4 + 1) * 33 + r] = kv.y;
            Kst[(c4 * 4 + 2) * 33 + r] = kv.z;
            Kst[(c4 * 4 + 3) * 33 + r] = kv.w;
            float4 vv = *reinterpret_cast<const float4*>(V + base);
            *reinterpret_cast<float4*>(&Vs[r * 68 + c4 * 4]) = vv;
        }
        __syncthreads();

        float sc[8];
#pragma unroll
        for (int r = 0; r < 8; r++) sc[r] = 0.f;
#pragma unroll
        for (int d4 = 0; d4 < 16; d4++) {
            float k0v = Kst[(d4 * 4 + 0) * 33 + lane];
            float k1v = Kst[(d4 * 4 + 1) * 33 + lane];
            float k2v = Kst[(d4 * 4 + 2) * 33 + lane];
            float k3v = Kst[(d4 * 4 + 3) * 33 + lane];
#pragma unroll
            for (int r = 0; r < 8; r++) {
                float4 qv = *reinterpret_cast<const float4*>(&Qs[(r0 + r) * 64 + d4 * 4]);
                sc[r] += qv.x * k0v + qv.y * k1v + qv.z * k2v + qv.w * k3v;
            }
        }
#pragma unroll
        for (int r = 0; r < 8; r++) {
            sc[r] *= 0.125f;
            if (CAUSAL) {
                int qg = q0 + r0 + r;
                int kg = k0 + lane;
                if (kg > qg) sc[r] = -1e9f;
            }
        }
#pragma unroll
        for (int r = 0; r < 8; r++) {
            float mx = sc[r];
#pragma unroll
            for (int off = 16; off > 0; off >>= 1)
                mx = fmaxf(mx, __shfl_xor_sync(0xffffffffu, mx, off));
            float m_new = fmaxf(m_run[r], mx);
            float p = __expf(sc[r] - m_new);
            float ps = p;
#pragma unroll
            for (int off = 16; off > 0; off >>= 1)
                ps += __shfl_xor_sync(0xffffffffu, ps, off);
            float alpha = __expf(m_run[r] - m_new);
            l_run[r] = l_run[r] * alpha + ps;
            m_run[r] = m_new;
            o0[r] *= alpha;
            o1[r] *= alpha;
            Ps[(r0 + r) * 32 + lane] = p;
        }
        __syncwarp();
#pragma unroll
        for (int k4 = 0; k4 < 8; k4++) {
            float v00 = Vs[(k4 * 4 + 0) * 68 + lane];
            float v01 = Vs[(k4 * 4 + 1) * 68 + lane];
            float v02 = Vs[(k4 * 4 + 2) * 68 + lane];
            float v03 = Vs[(k4 * 4 + 3) * 68 + lane];
            float v10 = Vs[(k4 * 4 + 0) * 68 + 32 + lane];
            float v11 = Vs[(k4 * 4 + 1) * 68 + 32 + lane];
            float v12 = Vs[(k4 * 4 + 2) * 68 + 32 + lane];
            float v13 = Vs[(k4 * 4 + 3) * 68 + 32 + lane];
#pragma unroll
            for (int r = 0; r < 8; r++) {
                float4 pv = *reinterpret_cast<const float4*>(&Ps[(r0 + r) * 32 + k4 * 4]);
                o0[r] += pv.x * v00 + pv.y * v01 + pv.z * v02 + pv.w * v03;
                o1[r] += pv.x * v10 + pv.y * v11 + pv.z * v12 + pv.w * v13;
            }
        }
    }

#pragma unroll
    for (int r = 0; r < 8; r++) {
        float invl = 1.f / l_run[r];
        size_t base = (size_t)(b * Sc + q0 + r0 + r) * Dc + h * 64;
        float v0 = o0[r] * invl, v1 = o1[r] * invl;
        bf16 h0, l0, h1, l1;
        split1(v0, h0, l0);
        split1(v1, h1, l1);
        Ohi[base + lane]      = h0;
        Olo[base + lane]      = l0;
        Ohi[base + 32 + lane] = h1;
        Olo[base + 32 + lane] = l1;
    }
}

// ---------------------------------------------------------------------------
// Residual + LayerNorm; writes fp32 + hi/lo bf16 mirrors
// ---------------------------------------------------------------------------
__global__ void __launch_bounds__(256)
ln_kernel(const float* __restrict__ x, const float* __restrict__ add,
          const float* __restrict__ s, const float* __restrict__ b,
          float* __restrict__ out, bf16* __restrict__ ohi, bf16* __restrict__ olo)
{
    const int row = blockIdx.x;
    const int tid = threadIdx.x;
    const size_t base = (size_t)row * Dc;

    float v[4];
    float sum = 0.f, sq = 0.f;
#pragma unroll
    for (int i = 0; i < 4; i++) {
        int c = tid + i * 256;
        float val = x[base + c];
        if (add) val += add[base + c];
        v[i] = val;
        sum += val;
        sq  += val * val;
    }
#pragma unroll
    for (int off = 16; off > 0; off >>= 1) {
        sum += __shfl_xor_sync(0xffffffffu, sum, off);
        sq  += __shfl_xor_sync(0xffffffffu, sq, off);
    }
    __shared__ float s1[8], s2[8];
    __shared__ float mu_s, inv_s;
    int lane = tid & 31, wid = tid >> 5;
    if (lane == 0) { s1[wid] = sum; s2[wid] = sq; }
    __syncthreads();
    if (tid == 0) {
        float ts = 0.f, tq = 0.f;
#pragma unroll
        for (int i = 0; i < 8; i++) { ts += s1[i]; tq += s2[i]; }
        float mu  = ts * (1.f / Dc);
        float var = tq * (1.f / Dc) - mu * mu;
        mu_s  = mu;
        inv_s = rsqrtf(var + 1e-5f);
    }
    __syncthreads();
    float mu = mu_s, inv = inv_s;
#pragma unroll
    for (int i = 0; i < 4; i++) {
        int c = tid + i * 256;
        float r = (v[i] - mu) * inv * s[c] + b[c];
        out[base + c] = r;
        bf16 h, l;
        split1(r, h, l);
        ohi[base + c] = h;
        olo[base + c] = l;
    }
}

// ---------------------------------------------------------------------------
// Embedding gather + positional add; writes fp32 + hi/lo
// ---------------------------------------------------------------------------
__global__ void __launch_bounds__(256)
embed_kernel(const int* __restrict__ seq, const float* __restrict__ emb,
             const float* __restrict__ pos, float* __restrict__ x,
             bf16* __restrict__ xhi, bf16* __restrict__ xlo)
{
    const int row  = blockIdx.x;
    const int sidx = row & (Sc - 1);
    const int tok  = seq[row];
    const int tid  = threadIdx.x;
#pragma unroll
    for (int i = 0; i < 4; i++) {
        int c = tid + i * 256;
        float r = emb[(size_t)tok * Dc + c] + pos[(size_t)sidx * Dc + c];
        size_t o = (size_t)row * Dc + c;
        x[o] = r;
        bf16 h, l;
        split1(r, h, l);
        xhi[o] = h;
        xlo[o] = l;
    }
}

// ---------------------------------------------------------------------------
// Host orchestration
// ---------------------------------------------------------------------------
template <bool BIAS, bool RELU, bool OUTSPLIT>
static void launch_gemm(const bf16* ahi, const bf16* alo,
                        const bf16* bhi, const bf16* blo,
                        const float* bias, float* C, bf16* chi, bf16* clo,
                        int M, int N, int K)
{
    cudaFuncSetAttribute(tc_gemm<BIAS, RELU, OUTSPLIT>,
                         cudaFuncAttributeMaxDynamicSharedMemorySize, GEMM_SMEM);
    dim3 grid(N / 128, M / 128);
    tc_gemm<BIAS, RELU, OUTSPLIT><<<grid, 256, GEMM_SMEM>>>(
        ahi, alo, bhi, blo, bias, C, chi, clo, M, N, K);
}

extern "C" void kernel_launch(void* const* d_in, const int* in_sizes, int n_in,
                              void* d_out, int out_size)
{
    (void)in_sizes; (void)n_in; (void)out_size;

    const float* encoded      = (const float*)d_in[0];
    const int*   seq          = (const int*)  d_in[1];
    const float* input_embed  = (const float*)d_in[2];
    const float* output_embed = (const float*)d_in[3];
    const float* output_bias  = (const float*)d_in[4];
    const float* pos_embed    = (const float*)d_in[5];
    const float* Wq  = (const float*)d_in[6];
    const float* Wk  = (const float*)d_in[7];
    const float* Wv  = (const float*)d_in[8];
    const float* Wo  = (const float*)d_in[9];
    const float* Wqc = (const float*)d_in[10];
    const float* Wkc = (const float*)d_in[11];
    const float* Wvc = (const float*)d_in[12];
    const float* Woc = (const float*)d_in[13];
    const float* W1  = (const float*)d_in[14];
    const float* b1  = (const float*)d_in[15];
    const float* W2  = (const float*)d_in[16];
    const float* b2  = (const float*)d_in[17];
    const float* ln1s = (const float*)d_in[18];
    const float* ln1b = (const float*)d_in[19];
    const float* ln2s = (const float*)d_in[20];
    const float* ln2b = (const float*)d_in[21];
    const float* ln3s = (const float*)d_in[22];
    const float* ln3b = (const float*)d_in[23];
    const float* lnfs = (const float*)d_in[24];
    const float* lnfb = (const float*)d_in[25];

    float *x, *q, *k, *v, *o;
    cudaGetSymbolAddress((void**)&x, g_x);
    cudaGetSymbolAddress((void**)&q, g_q);
    cudaGetSymbolAddress((void**)&k, g_k);
    cudaGetSymbolAddress((void**)&v, g_v);
    cudaGetSymbolAddress((void**)&o, g_o);
    bf16 *whi, *wlo, *xhi, *xlo, *ahi, *alo, *fhi, *flo, *ehi, *elo;
    cudaGetSymbolAddress((void**)&whi, g_whi);
    cudaGetSymbolAddress((void**)&wlo, g_wlo);
    cudaGetSymbolAddress((void**)&xhi, g_xhi);
    cudaGetSymbolAddress((void**)&xlo, g_xlo);
    cudaGetSymbolAddress((void**)&ahi, g_ahi);
    cudaGetSymbolAddress((void**)&alo, g_alo);
    cudaGetSymbolAddress((void**)&fhi, g_fhi);
    cudaGetSymbolAddress((void**)&flo, g_flo);
    cudaGetSymbolAddress((void**)&ehi, g_ehi);
    cudaGetSymbolAddress((void**)&elo, g_elo);

    // ---- conversions: 2 launches ----
    convT_all<<<dim3(4096, 1, 60), dim3(32, 8)>>>(Wq, Wk, Wv, Wo, Wqc, Wkc, Wvc, Woc,
                                                  W1, W2, whi, wlo);
    conv_all<<<dim3(Vc, 1, 2), 256>>>((const float4*)output_embed, (const float4*)encoded,
                                      (__nv_bfloat162*)(whi + EOFF),
                                      (__nv_bfloat162*)(wlo + EOFF),
                                      (__nv_bfloat162*)ehi, (__nv_bfloat162*)elo);

    const int NR  = Bc * Sc;   // 4096
    const int NRE = Bc * Mc;   // 8192

    embed_kernel<<<NR, 256>>>(seq, input_embed, pos_embed, x, xhi, xlo);

    const dim3 agrid(Sc / 32, Hc, Bc);   // (16, 16, 8)

    for (int i = 0; i < Lc; i++) {
        const size_t lb = (size_t)i * WOFF_LAYER;
        const bf16* wq = whi + lb;
        const bf16* lq = wlo + lb;

        // ---- self attention ----
        launch_gemm<false, false, false>(xhi, xlo, wq + 0 * 1048576, lq + 0 * 1048576,
                                         nullptr, q, nullptr, nullptr, NR, Dc, Dc);
        launch_gemm<false, false, false>(xhi, xlo, wq + 1 * 1048576, lq + 1 * 1048576,
                                         nullptr, k, nullptr, nullptr, NR, Dc, Dc);
        launch_gemm<false, false, false>(xhi, xlo, wq + 2 * 1048576, lq + 2 * 1048576,
                                         nullptr, v, nullptr, nullptr, NR, Dc, Dc);
        attn_kernel<true><<<agrid, 128>>>(q, k, v, ahi, alo, Sc);
        launch_gemm<false, false, false>(ahi, alo, wq + 3 * 1048576, lq + 3 * 1048576,
                                         nullptr, o, nullptr, nullptr, NR, Dc, Dc);
        ln_kernel<<<NR, 256>>>(x, o, ln1s + (size_t)i * Dc, ln1b + (size_t)i * Dc,
                               x, xhi, xlo);

        // ---- cross attention ----
        launch_gemm<false, false, false>(xhi, xlo, wq + 4 * 1048576, lq + 4 * 1048576,
                                         nullptr, q, nullptr, nullptr, NR, Dc, Dc);
        launch_gemm<false, false, false>(ehi, elo, wq + 5 * 1048576, lq + 5 * 1048576,
                                         nullptr, k, nullptr, nullptr, NRE, Dc, Dc);
        launch_gemm<false, false, false>(ehi, elo, wq + 6 * 1048576, lq + 6 * 1048576,
                                         nullptr, v, nullptr, nullptr, NRE, Dc, Dc);
        attn_kernel<false><<<agrid, 128>>>(q, k, v, ahi, alo, Mc);
        launch_gemm<false, false, false>(ahi, alo, wq + 7 * 1048576, lq + 7 * 1048576,
                                         nullptr, o, nullptr, nullptr, NR, Dc, Dc);
        ln_kernel<<<NR, 256>>>(x, o, ln2s + (size_t)i * Dc, ln2b + (size_t)i * Dc,
                               x, xhi, xlo);

        // ---- FFN ----
        launch_gemm<true, true, true>(xhi, xlo, wq + WOFF_W1, lq + WOFF_W1,
                                      b1 + (size_t)i * DFc, nullptr, fhi, flo,
                                      NR, DFc, Dc);
        launch_gemm<true, false, false>(fhi, flo, wq + WOFF_W2, lq + WOFF_W2,
                                        b2 + (size_t)i * Dc, o, nullptr, nullptr,
                                        NR, Dc, DFc);
        ln_kernel<<<NR, 256>>>(x, o, ln3s + (size_t)i * Dc, ln3b + (size_t)i * Dc,
                               x, xhi, xlo);
    }

    // final norm + logits
    ln_kernel<<<NR, 256>>>(x, nullptr, lnfs, lnfb, x, xhi, xlo);
    launch_gemm<true, false, false>(xhi, xlo, whi + EOFF, wlo + EOFF,
                                    output_bias, (float*)d_out, nullptr, nullptr,
                                    NR, Vc, Dc);
}

// round 11
// speedup vs baseline: 1.0565x; 1.0051x over previous
#include <cuda_runtime.h>
#include <cuda_bf16.h>
#include <math.h>
#include <stdint.h>

// Problem constants
#define Bc   8
#define Sc   512
#define Dc   1024
#define Hc   16
#define DHc  64
#define Mc   1024
#define DFc  4096
#define Vc   32000
#define Lc   6

typedef __nv_bfloat16 bf16;

// ---------------------------------------------------------------------------
// Scratch (device globals)
// ---------------------------------------------------------------------------
__device__ float g_x[Bc * Sc * Dc];        // residual stream fp32
__device__ float g_q[Bc * Sc * Dc];
__device__ float g_k[Bc * Mc * Dc];
__device__ float g_v[Bc * Mc * Dc];
__device__ float g_o[Bc * Sc * Dc];
// hi/lo bf16 activation mirrors (GEMM A-side inputs)
__device__ bf16 g_xhi[Bc * Sc * Dc],  g_xlo[Bc * Sc * Dc];
__device__ bf16 g_ahi[Bc * Sc * Dc],  g_alo[Bc * Sc * Dc];
__device__ bf16 g_fhi[Bc * Sc * DFc], g_flo[Bc * Sc * DFc];
__device__ bf16 g_ehi[Bc * Mc * Dc],  g_elo[Bc * Mc * Dc];

// Pre-converted weights: [N,K] bf16 hi/lo.
#define WOFF_LAYER 16777216ull
#define WOFF_W1    8388608ull
#define WOFF_W2    12582912ull
#define EOFF       100663296ull
#define WTOTAL     133431296ull
__device__ bf16 g_whi[WTOTAL];
__device__ bf16 g_wlo[WTOTAL];

// ===========================================================================
// helpers
// ===========================================================================
__device__ __forceinline__ uint32_t smem_u32(const void* p) {
    uint32_t a;
    asm("{ .reg .u64 t; cvta.to.shared.u64 t, %1; cvt.u32.u64 %0, t; }"
        : "=r"(a) : "l"(p));
    return a;
}

__device__ __forceinline__ void mma_bf16(float* d, const uint32_t* a, const uint32_t* b) {
    asm volatile(
        "mma.sync.aligned.m16n8k16.row.col.f32.bf16.bf16.f32 "
        "{%0,%1,%2,%3}, {%4,%5,%6,%7}, {%8,%9}, {%0,%1,%2,%3};"
        : "+f"(d[0]), "+f"(d[1]), "+f"(d[2]), "+f"(d[3])
        : "r"(a[0]), "r"(a[1]), "r"(a[2]), "r"(a[3]), "r"(b[0]), "r"(b[1]));
}

#define LDSM_X4(r, addr) \
    asm volatile("ldmatrix.sync.aligned.m8n8.x4.shared.b16 {%0,%1,%2,%3}, [%4];" \
        : "=r"((r)[0]), "=r"((r)[1]), "=r"((r)[2]), "=r"((r)[3]) : "r"(addr))

#define CP_ASYNC16(dst, src) \
    asm volatile("cp.async.cg.shared.global [%0], [%1], 16;" :: "r"(dst), "l"(src))
#define CP_COMMIT()  asm volatile("cp.async.commit_group;" ::: "memory")
#define CP_WAIT1()   asm volatile("cp.async.wait_group 1;" ::: "memory")
#define CP_WAIT0()   asm volatile("cp.async.wait_group 0;" ::: "memory")

// split one float into hi/lo bf16
__device__ __forceinline__ void split1(float v, bf16& h, bf16& l) {
    h = __float2bfloat16(v);
    l = __float2bfloat16(v - __bfloat162float(h));
}

// ===========================================================================
// Conversion kernels — 2 launches total
// ===========================================================================
__global__ void convT_all(const float* __restrict__ Wq, const float* __restrict__ Wk,
                          const float* __restrict__ Wv, const float* __restrict__ Wo,
                          const float* __restrict__ Wqc, const float* __restrict__ Wkc,
                          const float* __restrict__ Wvc, const float* __restrict__ Woc,
                          const float* __restrict__ W1, const float* __restrict__ W2,
                          bf16* __restrict__ hi, bf16* __restrict__ lo)
{
    __shared__ float ts[32][33];
    const int z = blockIdx.z;
    const int t = blockIdx.x;

    const float* src;
    bf16 *ho, *lo_;
    int K, N, k0, n0;

    if (z < 48) {
        if (t >= 1024) return;
        const int layer = z >> 3;
        const int j     = z & 7;
        const float* srcs[8] = { Wq, Wk, Wv, Wo, Wqc, Wkc, Wvc, Woc };
        src = srcs[j] + (size_t)layer * Dc * Dc;
        ho  = hi + (size_t)layer * WOFF_LAYER + (size_t)j * 1048576;
        lo_ = lo + (size_t)layer * WOFF_LAYER + (size_t)j * 1048576;
        K = Dc; N = Dc;
        k0 = (t >> 5) * 32;
        n0 = (t & 31) * 32;
    } else if (z < 54) {
        const int layer = z - 48;
        src = W1 + (size_t)layer * Dc * DFc;
        ho  = hi + (size_t)layer * WOFF_LAYER + WOFF_W1;
        lo_ = lo + (size_t)layer * WOFF_LAYER + WOFF_W1;
        K = Dc; N = DFc;
        n0 = (t & 127) * 32;
        k0 = (t >> 7) * 32;
    } else {
        const int layer = z - 54;
        src = W2 + (size_t)layer * DFc * Dc;
        ho  = hi + (size_t)layer * WOFF_LAYER + WOFF_W2;
        lo_ = lo + (size_t)layer * WOFF_LAYER + WOFF_W2;
        K = DFc; N = Dc;
        n0 = (t & 31) * 32;
        k0 = (t >> 5) * 32;
    }

    const int tx = threadIdx.x, ty = threadIdx.y;
#pragma unroll
    for (int j = 0; j < 4; j++)
        ts[ty + j * 8][tx] = src[(size_t)(k0 + ty + j * 8) * N + n0 + tx];
    __syncthreads();
#pragma unroll
    for (int j = 0; j < 4; j++) {
        int n = ty + j * 8;
        float v = ts[tx][n];
        size_t o = (size_t)(n0 + n) * K + k0 + tx;
        split1(v, ho[o], lo_[o]);
    }
}

__global__ void conv_all(const float4* __restrict__ outemb, const float4* __restrict__ enc,
                         __nv_bfloat162* __restrict__ ehi_w, __nv_bfloat162* __restrict__ elo_w,
                         __nv_bfloat162* __restrict__ ehi_e, __nv_bfloat162* __restrict__ elo_e)
{
    const int z = blockIdx.z;
    if (z == 1 && blockIdx.x >= (Bc * Mc)) return;
    const float4* src = (z == 0) ? outemb : enc;
    __nv_bfloat162* hi = (z == 0) ? ehi_w : ehi_e;
    __nv_bfloat162* lo = (z == 0) ? elo_w : elo_e;

    size_t i = (size_t)blockIdx.x * blockDim.x + threadIdx.x;
    float4 v = src[i];
    __nv_bfloat162 h0 = __floats2bfloat162_rn(v.x, v.y);
    __nv_bfloat162 h1 = __floats2bfloat162_rn(v.z, v.w);
    float rx = v.x - __low2float(h0), ry = v.y - __high2float(h0);
    float rz = v.z - __low2float(h1), rw = v.w - __high2float(h1);
    hi[i * 2]     = h0;
    hi[i * 2 + 1] = h1;
    lo[i * 2]     = __floats2bfloat162_rn(rx, ry);
    lo[i * 2 + 1] = __floats2bfloat162_rn(rz, rw);
}

// ===========================================================================
// Tensor-core GEMM v4: 3-stage cp.async pipeline, ONE barrier per K-stage,
// ldmatrix direct-operand fragments, 2 CTAs/SM.
// ===========================================================================
#define PROWB  144
#define TILEB  (64 * PROWB)
#define STAGEB (4 * TILEB)                 // 36864 B per pipeline stage
#define NSTAGE 3
#define GEMM_SMEM (NSTAGE * STAGEB)        // 110592 B
#define ROWOFF(r) (((r) & 63) * PROWB + ((r) >> 6) * 64)

template <bool BIAS, bool RELU, bool OUTSPLIT>
__global__ void __launch_bounds__(256, 2)
tc_gemm(const bf16* __restrict__ Ahi_g, const bf16* __restrict__ Alo_g,
        const bf16* __restrict__ Bhi_g, const bf16* __restrict__ Blo_g,
        const float* __restrict__ bias, float* __restrict__ C,
        bf16* __restrict__ Chi, bf16* __restrict__ Clo,
        int M, int N, int K)
{
    extern __shared__ char smem[];
    const int tid  = threadIdx.x;
    const int wid  = tid >> 5;
    const int lane = tid & 31;
    const int g    = lane >> 2;
    const int t    = lane & 3;
    const int wm   = wid & 1;
    const int wn   = wid >> 1;
    const int m0   = blockIdx.y * 128;
    const int n0   = blockIdx.x * 128;

    const uint32_t smem0 = smem_u32(smem);

    // ---- ldmatrix per-lane address offsets (direct operand-order) ----
    const int arow_l = (lane & 7) + ((lane >> 3) & 1) * 8;   // 0..15
    const uint32_t aoffL =
        (uint32_t)(arow_l * PROWB + wm * 64 + (lane >> 4) * 16);
    const int brow_l = ((lane >> 4) & 1) * 8 + (lane & 7);   // 0..15
    const uint32_t boffL =
        (uint32_t)(((wn & 1) * 32 + brow_l) * PROWB + (wn >> 1) * 64 +
                   ((lane >> 3) & 1) * 16);

    float acc[4][4][4];
#pragma unroll
    for (int i = 0; i < 4; i++)
#pragma unroll
        for (int j = 0; j < 4; j++)
#pragma unroll
            for (int c = 0; c < 4; c++) acc[i][j][c] = 0.f;

    const int S = K >> 5;

    auto cp_stage = [&](int s, int b) {
        const int k0 = s << 5;
        char* base = smem + b * STAGEB;
#pragma unroll
        for (int i = 0; i < 8; i++) {
            const int sel  = i >> 1;
            const int idx2 = tid + (i & 1) * 256;
            const int r    = idx2 >> 2;
            const int c    = idx2 & 3;
            const bf16* srcs[4] = { Ahi_g, Alo_g, Bhi_g, Blo_g };
            const int   rg  = (sel < 2 ? m0 : n0) + r;
            const bf16* src = srcs[sel] + (size_t)rg * K + k0 + c * 8;
            uint32_t dst = smem_u32(base + sel * TILEB + ROWOFF(r) + c * 16);
            CP_ASYNC16(dst, src);
        }
    };

    auto compute = [&](int b) {
        const uint32_t base = smem0 + b * STAGEB;
        const uint32_t Ah = base + aoffL;
        const uint32_t Al = base + TILEB + aoffL;
        const uint32_t Bh = base + 2 * TILEB + boffL;
        const uint32_t Bl = base + 3 * TILEB + boffL;
#pragma unroll
        for (int ks = 0; ks < 2; ks++) {
            const uint32_t kb = ks * 32;
            uint32_t ah[4][4], al[4][4], bh[2][4], bl[2][4];
#pragma unroll
            for (int mt = 0; mt < 4; mt++)
                LDSM_X4(ah[mt], Ah + mt * (16 * PROWB) + kb);
#pragma unroll
            for (int j = 0; j < 2; j++)
                LDSM_X4(bh[j], Bh + j * (16 * PROWB) + kb);
#pragma unroll
            for (int mt = 0; mt < 4; mt++)
#pragma unroll
                for (int nt = 0; nt < 4; nt++)
                    mma_bf16(acc[mt][nt], ah[mt], &bh[nt >> 1][(nt & 1) * 2]);
#pragma unroll
            for (int j = 0; j < 2; j++)
                LDSM_X4(bl[j], Bl + j * (16 * PROWB) + kb);
#pragma unroll
            for (int mt = 0; mt < 4; mt++)
#pragma unroll
                for (int nt = 0; nt < 4; nt++)
                    mma_bf16(acc[mt][nt], ah[mt], &bl[nt >> 1][(nt & 1) * 2]);
#pragma unroll
            for (int mt = 0; mt < 4; mt++)
                LDSM_X4(al[mt], Al + mt * (16 * PROWB) + kb);
#pragma unroll
            for (int mt = 0; mt < 4; mt++)
#pragma unroll
                for (int nt = 0; nt < 4; nt++)
                    mma_bf16(acc[mt][nt], al[mt], &bh[nt >> 1][(nt & 1) * 2]);
        }
    };

    // ---- 3-stage pipeline, one barrier per stage ----
    // iter s: wait(stage s done; s+1 may be in flight) -> sync (also separates
    // all warps' compute(s-1) from the cp below that refills its buffer)
    // -> cp(s+2 into (s+2)%3) -> compute(s%3).
    cp_stage(0, 0);
    CP_COMMIT();
    if (S > 1) { cp_stage(1, 1); CP_COMMIT(); }

    for (int s = 0; s < S; s++) {
        if (s + 1 < S) CP_WAIT1();
        else           CP_WAIT0();
        __syncthreads();
        if (s + 2 < S) { cp_stage(s + 2, (s + 2) % NSTAGE); CP_COMMIT(); }
        compute(s % NSTAGE);
    }
    __syncthreads();   // all computes done before epilogue reuses smem

    // ---- epilogue ----
    float* stage = reinterpret_cast<float*>(smem);
#pragma unroll
    for (int mt = 0; mt < 4; mt++) {
#pragma unroll
        for (int nt = 0; nt < 4; nt++) {
            int row = wm * 64 + mt * 16 + g;
            int col = wn * 32 + nt * 8 + t * 2;
            *reinterpret_cast<float2*>(&stage[row * 132 + col]) =
                make_float2(acc[mt][nt][0], acc[mt][nt][1]);
            *reinterpret_cast<float2*>(&stage[(row + 8) * 132 + col]) =
                make_float2(acc[mt][nt][2], acc[mt][nt][3]);
        }
    }
    __syncthreads();

#pragma unroll
    for (int i = 0; i < 16; i++) {
        int f   = i * 256 + tid;
        int row = f >> 5;
        int c4  = f & 31;
        float4 v = *reinterpret_cast<float4*>(&stage[row * 132 + c4 * 4]);
        if (BIAS) {
            float4 bv = *reinterpret_cast<const float4*>(bias + n0 + c4 * 4);
            v.x += bv.x; v.y += bv.y; v.z += bv.z; v.w += bv.w;
        }
        if (RELU) {
            v.x = fmaxf(v.x, 0.f); v.y = fmaxf(v.y, 0.f);
            v.z = fmaxf(v.z, 0.f); v.w = fmaxf(v.w, 0.f);
        }
        size_t oidx = (size_t)(m0 + row) * N + n0 + c4 * 4;
        if (OUTSPLIT) {
            __nv_bfloat162 h0 = __floats2bfloat162_rn(v.x, v.y);
            __nv_bfloat162 h1 = __floats2bfloat162_rn(v.z, v.w);
            float rx = v.x - __low2float(h0), ry = v.y - __high2float(h0);
            float rz = v.z - __low2float(h1), rw = v.w - __high2float(h1);
            *reinterpret_cast<__nv_bfloat162*>(Chi + oidx)     = h0;
            *reinterpret_cast<__nv_bfloat162*>(Chi + oidx + 2) = h1;
            *reinterpret_cast<__nv_bfloat162*>(Clo + oidx)     = __floats2bfloat162_rn(rx, ry);
            *reinterpret_cast<__nv_bfloat162*>(Clo + oidx + 2) = __floats2bfloat162_rn(rz, rw);
        } else {
            *reinterpret_cast<float4*>(C + oidx) = v;
        }
    }
}

// ---------------------------------------------------------------------------
// Fused attention (R8-proven: R4 layout, hi/lo bf16 output)
// ---------------------------------------------------------------------------
template <bool CAUSAL>
__global__ void __launch_bounds__(128)
attn_kernel(const float* __restrict__ Q, const float* __restrict__ K,
            const float* __restrict__ V, bf16* __restrict__ Ohi,
            bf16* __restrict__ Olo, int Lk)
{
    __shared__ float Qs[32 * 64];
    __shared__ float Kst[64 * 33];
    __shared__ float Vs[32 * 68];
    __shared__ float Ps[32 * 32];

    const int b    = blockIdx.z;
    const int h    = blockIdx.y;
    const int q0   = blockIdx.x * 32;
    const int tid  = threadIdx.x;
    const int lane = tid & 31;
    const int w    = tid >> 5;
    const int r0   = w * 8;

#pragma unroll
    for (int s = tid; s < 512; s += 128) {
        int r  = s >> 4;
        int c4 = s & 15;
        float4 v = *reinterpret_cast<const float4*>(
            Q + (size_t)(b * Sc + q0 + r) * Dc + h * 64 + c4 * 4);
        *reinterpret_cast<float4*>(&Qs[r * 64 + c4 * 4]) = v;
    }

    float m_run[8], l_run[8], o0[8], o1[8];
#pragma unroll
    for (int r = 0; r < 8; r++) { m_run[r] = -1e30f; l_run[r] = 0.f; o0[r] = 0.f; o1[r] = 0.f; }

    const int nkt = CAUSAL ? (blockIdx.x + 1) : (Lk >> 5);

    for (int kt = 0; kt < nkt; kt++) {
        const int k0 = kt * 32;
        __syncthreads();
#pragma unroll
        for (int s = tid; s < 512; s += 128) {
            int r  = s >> 4;
            int c4 = s & 15;
            size_t base = (size_t)(b * Lk + k0 + r) * Dc + h * 64 + c4 * 4;
            float4 kv = *reinterpret_cast<const float4*>(K + base);
            Kst[(c4 * 4 + 0) * 33 + r] = kv.x;
            Kst[(c4 * 4 + 1) * 33 + r] = kv.y;
            Kst[(c4 * 4 + 2) * 33 + r] = kv.z;
            Kst[(c4 * 4 + 3) * 33 + r] = kv.w;
            float4 vv = *reinterpret_cast<const float4*>(V + base);
            *reinterpret_cast<float4*>(&Vs[r * 68 + c4 * 4]) = vv;
        }
        __syncthreads();

        float sc[8];
#pragma unroll
        for (int r = 0; r < 8; r++) sc[r] = 0.f;
#pragma unroll
        for (int d4 = 0; d4 < 16; d4++) {
            float k0v = Kst[(d4 * 4 + 0) * 33 + lane];
            float k1v = Kst[(d4 * 4 + 1) * 33 + lane];
            float k2v = Kst[(d4 * 4 + 2) * 33 + lane];
            float k3v = Kst[(d4 * 4 + 3) * 33 + lane];
#pragma unroll
            for (int r = 0; r < 8; r++) {
                float4 qv = *reinterpret_cast<const float4*>(&Qs[(r0 + r) * 64 + d4 * 4]);
                sc[r] += qv.x * k0v + qv.y * k1v + qv.z * k2v + qv.w * k3v;
            }
        }
#pragma unroll
        for (int r = 0; r < 8; r++) {
            sc[r] *= 0.125f;
            if (CAUSAL) {
                int qg = q0 + r0 + r;
                int kg = k0 + lane;
                if (kg > qg) sc[r] = -1e9f;
            }
        }
#pragma unroll
        for (int r = 0; r < 8; r++) {
            float mx = sc[r];
#pragma unroll
            for (int off = 16; off > 0; off >>= 1)
                mx = fmaxf(mx, __shfl_xor_sync(0xffffffffu, mx, off));
            float m_new = fmaxf(m_run[r], mx);
            float p = __expf(sc[r] - m_new);
            float ps = p;
#pragma unroll
            for (int off = 16; off > 0; off >>= 1)
                ps += __shfl_xor_sync(0xffffffffu, ps, off);
            float alpha = __expf(m_run[r] - m_new);
            l_run[r] = l_run[r] * alpha + ps;
            m_run[r] = m_new;
            o0[r] *= alpha;
            o1[r] *= alpha;
            Ps[(r0 + r) * 32 + lane] = p;
        }
        __syncwarp();
#pragma unroll
        for (int k4 = 0; k4 < 8; k4++) {
            float v00 = Vs[(k4 * 4 + 0) * 68 + lane];
            float v01 = Vs[(k4 * 4 + 1) * 68 + lane];
            float v02 = Vs[(k4 * 4 + 2) * 68 + lane];
            float v03 = Vs[(k4 * 4 + 3) * 68 + lane];
            float v10 = Vs[(k4 * 4 + 0) * 68 + 32 + lane];
            float v11 = Vs[(k4 * 4 + 1) * 68 + 32 + lane];
            float v12 = Vs[(k4 * 4 + 2) * 68 + 32 + lane];
            float v13 = Vs[(k4 * 4 + 3) * 68 + 32 + lane];
#pragma unroll
            for (int r = 0; r < 8; r++) {
                float4 pv = *reinterpret_cast<const float4*>(&Ps[(r0 + r) * 32 + k4 * 4]);
                o0[r] += pv.x * v00 + pv.y * v01 + pv.z * v02 + pv.w * v03;
                o1[r] += pv.x * v10 + pv.y * v11 + pv.z * v12 + pv.w * v13;
            }
        }
    }

#pragma unroll
    for (int r = 0; r < 8; r++) {
        float invl = 1.f / l_run[r];
        size_t base = (size_t)(b * Sc + q0 + r0 + r) * Dc + h * 64;
        float v0 = o0[r] * invl, v1 = o1[r] * invl;
        bf16 h0, l0, h1, l1;
        split1(v0, h0, l0);
        split1(v1, h1, l1);
        Ohi[base + lane]      = h0;
        Olo[base + lane]      = l0;
        Ohi[base + 32 + lane] = h1;
        Olo[base + 32 + lane] = l1;
    }
}

// ---------------------------------------------------------------------------
// Residual + LayerNorm; writes fp32 + hi/lo bf16 mirrors
// ---------------------------------------------------------------------------
__global__ void __launch_bounds__(256)
ln_kernel(const float* __restrict__ x, const float* __restrict__ add,
          const float* __restrict__ s, const float* __restrict__ b,
          float* __restrict__ out, bf16* __restrict__ ohi, bf16* __restrict__ olo)
{
    const int row = blockIdx.x;
    const int tid = threadIdx.x;
    const size_t base = (size_t)row * Dc;

    float v[4];
    float sum = 0.f, sq = 0.f;
#pragma unroll
    for (int i = 0; i < 4; i++) {
        int c = tid + i * 256;
        float val = x[base + c];
        if (add) val += add[base + c];
        v[i] = val;
        sum += val;
        sq  += val * val;
    }
#pragma unroll
    for (int off = 16; off > 0; off >>= 1) {
        sum += __shfl_xor_sync(0xffffffffu, sum, off);
        sq  += __shfl_xor_sync(0xffffffffu, sq, off);
    }
    __shared__ float s1[8], s2[8];
    __shared__ float mu_s, inv_s;
    int lane = tid & 31, wid = tid >> 5;
    if (lane == 0) { s1[wid] = sum; s2[wid] = sq; }
    __syncthreads();
    if (tid == 0) {
        float ts = 0.f, tq = 0.f;
#pragma unroll
        for (int i = 0; i < 8; i++) { ts += s1[i]; tq += s2[i]; }
        float mu  = ts * (1.f / Dc);
        float var = tq * (1.f / Dc) - mu * mu;
        mu_s  = mu;
        inv_s = rsqrtf(var + 1e-5f);
    }
    __syncthreads();
    float mu = mu_s, inv = inv_s;
#pragma unroll
    for (int i = 0; i < 4; i++) {
        int c = tid + i * 256;
        float r = (v[i] - mu) * inv * s[c] + b[c];
        out[base + c] = r;
        bf16 h, l;
        split1(r, h, l);
        ohi[base + c] = h;
        olo[base + c] = l;
    }
}

// ---------------------------------------------------------------------------
// Embedding gather + positional add; writes fp32 + hi/lo
// ---------------------------------------------------------------------------
__global__ void __launch_bounds__(256)
embed_kernel(const int* __restrict__ seq, const float* __restrict__ emb,
             const float* __restrict__ pos, float* __restrict__ x,
             bf16* __restrict__ xhi, bf16* __restrict__ xlo)
{
    const int row  = blockIdx.x;
    const int sidx = row & (Sc - 1);
    const int tok  = seq[row];
    const int tid  = threadIdx.x;
#pragma unroll
    for (int i = 0; i < 4; i++) {
        int c = tid + i * 256;
        float r = emb[(size_t)tok * Dc + c] + pos[(size_t)sidx * Dc + c];
        size_t o = (size_t)row * Dc + c;
        x[o] = r;
        bf16 h, l;
        split1(r, h, l);
        xhi[o] = h;
        xlo[o] = l;
    }
}

// ---------------------------------------------------------------------------
// Host orchestration
// ---------------------------------------------------------------------------
template <bool BIAS, bool RELU, bool OUTSPLIT>
static void launch_gemm(const bf16* ahi, const bf16* alo,
                        const bf16* bhi, const bf16* blo,
                        const float* bias, float* C, bf16* chi, bf16* clo,
                        int M, int N, int K)
{
    cudaFuncSetAttribute(tc_gemm<BIAS, RELU, OUTSPLIT>,
                         cudaFuncAttributeMaxDynamicSharedMemorySize, GEMM_SMEM);
    dim3 grid(N / 128, M / 128);
    tc_gemm<BIAS, RELU, OUTSPLIT><<<grid, 256, GEMM_SMEM>>>(
        ahi, alo, bhi, blo, bias, C, chi, clo, M, N, K);
}

extern "C" void kernel_launch(void* const* d_in, const int* in_sizes, int n_in,
                              void* d_out, int out_size)
{
    (void)in_sizes; (void)n_in; (void)out_size;

    const float* encoded      = (const float*)d_in[0];
    const int*   seq          = (const int*)  d_in[1];
    const float* input_embed  = (const float*)d_in[2];
    const float* output_embed = (const float*)d_in[3];
    const float* output_bias  = (const float*)d_in[4];
    const float* pos_embed    = (const float*)d_in[5];
    const float* Wq  = (const float*)d_in[6];
    const float* Wk  = (const float*)d_in[7];
    const float* Wv  = (const float*)d_in[8];
    const float* Wo  = (const float*)d_in[9];
    const float* Wqc = (const float*)d_in[10];
    const float* Wkc = (const float*)d_in[11];
    const float* Wvc = (const float*)d_in[12];
    const float* Woc = (const float*)d_in[13];
    const float* W1  = (const float*)d_in[14];
    const float* b1  = (const float*)d_in[15];
    const float* W2  = (const float*)d_in[16];
    const float* b2  = (const float*)d_in[17];
    const float* ln1s = (const float*)d_in[18];
    const float* ln1b = (const float*)d_in[19];
    const float* ln2s = (const float*)d_in[20];
    const float* ln2b = (const float*)d_in[21];
    const float* ln3s = (const float*)d_in[22];
    const float* ln3b = (const float*)d_in[23];
    const float* lnfs = (const float*)d_in[24];
    const float* lnfb = (const float*)d_in[25];

    float *x, *q, *k, *v, *o;
    cudaGetSymbolAddress((void**)&x, g_x);
    cudaGetSymbolAddress((void**)&q, g_q);
    cudaGetSymbolAddress((void**)&k, g_k);
    cudaGetSymbolAddress((void**)&v, g_v);
    cudaGetSymbolAddress((void**)&o, g_o);
    bf16 *whi, *wlo, *xhi, *xlo, *ahi, *alo, *fhi, *flo, *ehi, *elo;
    cudaGetSymbolAddress((void**)&whi, g_whi);
    cudaGetSymbolAddress((void**)&wlo, g_wlo);
    cudaGetSymbolAddress((void**)&xhi, g_xhi);
    cudaGetSymbolAddress((void**)&xlo, g_xlo);
    cudaGetSymbolAddress((void**)&ahi, g_ahi);
    cudaGetSymbolAddress((void**)&alo, g_alo);
    cudaGetSymbolAddress((void**)&fhi, g_fhi);
    cudaGetSymbolAddress((void**)&flo, g_flo);
    cudaGetSymbolAddress((void**)&ehi, g_ehi);
    cudaGetSymbolAddress((void**)&elo, g_elo);

    // ---- conversions: 2 launches ----
    convT_all<<<dim3(4096, 1, 60), dim3(32, 8)>>>(Wq, Wk, Wv, Wo, Wqc, Wkc, Wvc, Woc,
                                                  W1, W2, whi, wlo);
    conv_all<<<dim3(Vc, 1, 2), 256>>>((const float4*)output_embed, (const float4*)encoded,
                                      (__nv_bfloat162*)(whi + EOFF),
                                      (__nv_bfloat162*)(wlo + EOFF),
                                      (__nv_bfloat162*)ehi, (__nv_bfloat162*)elo);

    const int NR  = Bc * Sc;   // 4096
    const int NRE = Bc * Mc;   // 8192

    embed_kernel<<<NR, 256>>>(seq, input_embed, pos_embed, x, xhi, xlo);

    const dim3 agrid(Sc / 32, Hc, Bc);   // (16, 16, 8)

    for (int i = 0; i < Lc; i++) {
        const size_t lb = (size_t)i * WOFF_LAYER;
        const bf16* wq = whi + lb;
        const bf16* lq = wlo + lb;

        // ---- self attention ----
        launch_gemm<false, false, false>(xhi, xlo, wq + 0 * 1048576, lq + 0 * 1048576,
                                         nullptr, q, nullptr, nullptr, NR, Dc, Dc);
        launch_gemm<false, false, false>(xhi, xlo, wq + 1 * 1048576, lq + 1 * 1048576,
                                         nullptr, k, nullptr, nullptr, NR, Dc, Dc);
        launch_gemm<false, false, false>(xhi, xlo, wq + 2 * 1048576, lq + 2 * 1048576,
                                         nullptr, v, nullptr, nullptr, NR, Dc, Dc);
        attn_kernel<true><<<agrid, 128>>>(q, k, v, ahi, alo, Sc);
        launch_gemm<false, false, false>(ahi, alo, wq + 3 * 1048576, lq + 3 * 1048576,
                                         nullptr, o, nullptr, nullptr, NR, Dc, Dc);
        ln_kernel<<<NR, 256>>>(x, o, ln1s + (size_t)i * Dc, ln1b + (size_t)i * Dc,
                               x, xhi, xlo);

        // ---- cross attention ----
        launch_gemm<false, false, false>(xhi, xlo, wq + 4 * 1048576, lq + 4 * 1048576,
                                         nullptr, q, nullptr, nullptr, NR, Dc, Dc);
        launch_gemm<false, false, false>(ehi, elo, wq + 5 * 1048576, lq + 5 * 1048576,
                                         nullptr, k, nullptr, nullptr, NRE, Dc, Dc);
        launch_gemm<false, false, false>(ehi, elo, wq + 6 * 1048576, lq + 6 * 1048576,
                                         nullptr, v, nullptr, nullptr, NRE, Dc, Dc);
        attn_kernel<false><<<agrid, 128>>>(q, k, v, ahi, alo, Mc);
        launch_gemm<false, false, false>(ahi, alo, wq + 7 * 1048576, lq + 7 * 1048576,
                                         nullptr, o, nullptr, nullptr, NR, Dc, Dc);
        ln_kernel<<<NR, 256>>>(x, o, ln2s + (size_t)i * Dc, ln2b + (size_t)i * Dc,
                               x, xhi, xlo);

        // ---- FFN ----
        launch_gemm<true, true, true>(xhi, xlo, wq + WOFF_W1, lq + WOFF_W1,
                                      b1 + (size_t)i * DFc, nullptr, fhi, flo,
                                      NR, DFc, Dc);
        launch_gemm<true, false, false>(fhi, flo, wq + WOFF_W2, lq + WOFF_W2,
                                        b2 + (size_t)i * Dc, o, nullptr, nullptr,
                                        NR, Dc, DFc);
        ln_kernel<<<NR, 256>>>(x, o, ln3s + (size_t)i * Dc, ln3b + (size_t)i * Dc,
                               x, xhi, xlo);
    }

    // final norm + logits
    ln_kernel<<<NR, 256>>>(x, nullptr, lnfs, lnfb, x, xhi, xlo);
    launch_gemm<true, false, false>(xhi, xlo, whi + EOFF, wlo + EOFF,
                                    output_bias, (float*)d_out, nullptr, nullptr,
                                    NR, Vc, Dc);
}

// round 12
// speedup vs baseline: 1.7088x; 1.6174x over previous
#include <cuda_runtime.h>
#include <cuda_fp16.h>
#include <math.h>
#include <stdint.h>

// Problem constants
#define Bc   8
#define Sc   512
#define Dc   1024
#define Hc   16
#define DHc  64
#define Mc   1024
#define DFc  4096
#define Vc   32000
#define Lc   6

typedef __half h16;

// ---------------------------------------------------------------------------
// Scratch (device globals)
// ---------------------------------------------------------------------------
__device__ float g_x[Bc * Sc * Dc];        // residual stream fp32
__device__ float g_q[Bc * Sc * Dc];
__device__ float g_k[Bc * Mc * Dc];
__device__ float g_v[Bc * Mc * Dc];
__device__ float g_o[Bc * Sc * Dc];
// fp16 activation mirrors (GEMM A-side inputs)
__device__ h16 g_xh[Bc * Sc * Dc];
__device__ h16 g_ah[Bc * Sc * Dc];
__device__ h16 g_fh[Bc * Sc * DFc];
__device__ h16 g_eh[Bc * Mc * Dc];

// Pre-converted weights: [N,K] fp16.
#define WOFF_LAYER 16777216ull
#define WOFF_W1    8388608ull
#define WOFF_W2    12582912ull
#define EOFF       100663296ull
#define WTOTAL     133431296ull
__device__ h16 g_w[WTOTAL];

// ===========================================================================
// helpers
// ===========================================================================
__device__ __forceinline__ uint32_t smem_u32(const void* p) {
    uint32_t a;
    asm("{ .reg .u64 t; cvta.to.shared.u64 t, %1; cvt.u32.u64 %0, t; }"
        : "=r"(a) : "l"(p));
    return a;
}

__device__ __forceinline__ void mma_f16(float* d, const uint32_t* a, const uint32_t* b) {
    asm volatile(
        "mma.sync.aligned.m16n8k16.row.col.f32.f16.f16.f32 "
        "{%0,%1,%2,%3}, {%4,%5,%6,%7}, {%8,%9}, {%0,%1,%2,%3};"
        : "+f"(d[0]), "+f"(d[1]), "+f"(d[2]), "+f"(d[3])
        : "r"(a[0]), "r"(a[1]), "r"(a[2]), "r"(a[3]), "r"(b[0]), "r"(b[1]));
}

#define LDSM_X4(r, addr) \
    asm volatile("ldmatrix.sync.aligned.m8n8.x4.shared.b16 {%0,%1,%2,%3}, [%4];" \
        : "=r"((r)[0]), "=r"((r)[1]), "=r"((r)[2]), "=r"((r)[3]) : "r"(addr))

#define CP_ASYNC16(dst, src) \
    asm volatile("cp.async.cg.shared.global [%0], [%1], 16;" :: "r"(dst), "l"(src))
#define CP_COMMIT()  asm volatile("cp.async.commit_group;" ::: "memory")
#define CP_WAIT1()   asm volatile("cp.async.wait_group 1;" ::: "memory")
#define CP_WAIT0()   asm volatile("cp.async.wait_group 0;" ::: "memory")

// ===========================================================================
// Conversion kernels — 2 launches total
// ===========================================================================
__global__ void convT_all(const float* __restrict__ Wq, const float* __restrict__ Wk,
                          const float* __restrict__ Wv, const float* __restrict__ Wo,
                          const float* __restrict__ Wqc, const float* __restrict__ Wkc,
                          const float* __restrict__ Wvc, const float* __restrict__ Woc,
                          const float* __restrict__ W1, const float* __restrict__ W2,
                          h16* __restrict__ dst)
{
    __shared__ float ts[32][33];
    const int z = blockIdx.z;
    const int t = blockIdx.x;

    const float* src;
    h16* out;
    int K, N, k0, n0;

    if (z < 48) {
        if (t >= 1024) return;
        const int layer = z >> 3;
        const int j     = z & 7;
        const float* srcs[8] = { Wq, Wk, Wv, Wo, Wqc, Wkc, Wvc, Woc };
        src = srcs[j] + (size_t)layer * Dc * Dc;
        out = dst + (size_t)layer * WOFF_LAYER + (size_t)j * 1048576;
        K = Dc; N = Dc;
        k0 = (t >> 5) * 32;
        n0 = (t & 31) * 32;
    } else if (z < 54) {
        const int layer = z - 48;
        src = W1 + (size_t)layer * Dc * DFc;
        out = dst + (size_t)layer * WOFF_LAYER + WOFF_W1;
        K = Dc; N = DFc;
        n0 = (t & 127) * 32;
        k0 = (t >> 7) * 32;
    } else {
        const int layer = z - 54;
        src = W2 + (size_t)layer * DFc * Dc;
        out = dst + (size_t)layer * WOFF_LAYER + WOFF_W2;
        K = DFc; N = Dc;
        n0 = (t & 31) * 32;
        k0 = (t >> 5) * 32;
    }

    const int tx = threadIdx.x, ty = threadIdx.y;
#pragma unroll
    for (int j = 0; j < 4; j++)
        ts[ty + j * 8][tx] = src[(size_t)(k0 + ty + j * 8) * N + n0 + tx];
    __syncthreads();
#pragma unroll
    for (int j = 0; j < 4; j++) {
        int n = ty + j * 8;
        out[(size_t)(n0 + n) * K + k0 + tx] = __float2half(ts[tx][n]);
    }
}

__global__ void conv_all(const float4* __restrict__ outemb, const float4* __restrict__ enc,
                         __half2* __restrict__ w_out, __half2* __restrict__ e_out)
{
    const int z = blockIdx.z;
    if (z == 1 && blockIdx.x >= (Bc * Mc)) return;
    const float4* src = (z == 0) ? outemb : enc;
    __half2* out = (z == 0) ? w_out : e_out;

    size_t i = (size_t)blockIdx.x * blockDim.x + threadIdx.x;
    float4 v = src[i];
    out[i * 2]     = __floats2half2_rn(v.x, v.y);
    out[i * 2 + 1] = __floats2half2_rn(v.z, v.w);
}

// ===========================================================================
// Tensor-core GEMM v5: fp16 single-pass, 3-stage cp.async pipeline,
// ldmatrix direct-operand fragments, 2 CTAs/SM.
//   C[M,N] = A[M,K](fp16) @ B[N,K](fp16)^T, fp32 accumulation.
// ===========================================================================
#define PROWB  144
#define TILEB  (64 * PROWB)                // 9216 B: 128 logical rows x 64B
#define STAGEB (2 * TILEB)                 // 18432 B (A tile + B tile)
#define NSTAGE 3
#define GEMM_SMEM (NSTAGE * STAGEB)        // 55296 B (epilogue needs 67584 -> use max)
#define EPI_SMEM (128 * 132 * 4)           // 67584 B
#define GEMM_SMEM_TOTAL (EPI_SMEM > GEMM_SMEM ? EPI_SMEM : GEMM_SMEM)
#define ROWOFF(r) (((r) & 63) * PROWB + ((r) >> 6) * 64)

template <bool BIAS, bool RELU, bool OUTHALF>
__global__ void __launch_bounds__(256, 2)
tc_gemm(const h16* __restrict__ A_g, const h16* __restrict__ B_g,
        const float* __restrict__ bias, float* __restrict__ C,
        h16* __restrict__ Ch, int M, int N, int K)
{
    extern __shared__ char smem[];
    const int tid  = threadIdx.x;
    const int wid  = tid >> 5;
    const int lane = tid & 31;
    const int g    = lane >> 2;
    const int t    = lane & 3;
    const int wm   = wid & 1;
    const int wn   = wid >> 1;
    const int m0   = blockIdx.y * 128;
    const int n0   = blockIdx.x * 128;

    const uint32_t smem0 = smem_u32(smem);

    // ---- ldmatrix per-lane address offsets (direct operand-order) ----
    const int arow_l = (lane & 7) + ((lane >> 3) & 1) * 8;   // 0..15
    const uint32_t aoffL =
        (uint32_t)(arow_l * PROWB + wm * 64 + (lane >> 4) * 16);
    const int brow_l = ((lane >> 4) & 1) * 8 + (lane & 7);   // 0..15
    const uint32_t boffL =
        (uint32_t)(((wn & 1) * 32 + brow_l) * PROWB + (wn >> 1) * 64 +
                   ((lane >> 3) & 1) * 16);

    float acc[4][4][4];
#pragma unroll
    for (int i = 0; i < 4; i++)
#pragma unroll
        for (int j = 0; j < 4; j++)
#pragma unroll
            for (int c = 0; c < 4; c++) acc[i][j][c] = 0.f;

    const int S = K >> 5;

    // 2 tensors x 512 chunks(16B) = 1024 -> 4 per thread
    auto cp_stage = [&](int s, int b) {
        const int k0 = s << 5;
        char* base = smem + b * STAGEB;
#pragma unroll
        for (int i = 0; i < 4; i++) {
            const int sel  = i >> 1;                    // 0:A, 1:B
            const int idx2 = tid + (i & 1) * 256;       // 0..511
            const int r    = idx2 >> 2;                 // 0..127
            const int c    = idx2 & 3;                  // 16B chunk (row = 64B)
            const h16* src = (sel ? B_g : A_g) +
                             (size_t)((sel ? n0 : m0) + r) * K + k0 + c * 8;
            uint32_t dst = smem_u32(base + sel * TILEB + ROWOFF(r) + c * 16);
            CP_ASYNC16(dst, src);
        }
    };

    auto compute = [&](int b) {
        const uint32_t base = smem0 + b * STAGEB;
        const uint32_t Aa = base + aoffL;
        const uint32_t Bb = base + TILEB + boffL;
#pragma unroll
        for (int ks = 0; ks < 2; ks++) {
            const uint32_t kb = ks * 32;               // 16 fp16 = 32 bytes
            uint32_t af[4][4], bf[2][4];
#pragma unroll
            for (int mt = 0; mt < 4; mt++)
                LDSM_X4(af[mt], Aa + mt * (16 * PROWB) + kb);
#pragma unroll
            for (int j = 0; j < 2; j++)
                LDSM_X4(bf[j], Bb + j * (16 * PROWB) + kb);
#pragma unroll
            for (int mt = 0; mt < 4; mt++)
#pragma unroll
                for (int nt = 0; nt < 4; nt++)
                    mma_f16(acc[mt][nt], af[mt], &bf[nt >> 1][(nt & 1) * 2]);
        }
    };

    // ---- 3-stage pipeline, one barrier per stage ----
    cp_stage(0, 0);
    CP_COMMIT();
    if (S > 1) { cp_stage(1, 1); CP_COMMIT(); }

    for (int s = 0; s < S; s++) {
        if (s + 1 < S) CP_WAIT1();
        else           CP_WAIT0();
        __syncthreads();
        if (s + 2 < S) { cp_stage(s + 2, (s + 2) % NSTAGE); CP_COMMIT(); }
        compute(s % NSTAGE);
    }
    __syncthreads();

    // ---- epilogue ----
    float* stage = reinterpret_cast<float*>(smem);
#pragma unroll
    for (int mt = 0; mt < 4; mt++) {
#pragma unroll
        for (int nt = 0; nt < 4; nt++) {
            int row = wm * 64 + mt * 16 + g;
            int col = wn * 32 + nt * 8 + t * 2;
            *reinterpret_cast<float2*>(&stage[row * 132 + col]) =
                make_float2(acc[mt][nt][0], acc[mt][nt][1]);
            *reinterpret_cast<float2*>(&stage[(row + 8) * 132 + col]) =
                make_float2(acc[mt][nt][2], acc[mt][nt][3]);
        }
    }
    __syncthreads();

#pragma unroll
    for (int i = 0; i < 16; i++) {
        int f   = i * 256 + tid;
        int row = f >> 5;
        int c4  = f & 31;
        float4 v = *reinterpret_cast<float4*>(&stage[row * 132 + c4 * 4]);
        if (BIAS) {
            float4 bv = *reinterpret_cast<const float4*>(bias + n0 + c4 * 4);
            v.x += bv.x; v.y += bv.y; v.z += bv.z; v.w += bv.w;
        }
        if (RELU) {
            v.x = fmaxf(v.x, 0.f); v.y = fmaxf(v.y, 0.f);
            v.z = fmaxf(v.z, 0.f); v.w = fmaxf(v.w, 0.f);
        }
        size_t oidx = (size_t)(m0 + row) * N + n0 + c4 * 4;
        if (OUTHALF) {
            __half2 h0 = __floats2half2_rn(v.x, v.y);
            __half2 h1 = __floats2half2_rn(v.z, v.w);
            *reinterpret_cast<__half2*>(Ch + oidx)     = h0;
            *reinterpret_cast<__half2*>(Ch + oidx + 2) = h1;
        } else {
            *reinterpret_cast<float4*>(C + oidx) = v;
        }
    }
}

// ---------------------------------------------------------------------------
// Fused attention (R8-proven layout; output written as fp16)
// ---------------------------------------------------------------------------
template <bool CAUSAL>
__global__ void __launch_bounds__(128)
attn_kernel(const float* __restrict__ Q, const float* __restrict__ K,
            const float* __restrict__ V, h16* __restrict__ Oh, int Lk)
{
    __shared__ float Qs[32 * 64];
    __shared__ float Kst[64 * 33];
    __shared__ float Vs[32 * 68];
    __shared__ float Ps[32 * 32];

    const int b    = blockIdx.z;
    const int h    = blockIdx.y;
    const int q0   = blockIdx.x * 32;
    const int tid  = threadIdx.x;
    const int lane = tid & 31;
    const int w    = tid >> 5;
    const int r0   = w * 8;

#pragma unroll
    for (int s = tid; s < 512; s += 128) {
        int r  = s >> 4;
        int c4 = s & 15;
        float4 v = *reinterpret_cast<const float4*>(
            Q + (size_t)(b * Sc + q0 + r) * Dc + h * 64 + c4 * 4);
        *reinterpret_cast<float4*>(&Qs[r * 64 + c4 * 4]) = v;
    }

    float m_run[8], l_run[8], o0[8], o1[8];
#pragma unroll
    for (int r = 0; r < 8; r++) { m_run[r] = -1e30f; l_run[r] = 0.f; o0[r] = 0.f; o1[r] = 0.f; }

    const int nkt = CAUSAL ? (blockIdx.x + 1) : (Lk >> 5);

    for (int kt = 0; kt < nkt; kt++) {
        const int k0 = kt * 32;
        __syncthreads();
#pragma unroll
        for (int s = tid; s < 512; s += 128) {
            int r  = s >> 4;
            int c4 = s & 15;
            size_t base = (size_t)(b * Lk + k0 + r) * Dc + h * 64 + c4 * 4;
            float4 kv = *reinterpret_cast<const float4*>(K + base);
            Kst[(c4 * 4 + 0) * 33 + r] = kv.x;
            Kst[(c4 * 4 + 1) * 33 + r] = kv.y;
            Kst[(c4 * 4 + 2) * 33 + r] = kv.z;
            Kst[(c4 * 4 + 3) * 33 + r] = kv.w;
            float4 vv = *reinterpret_cast<const float4*>(V + base);
            *reinterpret_cast<float4*>(&Vs[r * 68 + c4 * 4]) = vv;
        }
        __syncthreads();

        float sc[8];
#pragma unroll
        for (int r = 0; r < 8; r++) sc[r] = 0.f;
#pragma unroll
        for (int d4 = 0; d4 < 16; d4++) {
            float k0v = Kst[(d4 * 4 + 0) * 33 + lane];
            float k1v = Kst[(d4 * 4 + 1) * 33 + lane];
            float k2v = Kst[(d4 * 4 + 2) * 33 + lane];
            float k3v = Kst[(d4 * 4 + 3) * 33 + lane];
#pragma unroll
            for (int r = 0; r < 8; r++) {
                float4 qv = *reinterpret_cast<const float4*>(&Qs[(r0 + r) * 64 + d4 * 4]);
                sc[r] += qv.x * k0v + qv.y * k1v + qv.z * k2v + qv.w * k3v;
            }
        }
#pragma unroll
        for (int r = 0; r < 8; r++) {
            sc[r] *= 0.125f;
            if (CAUSAL) {
                int qg = q0 + r0 + r;
                int kg = k0 + lane;
                if (kg > qg) sc[r] = -1e9f;
            }
        }
#pragma unroll
        for (int r = 0; r < 8; r++) {
            float mx = sc[r];
#pragma unroll
            for (int off = 16; off > 0; off >>= 1)
                mx = fmaxf(mx, __shfl_xor_sync(0xffffffffu, mx, off));
            float m_new = fmaxf(m_run[r], mx);
            float p = __expf(sc[r] - m_new);
            float ps = p;
#pragma unroll
            for (int off = 16; off > 0; off >>= 1)
                ps += __shfl_xor_sync(0xffffffffu, ps, off);
            float alpha = __expf(m_run[r] - m_new);
            l_run[r] = l_run[r] * alpha + ps;
            m_run[r] = m_new;
            o0[r] *= alpha;
            o1[r] *= alpha;
            Ps[(r0 + r) * 32 + lane] = p;
        }
        __syncwarp();
#pragma unroll
        for (int k4 = 0; k4 < 8; k4++) {
            float v00 = Vs[(k4 * 4 + 0) * 68 + lane];
            float v01 = Vs[(k4 * 4 + 1) * 68 + lane];
            float v02 = Vs[(k4 * 4 + 2) * 68 + lane];
            float v03 = Vs[(k4 * 4 + 3) * 68 + lane];
            float v10 = Vs[(k4 * 4 + 0) * 68 + 32 + lane];
            float v11 = Vs[(k4 * 4 + 1) * 68 + 32 + lane];
            float v12 = Vs[(k4 * 4 + 2) * 68 + 32 + lane];
            float v13 = Vs[(k4 * 4 + 3) * 68 + 32 + lane];
#pragma unroll
            for (int r = 0; r < 8; r++) {
                float4 pv = *reinterpret_cast<const float4*>(&Ps[(r0 + r) * 32 + k4 * 4]);
                o0[r] += pv.x * v00 + pv.y * v01 + pv.z * v02 + pv.w * v03;
                o1[r] += pv.x * v10 + pv.y * v11 + pv.z * v12 + pv.w * v13;
            }
        }
    }

#pragma unroll
    for (int r = 0; r < 8; r++) {
        float invl = 1.f / l_run[r];
        size_t base = (size_t)(b * Sc + q0 + r0 + r) * Dc + h * 64;
        Oh[base + lane]      = __float2half(o0[r] * invl);
        Oh[base + 32 + lane] = __float2half(o1[r] * invl);
    }
}

// ---------------------------------------------------------------------------
// Residual + LayerNorm; writes fp32 + fp16 mirror
// ---------------------------------------------------------------------------
__global__ void __launch_bounds__(256)
ln_kernel(const float* __restrict__ x, const float* __restrict__ add,
          const float* __restrict__ s, const float* __restrict__ b,
          float* __restrict__ out, h16* __restrict__ oh)
{
    const int row = blockIdx.x;
    const int tid = threadIdx.x;
    const size_t base = (size_t)row * Dc;

    float v[4];
    float sum = 0.f, sq = 0.f;
#pragma unroll
    for (int i = 0; i < 4; i++) {
        int c = tid + i * 256;
        float val = x[base + c];
        if (add) val += add[base + c];
        v[i] = val;
        sum += val;
        sq  += val * val;
    }
#pragma unroll
    for (int off = 16; off > 0; off >>= 1) {
        sum += __shfl_xor_sync(0xffffffffu, sum, off);
        sq  += __shfl_xor_sync(0xffffffffu, sq, off);
    }
    __shared__ float s1[8], s2[8];
    __shared__ float mu_s, inv_s;
    int lane = tid & 31, wid = tid >> 5;
    if (lane == 0) { s1[wid] = sum; s2[wid] = sq; }
    __syncthreads();
    if (tid == 0) {
        float ts = 0.f, tq = 0.f;
#pragma unroll
        for (int i = 0; i < 8; i++) { ts += s1[i]; tq += s2[i]; }
        float mu  = ts * (1.f / Dc);
        float var = tq * (1.f / Dc) - mu * mu;
        mu_s  = mu;
        inv_s = rsqrtf(var + 1e-5f);
    }
    __syncthreads();
    float mu = mu_s, inv = inv_s;
#pragma unroll
    for (int i = 0; i < 4; i++) {
        int c = tid + i * 256;
        float r = (v[i] - mu) * inv * s[c] + b[c];
        out[base + c] = r;
        oh[base + c]  = __float2half(r);
    }
}

// ---------------------------------------------------------------------------
// Embedding gather + positional add; writes fp32 + fp16
// ---------------------------------------------------------------------------
__global__ void __launch_bounds__(256)
embed_kernel(const int* __restrict__ seq, const float* __restrict__ emb,
             const float* __restrict__ pos, float* __restrict__ x,
             h16* __restrict__ xh)
{
    const int row  = blockIdx.x;
    const int sidx = row & (Sc - 1);
    const int tok  = seq[row];
    const int tid  = threadIdx.x;
#pragma unroll
    for (int i = 0; i < 4; i++) {
        int c = tid + i * 256;
        float r = emb[(size_t)tok * Dc + c] + pos[(size_t)sidx * Dc + c];
        size_t o = (size_t)row * Dc + c;
        x[o]  = r;
        xh[o] = __float2half(r);
    }
}

// ---------------------------------------------------------------------------
// Host orchestration
// ---------------------------------------------------------------------------
template <bool BIAS, bool RELU, bool OUTHALF>
static void launch_gemm(const h16* a, const h16* b, const float* bias,
                        float* C, h16* ch, int M, int N, int K)
{
    cudaFuncSetAttribute(tc_gemm<BIAS, RELU, OUTHALF>,
                         cudaFuncAttributeMaxDynamicSharedMemorySize, GEMM_SMEM_TOTAL);
    dim3 grid(N / 128, M / 128);
    tc_gemm<BIAS, RELU, OUTHALF><<<grid, 256, GEMM_SMEM_TOTAL>>>(a, b, bias, C, ch, M, N, K);
}

extern "C" void kernel_launch(void* const* d_in, const int* in_sizes, int n_in,
                              void* d_out, int out_size)
{
    (void)in_sizes; (void)n_in; (void)out_size;

    const float* encoded      = (const float*)d_in[0];
    const int*   seq          = (const int*)  d_in[1];
    const float* input_embed  = (const float*)d_in[2];
    const float* output_embed = (const float*)d_in[3];
    const float* output_bias  = (const float*)d_in[4];
    const float* pos_embed    = (const float*)d_in[5];
    const float* Wq  = (const float*)d_in[6];
    const float* Wk  = (const float*)d_in[7];
    const float* Wv  = (const float*)d_in[8];
    const float* Wo  = (const float*)d_in[9];
    const float* Wqc = (const float*)d_in[10];
    const float* Wkc = (const float*)d_in[11];
    const float* Wvc = (const float*)d_in[12];
    const float* Woc = (const float*)d_in[13];
    const float* W1  = (const float*)d_in[14];
    const float* b1  = (const float*)d_in[15];
    const float* W2  = (const float*)d_in[16];
    const float* b2  = (const float*)d_in[17];
    const float* ln1s = (const float*)d_in[18];
    const float* ln1b = (const float*)d_in[19];
    const float* ln2s = (const float*)d_in[20];
    const float* ln2b = (const float*)d_in[21];
    const float* ln3s = (const float*)d_in[22];
    const float* ln3b = (const float*)d_in[23];
    const float* lnfs = (const float*)d_in[24];
    const float* lnfb = (const float*)d_in[25];

    float *x, *q, *k, *v, *o;
    cudaGetSymbolAddress((void**)&x, g_x);
    cudaGetSymbolAddress((void**)&q, g_q);
    cudaGetSymbolAddress((void**)&k, g_k);
    cudaGetSymbolAddress((void**)&v, g_v);
    cudaGetSymbolAddress((void**)&o, g_o);
    h16 *w, *xh, *ah, *fh, *eh;
    cudaGetSymbolAddress((void**)&w,  g_w);
    cudaGetSymbolAddress((void**)&xh, g_xh);
    cudaGetSymbolAddress((void**)&ah, g_ah);
    cudaGetSymbolAddress((void**)&fh, g_fh);
    cudaGetSymbolAddress((void**)&eh, g_eh);

    // ---- conversions: 2 launches ----
    convT_all<<<dim3(4096, 1, 60), dim3(32, 8)>>>(Wq, Wk, Wv, Wo, Wqc, Wkc, Wvc, Woc,
                                                  W1, W2, w);
    conv_all<<<dim3(Vc, 1, 2), 256>>>((const float4*)output_embed, (const float4*)encoded,
                                      (__half2*)(w + EOFF), (__half2*)eh);

    const int NR  = Bc * Sc;   // 4096
    const int NRE = Bc * Mc;   // 8192

    embed_kernel<<<NR, 256>>>(seq, input_embed, pos_embed, x, xh);

    const dim3 agrid(Sc / 32, Hc, Bc);   // (16, 16, 8)

    for (int i = 0; i < Lc; i++) {
        const size_t lb = (size_t)i * WOFF_LAYER;
        const h16* wl = w + lb;

        // ---- self attention ----
        launch_gemm<false, false, false>(xh, wl + 0 * 1048576, nullptr, q, nullptr, NR, Dc, Dc);
        launch_gemm<false, false, false>(xh, wl + 1 * 1048576, nullptr, k, nullptr, NR, Dc, Dc);
        launch_gemm<false, false, false>(xh, wl + 2 * 1048576, nullptr, v, nullptr, NR, Dc, Dc);
        attn_kernel<true><<<agrid, 128>>>(q, k, v, ah, Sc);
        launch_gemm<false, false, false>(ah, wl + 3 * 1048576, nullptr, o, nullptr, NR, Dc, Dc);
        ln_kernel<<<NR, 256>>>(x, o, ln1s + (size_t)i * Dc, ln1b + (size_t)i * Dc, x, xh);

        // ---- cross attention ----
        launch_gemm<false, false, false>(xh, wl + 4 * 1048576, nullptr, q, nullptr, NR,  Dc, Dc);
        launch_gemm<false, false, false>(eh, wl + 5 * 1048576, nullptr, k, nullptr, NRE, Dc, Dc);
        launch_gemm<false, false, false>(eh, wl + 6 * 1048576, nullptr, v, nullptr, NRE, Dc, Dc);
        attn_kernel<false><<<agrid, 128>>>(q, k, v, ah, Mc);
        launch_gemm<false, false, false>(ah, wl + 7 * 1048576, nullptr, o, nullptr, NR, Dc, Dc);
        ln_kernel<<<NR, 256>>>(x, o, ln2s + (size_t)i * Dc, ln2b + (size_t)i * Dc, x, xh);

        // ---- FFN ----
        launch_gemm<true, true, true>(xh, wl + WOFF_W1, b1 + (size_t)i * DFc,
                                      nullptr, fh, NR, DFc, Dc);
        launch_gemm<true, false, false>(fh, wl + WOFF_W2, b2 + (size_t)i * Dc,
                                        o, nullptr, NR, Dc, DFc);
        ln_kernel<<<NR, 256>>>(x, o, ln3s + (size_t)i * Dc, ln3b + (size_t)i * Dc, x, xh);
    }

    // final norm + logits
    ln_kernel<<<NR, 256>>>(x, nullptr, lnfs, lnfb, x, xh);
    launch_gemm<true, false, false>(xh, w + EOFF, output_bias, (float*)d_out, nullptr,
                                    NR, Vc, Dc);
}

// round 13
// speedup vs baseline: 3.1797x; 1.8608x over previous
#include <cuda_runtime.h>
#include <cuda_fp16.h>
#include <math.h>
#include <stdint.h>

// Problem constants
#define Bc   8
#define Sc   512
#define Dc   1024
#define Hc   16
#define DHc  64
#define Mc   1024
#define DFc  4096
#define Vc   32000
#define Lc   6

typedef __half h16;

// ---------------------------------------------------------------------------
// Scratch (device globals)
// ---------------------------------------------------------------------------
__device__ float g_x[Bc * Sc * Dc];        // residual stream fp32
__device__ float g_o[Bc * Sc * Dc];        // proj / FFN2 output fp32
// fp16 activation buffers
__device__ h16 g_xh[Bc * Sc * Dc];
__device__ h16 g_qh[Bc * Sc * Dc];
__device__ h16 g_kh[Bc * Mc * Dc];
__device__ h16 g_vh[Bc * Mc * Dc];
__device__ h16 g_ah[Bc * Sc * Dc];
__device__ h16 g_fh[Bc * Sc * DFc];
__device__ h16 g_eh[Bc * Mc * Dc];

// Pre-converted weights: [N,K] fp16.
#define WOFF_LAYER 16777216ull
#define WOFF_W1    8388608ull
#define WOFF_W2    12582912ull
#define EOFF       100663296ull
#define WTOTAL     133431296ull
__device__ h16 g_w[WTOTAL];

// ===========================================================================
// helpers
// ===========================================================================
__device__ __forceinline__ uint32_t smem_u32(const void* p) {
    uint32_t a;
    asm("{ .reg .u64 t; cvta.to.shared.u64 t, %1; cvt.u32.u64 %0, t; }"
        : "=r"(a) : "l"(p));
    return a;
}

__device__ __forceinline__ void mma_f16(float* d, const uint32_t* a, const uint32_t* b) {
    asm volatile(
        "mma.sync.aligned.m16n8k16.row.col.f32.f16.f16.f32 "
        "{%0,%1,%2,%3}, {%4,%5,%6,%7}, {%8,%9}, {%0,%1,%2,%3};"
        : "+f"(d[0]), "+f"(d[1]), "+f"(d[2]), "+f"(d[3])
        : "r"(a[0]), "r"(a[1]), "r"(a[2]), "r"(a[3]), "r"(b[0]), "r"(b[1]));
}

#define LDSM_X4(r, addr) \
    asm volatile("ldmatrix.sync.aligned.m8n8.x4.shared.b16 {%0,%1,%2,%3}, [%4];" \
        : "=r"((r)[0]), "=r"((r)[1]), "=r"((r)[2]), "=r"((r)[3]) : "r"(addr))

#define LDSM_X4T(r, addr) \
    asm volatile("ldmatrix.sync.aligned.m8n8.x4.trans.shared.b16 {%0,%1,%2,%3}, [%4];" \
        : "=r"((r)[0]), "=r"((r)[1]), "=r"((r)[2]), "=r"((r)[3]) : "r"(addr))

#define CP_ASYNC16(dst, src) \
    asm volatile("cp.async.cg.shared.global [%0], [%1], 16;" :: "r"(dst), "l"(src))
#define CP_COMMIT()  asm volatile("cp.async.commit_group;" ::: "memory")
#define CP_WAIT2()   asm volatile("cp.async.wait_group 2;" ::: "memory")
#define CP_WAIT1()   asm volatile("cp.async.wait_group 1;" ::: "memory")
#define CP_WAIT0()   asm volatile("cp.async.wait_group 0;" ::: "memory")

// ===========================================================================
// Conversion kernels — 2 launches total
// ===========================================================================
__global__ void convT_all(const float* __restrict__ Wq, const float* __restrict__ Wk,
                          const float* __restrict__ Wv, const float* __restrict__ Wo,
                          const float* __restrict__ Wqc, const float* __restrict__ Wkc,
                          const float* __restrict__ Wvc, const float* __restrict__ Woc,
                          const float* __restrict__ W1, const float* __restrict__ W2,
                          h16* __restrict__ dst)
{
    __shared__ float ts[32][33];
    const int z = blockIdx.z;
    const int t = blockIdx.x;

    const float* src;
    h16* out;
    int K, N, k0, n0;

    if (z < 48) {
        if (t >= 1024) return;
        const int layer = z >> 3;
        const int j     = z & 7;
        const float* srcs[8] = { Wq, Wk, Wv, Wo, Wqc, Wkc, Wvc, Woc };
        src = srcs[j] + (size_t)layer * Dc * Dc;
        out = dst + (size_t)layer * WOFF_LAYER + (size_t)j * 1048576;
        K = Dc; N = Dc;
        k0 = (t >> 5) * 32;
        n0 = (t & 31) * 32;
    } else if (z < 54) {
        const int layer = z - 48;
        src = W1 + (size_t)layer * Dc * DFc;
        out = dst + (size_t)layer * WOFF_LAYER + WOFF_W1;
        K = Dc; N = DFc;
        n0 = (t & 127) * 32;
        k0 = (t >> 7) * 32;
    } else {
        const int layer = z - 54;
        src = W2 + (size_t)layer * DFc * Dc;
        out = dst + (size_t)layer * WOFF_LAYER + WOFF_W2;
        K = DFc; N = Dc;
        n0 = (t & 31) * 32;
        k0 = (t >> 5) * 32;
    }

    const int tx = threadIdx.x, ty = threadIdx.y;
#pragma unroll
    for (int j = 0; j < 4; j++)
        ts[ty + j * 8][tx] = src[(size_t)(k0 + ty + j * 8) * N + n0 + tx];
    __syncthreads();
#pragma unroll
    for (int j = 0; j < 4; j++) {
        int n = ty + j * 8;
        out[(size_t)(n0 + n) * K + k0 + tx] = __float2half(ts[tx][n]);
    }
}

__global__ void conv_all(const float4* __restrict__ outemb, const float4* __restrict__ enc,
                         __half2* __restrict__ w_out, __half2* __restrict__ e_out)
{
    const int z = blockIdx.z;
    if (z == 1 && blockIdx.x >= (Bc * Mc)) return;
    const float4* src = (z == 0) ? outemb : enc;
    __half2* out = (z == 0) ? w_out : e_out;

    size_t i = (size_t)blockIdx.x * blockDim.x + threadIdx.x;
    float4 v = src[i];
    out[i * 2]     = __floats2half2_rn(v.x, v.y);
    out[i * 2 + 1] = __floats2half2_rn(v.z, v.w);
}

// ===========================================================================
// Tensor-core GEMM (R12-proven fp16 single-pass)
// ===========================================================================
#define PROWB  144
#define TILEB  (64 * PROWB)
#define STAGEB (2 * TILEB)
#define NSTAGE 3
#define GEMM_SMEM (NSTAGE * STAGEB)
#define EPI_SMEM (128 * 132 * 4)
#define GEMM_SMEM_TOTAL (EPI_SMEM > GEMM_SMEM ? EPI_SMEM : GEMM_SMEM)
#define ROWOFF(r) (((r) & 63) * PROWB + ((r) >> 6) * 64)

template <bool BIAS, bool RELU, bool OUTHALF>
__global__ void __launch_bounds__(256, 2)
tc_gemm(const h16* __restrict__ A_g, const h16* __restrict__ B_g,
        const float* __restrict__ bias, float* __restrict__ C,
        h16* __restrict__ Ch, int M, int N, int K)
{
    extern __shared__ char smem[];
    const int tid  = threadIdx.x;
    const int wid  = tid >> 5;
    const int lane = tid & 31;
    const int g    = lane >> 2;
    const int t    = lane & 3;
    const int wm   = wid & 1;
    const int wn   = wid >> 1;
    const int m0   = blockIdx.y * 128;
    const int n0   = blockIdx.x * 128;

    const uint32_t smem0 = smem_u32(smem);

    const int arow_l = (lane & 7) + ((lane >> 3) & 1) * 8;
    const uint32_t aoffL =
        (uint32_t)(arow_l * PROWB + wm * 64 + (lane >> 4) * 16);
    const int brow_l = ((lane >> 4) & 1) * 8 + (lane & 7);
    const uint32_t boffL =
        (uint32_t)(((wn & 1) * 32 + brow_l) * PROWB + (wn >> 1) * 64 +
                   ((lane >> 3) & 1) * 16);

    float acc[4][4][4];
#pragma unroll
    for (int i = 0; i < 4; i++)
#pragma unroll
        for (int j = 0; j < 4; j++)
#pragma unroll
            for (int c = 0; c < 4; c++) acc[i][j][c] = 0.f;

    const int S = K >> 5;

    auto cp_stage = [&](int s, int b) {
        const int k0 = s << 5;
        char* base = smem + b * STAGEB;
#pragma unroll
        for (int i = 0; i < 4; i++) {
            const int sel  = i >> 1;
            const int idx2 = tid + (i & 1) * 256;
            const int r    = idx2 >> 2;
            const int c    = idx2 & 3;
            const h16* src = (sel ? B_g : A_g) +
                             (size_t)((sel ? n0 : m0) + r) * K + k0 + c * 8;
            uint32_t dst = smem_u32(base + sel * TILEB + ROWOFF(r) + c * 16);
            CP_ASYNC16(dst, src);
        }
    };

    auto compute = [&](int b) {
        const uint32_t base = smem0 + b * STAGEB;
        const uint32_t Aa = base + aoffL;
        const uint32_t Bb = base + TILEB + boffL;
#pragma unroll
        for (int ks = 0; ks < 2; ks++) {
            const uint32_t kb = ks * 32;
            uint32_t af[4][4], bf[2][4];
#pragma unroll
            for (int mt = 0; mt < 4; mt++)
                LDSM_X4(af[mt], Aa + mt * (16 * PROWB) + kb);
#pragma unroll
            for (int j = 0; j < 2; j++)
                LDSM_X4(bf[j], Bb + j * (16 * PROWB) + kb);
#pragma unroll
            for (int mt = 0; mt < 4; mt++)
#pragma unroll
                for (int nt = 0; nt < 4; nt++)
                    mma_f16(acc[mt][nt], af[mt], &bf[nt >> 1][(nt & 1) * 2]);
        }
    };

    cp_stage(0, 0);
    CP_COMMIT();
    if (S > 1) { cp_stage(1, 1); CP_COMMIT(); }

    for (int s = 0; s < S; s++) {
        if (s + 1 < S) CP_WAIT1();
        else           CP_WAIT0();
        __syncthreads();
        if (s + 2 < S) { cp_stage(s + 2, (s + 2) % NSTAGE); CP_COMMIT(); }
        compute(s % NSTAGE);
    }
    __syncthreads();

    float* stage = reinterpret_cast<float*>(smem);
#pragma unroll
    for (int mt = 0; mt < 4; mt++) {
#pragma unroll
        for (int nt = 0; nt < 4; nt++) {
            int row = wm * 64 + mt * 16 + g;
            int col = wn * 32 + nt * 8 + t * 2;
            *reinterpret_cast<float2*>(&stage[row * 132 + col]) =
                make_float2(acc[mt][nt][0], acc[mt][nt][1]);
            *reinterpret_cast<float2*>(&stage[(row + 8) * 132 + col]) =
                make_float2(acc[mt][nt][2], acc[mt][nt][3]);
        }
    }
    __syncthreads();

#pragma unroll
    for (int i = 0; i < 16; i++) {
        int f   = i * 256 + tid;
        int row = f >> 5;
        int c4  = f & 31;
        float4 v = *reinterpret_cast<float4*>(&stage[row * 132 + c4 * 4]);
        if (BIAS) {
            float4 bv = *reinterpret_cast<const float4*>(bias + n0 + c4 * 4);
            v.x += bv.x; v.y += bv.y; v.z += bv.z; v.w += bv.w;
        }
        if (RELU) {
            v.x = fmaxf(v.x, 0.f); v.y = fmaxf(v.y, 0.f);
            v.z = fmaxf(v.z, 0.f); v.w = fmaxf(v.w, 0.f);
        }
        size_t oidx = (size_t)(m0 + row) * N + n0 + c4 * 4;
        if (OUTHALF) {
            *reinterpret_cast<__half2*>(Ch + oidx)     = __floats2half2_rn(v.x, v.y);
            *reinterpret_cast<__half2*>(Ch + oidx + 2) = __floats2half2_rn(v.z, v.w);
        } else {
            *reinterpret_cast<float4*>(C + oidx) = v;
        }
    }
}

// ===========================================================================
// Flash attention via mma.sync (fp16 inputs, fp32 softmax/accum).
// CTA: 64 q rows of one (b,h); 4 warps x 16 rows. K-tiles of 32 keys,
// 3-stage cp.async pipeline. Output fp16 (feeds o-proj GEMM).
// ===========================================================================
#define AT_PITCH 72      // halves per smem row (64 used), 144 B

template <bool CAUSAL>
__global__ void __launch_bounds__(128)
attn_kernel(const h16* __restrict__ Qh, const h16* __restrict__ Kh,
            const h16* __restrict__ Vh, h16* __restrict__ Oh, int Lk)
{
    __shared__ h16 sQ[64 * AT_PITCH];
    __shared__ h16 sK[3][32 * AT_PITCH];
    __shared__ h16 sV[3][32 * AT_PITCH];

    const int b    = blockIdx.z;
    const int h    = blockIdx.y;
    const int q0   = blockIdx.x * 64;
    const int tid  = threadIdx.x;
    const int lane = tid & 31;
    const int w    = tid >> 5;
    const int wr0  = w * 16;
    const int g    = lane >> 2;
    const int t    = lane & 3;

    const int nkt = CAUSAL ? ((q0 + 64) >> 5) : (Lk >> 5);

    // ---- cp.async loaders ----
    auto cp_q = [&]() {
#pragma unroll
        for (int i = 0; i < 4; i++) {
            int idx = tid + i * 128;           // 0..511
            int r = idx >> 3, c = idx & 7;
            const h16* src = Qh + (size_t)(b * Sc + q0 + r) * Dc + h * 64 + c * 8;
            CP_ASYNC16(smem_u32(&sQ[r * AT_PITCH]) + c * 16, src);
        }
    };
    auto cp_kv = [&](int kt, int stg) {
        const int k0 = kt << 5;
#pragma unroll
        for (int i = 0; i < 4; i++) {
            int idx = tid + i * 128;           // 0..511
            int sel = idx >> 8;                // 0:K 1:V
            int rem = idx & 255;
            int r = rem >> 3, c = rem & 7;
            const h16* src = (sel ? Vh : Kh) +
                             (size_t)(b * Lk + k0 + r) * Dc + h * 64 + c * 8;
            h16* dst = (sel ? sV[stg] : sK[stg]) + r * AT_PITCH;
            CP_ASYNC16(smem_u32(dst) + c * 16, src);
        }
    };

    cp_q();
    CP_COMMIT();
    cp_kv(0, 0);
    CP_COMMIT();
    if (nkt > 1) { cp_kv(1, 1); CP_COMMIT(); }
    if (nkt > 1) CP_WAIT2(); else CP_WAIT1();   // Q complete
    __syncthreads();

    // ---- Q fragments (held in regs whole kernel) ----
    uint32_t aq[4][4];
    {
        const int qrow = (lane & 7) + ((lane >> 3) & 1) * 8;
        const uint32_t qaddr = smem_u32(sQ) +
            (uint32_t)((wr0 + qrow) * (AT_PITCH * 2) + (lane >> 4) * 16);
#pragma unroll
        for (int ks = 0; ks < 4; ks++)
            LDSM_X4(aq[ks], qaddr + ks * 32);
    }

    // ---- per-lane ldmatrix offsets for K (non-trans) and V (trans) ----
    const int kb_row = ((lane >> 4) & 1) * 8 + (lane & 7);
    const uint32_t kboff = (uint32_t)(kb_row * (AT_PITCH * 2) + ((lane >> 3) & 1) * 16);
    const int v_row = ((lane >> 3) & 1) * 8 + (lane & 7);
    const uint32_t vboff = (uint32_t)(v_row * (AT_PITCH * 2) + (lane >> 4) * 16);

    float oacc[8][4];
#pragma unroll
    for (int d = 0; d < 8; d++)
#pragma unroll
        for (int c = 0; c < 4; c++) oacc[d][c] = 0.f;
    float mrow0 = -1e30f, mrow1 = -1e30f, lrow0 = 0.f, lrow1 = 0.f;

    const int row0 = q0 + wr0 + g;
    const int row1 = row0 + 8;

    for (int kt = 0; kt < nkt; kt++) {
        if (kt + 1 < nkt) CP_WAIT1();
        else              CP_WAIT0();
        __syncthreads();
        if (kt + 2 < nkt) { cp_kv(kt + 2, (kt + 2) % 3); CP_COMMIT(); }

        const int stg = kt % 3;
        const int k0  = kt << 5;

        // ---- S = Q @ K^T (fp32 accum) ----
        float s[4][4];
#pragma unroll
        for (int nt = 0; nt < 4; nt++)
#pragma unroll
            for (int c = 0; c < 4; c++) s[nt][c] = 0.f;
        const uint32_t Kb = smem_u32(sK[stg]) + kboff;
#pragma unroll
        for (int ks = 0; ks < 4; ks++) {
            uint32_t bk[2][4];
#pragma unroll
            for (int j = 0; j < 2; j++)
                LDSM_X4(bk[j], Kb + j * (16 * AT_PITCH * 2) + ks * 32);
#pragma unroll
            for (int nt = 0; nt < 4; nt++)
                mma_f16(s[nt], aq[ks], &bk[nt >> 1][(nt & 1) * 2]);
        }

        // scale + causal mask
#pragma unroll
        for (int nt = 0; nt < 4; nt++) {
            const int col0 = k0 + nt * 8 + 2 * t;
#pragma unroll
            for (int c = 0; c < 4; c++) s[nt][c] *= 0.125f;
            if (CAUSAL) {
                if (col0     > row0) s[nt][0] = -1e9f;
                if (col0 + 1 > row0) s[nt][1] = -1e9f;
                if (col0     > row1) s[nt][2] = -1e9f;
                if (col0 + 1 > row1) s[nt][3] = -1e9f;
            }
        }

        // ---- online softmax (fp32, quad shuffles) ----
        float ml0 = -1e30f, ml1 = -1e30f;
#pragma unroll
        for (int nt = 0; nt < 4; nt++) {
            ml0 = fmaxf(ml0, fmaxf(s[nt][0], s[nt][1]));
            ml1 = fmaxf(ml1, fmaxf(s[nt][2], s[nt][3]));
        }
        ml0 = fmaxf(ml0, __shfl_xor_sync(0xffffffffu, ml0, 1));
        ml0 = fmaxf(ml0, __shfl_xor_sync(0xffffffffu, ml0, 2));
        ml1 = fmaxf(ml1, __shfl_xor_sync(0xffffffffu, ml1, 1));
        ml1 = fmaxf(ml1, __shfl_xor_sync(0xffffffffu, ml1, 2));
        const float mn0 = fmaxf(mrow0, ml0);
        const float mn1 = fmaxf(mrow1, ml1);
        const float al0 = __expf(mrow0 - mn0);
        const float al1 = __expf(mrow1 - mn1);
        mrow0 = mn0; mrow1 = mn1;

        uint32_t pa[4][2];
        float ls0 = 0.f, ls1 = 0.f;
#pragma unroll
        for (int nt = 0; nt < 4; nt++) {
            float p0 = __expf(s[nt][0] - mn0);
            float p1 = __expf(s[nt][1] - mn0);
            float p2 = __expf(s[nt][2] - mn1);
            float p3 = __expf(s[nt][3] - mn1);
            ls0 += p0 + p1;
            ls1 += p2 + p3;
            __half2 h01 = __floats2half2_rn(p0, p1);
            __half2 h23 = __floats2half2_rn(p2, p3);
            pa[nt][0] = *reinterpret_cast<uint32_t*>(&h01);
            pa[nt][1] = *reinterpret_cast<uint32_t*>(&h23);
        }
        ls0 += __shfl_xor_sync(0xffffffffu, ls0, 1);
        ls0 += __shfl_xor_sync(0xffffffffu, ls0, 2);
        ls1 += __shfl_xor_sync(0xffffffffu, ls1, 1);
        ls1 += __shfl_xor_sync(0xffffffffu, ls1, 2);
        lrow0 = lrow0 * al0 + ls0;
        lrow1 = lrow1 * al1 + ls1;
#pragma unroll
        for (int d = 0; d < 8; d++) {
            oacc[d][0] *= al0; oacc[d][1] *= al0;
            oacc[d][2] *= al1; oacc[d][3] *= al1;
        }

        // ---- O += P @ V (V fragments via ldmatrix.trans) ----
        const uint32_t Vb = smem_u32(sV[stg]) + vboff;
#pragma unroll
        for (int ks2 = 0; ks2 < 2; ks2++) {
            uint32_t aP[4] = { pa[2 * ks2][0], pa[2 * ks2][1],
                               pa[2 * ks2 + 1][0], pa[2 * ks2 + 1][1] };
#pragma unroll
            for (int dp = 0; dp < 4; dp++) {
                uint32_t bv[4];
                LDSM_X4T(bv, Vb + ks2 * (16 * AT_PITCH * 2) + dp * 32);
                mma_f16(oacc[dp * 2 + 0], aP, &bv[0]);
                mma_f16(oacc[dp * 2 + 1], aP, &bv[2]);
            }
        }
    }

    // ---- normalize + store fp16 ----
    const float inv0 = 1.f / lrow0;
    const float inv1 = 1.f / lrow1;
    h16* o0p = Oh + (size_t)(b * Sc + row0) * Dc + h * 64;
    h16* o1p = Oh + (size_t)(b * Sc + row1) * Dc + h * 64;
#pragma unroll
    for (int d = 0; d < 8; d++) {
        int col = d * 8 + 2 * t;
        *reinterpret_cast<__half2*>(o0p + col) =
            __floats2half2_rn(oacc[d][0] * inv0, oacc[d][1] * inv0);
        *reinterpret_cast<__half2*>(o1p + col) =
            __floats2half2_rn(oacc[d][2] * inv1, oacc[d][3] * inv1);
    }
}

// ---------------------------------------------------------------------------
// Residual + LayerNorm; writes fp32 + fp16 mirror
// ---------------------------------------------------------------------------
__global__ void __launch_bounds__(256)
ln_kernel(const float* __restrict__ x, const float* __restrict__ add,
          const float* __restrict__ s, const float* __restrict__ b,
          float* __restrict__ out, h16* __restrict__ oh)
{
    const int row = blockIdx.x;
    const int tid = threadIdx.x;
    const size_t base = (size_t)row * Dc;

    float v[4];
    float sum = 0.f, sq = 0.f;
#pragma unroll
    for (int i = 0; i < 4; i++) {
        int c = tid + i * 256;
        float val = x[base + c];
        if (add) val += add[base + c];
        v[i] = val;
        sum += val;
        sq  += val * val;
    }
#pragma unroll
    for (int off = 16; off > 0; off >>= 1) {
        sum += __shfl_xor_sync(0xffffffffu, sum, off);
        sq  += __shfl_xor_sync(0xffffffffu, sq, off);
    }
    __shared__ float s1[8], s2[8];
    __shared__ float mu_s, inv_s;
    int lane = tid & 31, wid = tid >> 5;
    if (lane == 0) { s1[wid] = sum; s2[wid] = sq; }
    __syncthreads();
    if (tid == 0) {
        float ts = 0.f, tq = 0.f;
#pragma unroll
        for (int i = 0; i < 8; i++) { ts += s1[i]; tq += s2[i]; }
        float mu  = ts * (1.f / Dc);
        float var = tq * (1.f / Dc) - mu * mu;
        mu_s  = mu;
        inv_s = rsqrtf(var + 1e-5f);
    }
    __syncthreads();
    float mu = mu_s, inv = inv_s;
#pragma unroll
    for (int i = 0; i < 4; i++) {
        int c = tid + i * 256;
        float r = (v[i] - mu) * inv * s[c] + b[c];
        out[base + c] = r;
        oh[base + c]  = __float2half(r);
    }
}

// ---------------------------------------------------------------------------
// Embedding gather + positional add; writes fp32 + fp16
// ---------------------------------------------------------------------------
__global__ void __launch_bounds__(256)
embed_kernel(const int* __restrict__ seq, const float* __restrict__ emb,
             const float* __restrict__ pos, float* __restrict__ x,
             h16* __restrict__ xh)
{
    const int row  = blockIdx.x;
    const int sidx = row & (Sc - 1);
    const int tok  = seq[row];
    const int tid  = threadIdx.x;
#pragma unroll
    for (int i = 0; i < 4; i++) {
        int c = tid + i * 256;
        float r = emb[(size_t)tok * Dc + c] + pos[(size_t)sidx * Dc + c];
        size_t o = (size_t)row * Dc + c;
        x[o]  = r;
        xh[o] = __float2half(r);
    }
}

// ---------------------------------------------------------------------------
// Host orchestration
// ---------------------------------------------------------------------------
template <bool BIAS, bool RELU, bool OUTHALF>
static void launch_gemm(const h16* a, const h16* b, const float* bias,
                        float* C, h16* ch, int M, int N, int K)
{
    cudaFuncSetAttribute(tc_gemm<BIAS, RELU, OUTHALF>,
                         cudaFuncAttributeMaxDynamicSharedMemorySize, GEMM_SMEM_TOTAL);
    dim3 grid(N / 128, M / 128);
    tc_gemm<BIAS, RELU, OUTHALF><<<grid, 256, GEMM_SMEM_TOTAL>>>(a, b, bias, C, ch, M, N, K);
}

extern "C" void kernel_launch(void* const* d_in, const int* in_sizes, int n_in,
                              void* d_out, int out_size)
{
    (void)in_sizes; (void)n_in; (void)out_size;

    const float* encoded      = (const float*)d_in[0];
    const int*   seq          = (const int*)  d_in[1];
    const float* input_embed  = (const float*)d_in[2];
    const float* output_embed = (const float*)d_in[3];
    const float* output_bias  = (const float*)d_in[4];
    const float* pos_embed    = (const float*)d_in[5];
    const float* Wq  = (const float*)d_in[6];
    const float* Wk  = (const float*)d_in[7];
    const float* Wv  = (const float*)d_in[8];
    const float* Wo  = (const float*)d_in[9];
    const float* Wqc = (const float*)d_in[10];
    const float* Wkc = (const float*)d_in[11];
    const float* Wvc = (const float*)d_in[12];
    const float* Woc = (const float*)d_in[13];
    const float* W1  = (const float*)d_in[14];
    const float* b1  = (const float*)d_in[15];
    const float* W2  = (const float*)d_in[16];
    const float* b2  = (const float*)d_in[17];
    const float* ln1s = (const float*)d_in[18];
    const float* ln1b = (const float*)d_in[19];
    const float* ln2s = (const float*)d_in[20];
    const float* ln2b = (const float*)d_in[21];
    const float* ln3s = (const float*)d_in[22];
    const float* ln3b = (const float*)d_in[23];
    const float* lnfs = (const float*)d_in[24];
    const float* lnfb = (const float*)d_in[25];

    float *x, *o;
    cudaGetSymbolAddress((void**)&x, g_x);
    cudaGetSymbolAddress((void**)&o, g_o);
    h16 *w, *xh, *qh, *kh, *vh, *ah, *fh, *eh;
    cudaGetSymbolAddress((void**)&w,  g_w);
    cudaGetSymbolAddress((void**)&xh, g_xh);
    cudaGetSymbolAddress((void**)&qh, g_qh);
    cudaGetSymbolAddress((void**)&kh, g_kh);
    cudaGetSymbolAddress((void**)&vh, g_vh);
    cudaGetSymbolAddress((void**)&ah, g_ah);
    cudaGetSymbolAddress((void**)&fh, g_fh);
    cudaGetSymbolAddress((void**)&eh, g_eh);

    // ---- conversions: 2 launches ----
    convT_all<<<dim3(4096, 1, 60), dim3(32, 8)>>>(Wq, Wk, Wv, Wo, Wqc, Wkc, Wvc, Woc,
                                                  W1, W2, w);
    conv_all<<<dim3(Vc, 1, 2), 256>>>((const float4*)output_embed, (const float4*)encoded,
                                      (__half2*)(w + EOFF), (__half2*)eh);

    const int NR  = Bc * Sc;   // 4096
    const int NRE = Bc * Mc;   // 8192

    embed_kernel<<<NR, 256>>>(seq, input_embed, pos_embed, x, xh);

    const dim3 agrid(Sc / 64, Hc, Bc);   // (8, 16, 8)

    for (int i = 0; i < Lc; i++) {
        const size_t lb = (size_t)i * WOFF_LAYER;
        const h16* wl = w + lb;

        // ---- self attention ----
        launch_gemm<false, false, true>(xh, wl + 0 * 1048576, nullptr, nullptr, qh, NR, Dc, Dc);
        launch_gemm<false, false, true>(xh, wl + 1 * 1048576, nullptr, nullptr, kh, NR, Dc, Dc);
        launch_gemm<false, false, true>(xh, wl + 2 * 1048576, nullptr, nullptr, vh, NR, Dc, Dc);
        attn_kernel<true><<<agrid, 128>>>(qh, kh, vh, ah, Sc);
        launch_gemm<false, false, false>(ah, wl + 3 * 1048576, nullptr, o, nullptr, NR, Dc, Dc);
        ln_kernel<<<NR, 256>>>(x, o, ln1s + (size_t)i * Dc, ln1b + (size_t)i * Dc, x, xh);

        // ---- cross attention ----
        launch_gemm<false, false, true>(xh, wl + 4 * 1048576, nullptr, nullptr, qh, NR,  Dc, Dc);
        launch_gemm<false, false, true>(eh, wl + 5 * 1048576, nullptr, nullptr, kh, NRE, Dc, Dc);
        launch_gemm<false, false, true>(eh, wl + 6 * 1048576, nullptr, nullptr, vh, NRE, Dc, Dc);
        attn_kernel<false><<<agrid, 128>>>(qh, kh, vh, ah, Mc);
        launch_gemm<false, false, false>(ah, wl + 7 * 1048576, nullptr, o, nullptr, NR, Dc, Dc);
        ln_kernel<<<NR, 256>>>(x, o, ln2s + (size_t)i * Dc, ln2b + (size_t)i * Dc, x, xh);

        // ---- FFN ----
        launch_gemm<true, true, true>(xh, wl + WOFF_W1, b1 + (size_t)i * DFc,
                                      nullptr, fh, NR, DFc, Dc);
        launch_gemm<true, false, false>(fh, wl + WOFF_W2, b2 + (size_t)i * Dc,
                                        o, nullptr, NR, Dc, DFc);
        ln_kernel<<<NR, 256>>>(x, o, ln3s + (size_t)i * Dc, ln3b + (size_t)i * Dc, x, xh);
    }

    // final norm + logits
    ln_kernel<<<NR, 256>>>(x, nullptr, lnfs, lnfb, x, xh);
    launch_gemm<true, false, false>(xh, w + EOFF, output_bias, (float*)d_out, nullptr,
                                    NR, Vc, Dc);
}

// round 14
// speedup vs baseline: 3.2191x; 1.0124x over previous
#include <cuda_runtime.h>
#include <cuda_fp16.h>
#include <math.h>
#include <stdint.h>

// Problem constants
#define Bc   8
#define Sc   512
#define Dc   1024
#define Hc   16
#define DHc  64
#define Mc   1024
#define DFc  4096
#define Vc   32000
#define Lc   6

typedef __half h16;

// ---------------------------------------------------------------------------
// Scratch (device globals)
// ---------------------------------------------------------------------------
__device__ float g_x[Bc * Sc * Dc];        // residual stream fp32
__device__ float g_o[Bc * Sc * Dc];        // proj / FFN2 output fp32
// fp16 activation buffers
__device__ h16 g_xh[Bc * Sc * Dc];
__device__ h16 g_qkvh[Bc * Sc * 3 * Dc];   // fused QKV (self)  [4096,3072]
__device__ h16 g_qh[Bc * Sc * Dc];         // cross Q           [4096,1024]
__device__ h16 g_kvh[Bc * Mc * 2 * Dc];    // fused KV (cross)  [8192,2048]
__device__ h16 g_ah[Bc * Sc * Dc];
__device__ h16 g_fh[Bc * Sc * DFc];
__device__ h16 g_eh[Bc * Mc * Dc];

// Pre-converted weights: [N,K] fp16.
#define WOFF_LAYER 16777216ull
#define WOFF_W1    8388608ull
#define WOFF_W2    12582912ull
#define EOFF       100663296ull
#define WTOTAL     133431296ull
__device__ h16 g_w[WTOTAL];

// ===========================================================================
// helpers
// ===========================================================================
__device__ __forceinline__ uint32_t smem_u32(const void* p) {
    uint32_t a;
    asm("{ .reg .u64 t; cvta.to.shared.u64 t, %1; cvt.u32.u64 %0, t; }"
        : "=r"(a) : "l"(p));
    return a;
}

__device__ __forceinline__ void mma_f16(float* d, const uint32_t* a, const uint32_t* b) {
    asm volatile(
        "mma.sync.aligned.m16n8k16.row.col.f32.f16.f16.f32 "
        "{%0,%1,%2,%3}, {%4,%5,%6,%7}, {%8,%9}, {%0,%1,%2,%3};"
        : "+f"(d[0]), "+f"(d[1]), "+f"(d[2]), "+f"(d[3])
        : "r"(a[0]), "r"(a[1]), "r"(a[2]), "r"(a[3]), "r"(b[0]), "r"(b[1]));
}

#define LDSM_X4(r, addr) \
    asm volatile("ldmatrix.sync.aligned.m8n8.x4.shared.b16 {%0,%1,%2,%3}, [%4];" \
        : "=r"((r)[0]), "=r"((r)[1]), "=r"((r)[2]), "=r"((r)[3]) : "r"(addr))

#define LDSM_X4T(r, addr) \
    asm volatile("ldmatrix.sync.aligned.m8n8.x4.trans.shared.b16 {%0,%1,%2,%3}, [%4];" \
        : "=r"((r)[0]), "=r"((r)[1]), "=r"((r)[2]), "=r"((r)[3]) : "r"(addr))

#define CP_ASYNC16(dst, src) \
    asm volatile("cp.async.cg.shared.global [%0], [%1], 16;" :: "r"(dst), "l"(src))
#define CP_COMMIT()  asm volatile("cp.async.commit_group;" ::: "memory")
#define CP_WAIT2()   asm volatile("cp.async.wait_group 2;" ::: "memory")
#define CP_WAIT1()   asm volatile("cp.async.wait_group 1;" ::: "memory")
#define CP_WAIT0()   asm volatile("cp.async.wait_group 0;" ::: "memory")

// ===========================================================================
// Conversion kernels — 2 launches total
// ===========================================================================
__global__ void convT_all(const float* __restrict__ Wq, const float* __restrict__ Wk,
                          const float* __restrict__ Wv, const float* __restrict__ Wo,
                          const float* __restrict__ Wqc, const float* __restrict__ Wkc,
                          const float* __restrict__ Wvc, const float* __restrict__ Woc,
                          const float* __restrict__ W1, const float* __restrict__ W2,
                          h16* __restrict__ dst)
{
    __shared__ float ts[32][33];
    const int z = blockIdx.z;
    const int t = blockIdx.x;

    const float* src;
    h16* out;
    int K, N, k0, n0;

    if (z < 48) {
        if (t >= 1024) return;
        const int layer = z >> 3;
        const int j     = z & 7;
        const float* srcs[8] = { Wq, Wk, Wv, Wo, Wqc, Wkc, Wvc, Woc };
        src = srcs[j] + (size_t)layer * Dc * Dc;
        out = dst + (size_t)layer * WOFF_LAYER + (size_t)j * 1048576;
        K = Dc; N = Dc;
        k0 = (t >> 5) * 32;
        n0 = (t & 31) * 32;
    } else if (z < 54) {
        const int layer = z - 48;
        src = W1 + (size_t)layer * Dc * DFc;
        out = dst + (size_t)layer * WOFF_LAYER + WOFF_W1;
        K = Dc; N = DFc;
        n0 = (t & 127) * 32;
        k0 = (t >> 7) * 32;
    } else {
        const int layer = z - 54;
        src = W2 + (size_t)layer * DFc * Dc;
        out = dst + (size_t)layer * WOFF_LAYER + WOFF_W2;
        K = DFc; N = Dc;
        n0 = (t & 31) * 32;
        k0 = (t >> 5) * 32;
    }

    const int tx = threadIdx.x, ty = threadIdx.y;
#pragma unroll
    for (int j = 0; j < 4; j++)
        ts[ty + j * 8][tx] = src[(size_t)(k0 + ty + j * 8) * N + n0 + tx];
    __syncthreads();
#pragma unroll
    for (int j = 0; j < 4; j++) {
        int n = ty + j * 8;
        out[(size_t)(n0 + n) * K + k0 + tx] = __float2half(ts[tx][n]);
    }
}

__global__ void conv_all(const float4* __restrict__ outemb, const float4* __restrict__ enc,
                         __half2* __restrict__ w_out, __half2* __restrict__ e_out)
{
    const int z = blockIdx.z;
    if (z == 1 && blockIdx.x >= (Bc * Mc)) return;
    const float4* src = (z == 0) ? outemb : enc;
    __half2* out = (z == 0) ? w_out : e_out;

    size_t i = (size_t)blockIdx.x * blockDim.x + threadIdx.x;
    float4 v = src[i];
    out[i * 2]     = __floats2half2_rn(v.x, v.y);
    out[i * 2 + 1] = __floats2half2_rn(v.z, v.w);
}

// ===========================================================================
// Tensor-core GEMM v6: fp16 single-pass, BK=64 (4 subtiles of the proven
// 9216B layout per stage), 3-stage cp.async pipeline, 2 CTAs/SM.
// ===========================================================================
#define PROWB  144
#define TILEB  (64 * PROWB)                // 9216 B subtile: 128 rows x 32 k
#define STAGEB (4 * TILEB)                 // 36864 B: A-k0, A-k1, B-k0, B-k1
#define NSTAGE 3
#define GEMM_SMEM (NSTAGE * STAGEB)        // 110592 B (epilogue 67584 fits)
#define ROWOFF(r) (((r) & 63) * PROWB + ((r) >> 6) * 64)

template <bool BIAS, bool RELU, bool OUTHALF>
__global__ void __launch_bounds__(256, 2)
tc_gemm(const h16* __restrict__ A_g, const h16* __restrict__ B_g,
        const float* __restrict__ bias, float* __restrict__ C,
        h16* __restrict__ Ch, int M, int N, int K)
{
    extern __shared__ char smem[];
    const int tid  = threadIdx.x;
    const int wid  = tid >> 5;
    const int lane = tid & 31;
    const int g    = lane >> 2;
    const int t    = lane & 3;
    const int wm   = wid & 1;
    const int wn   = wid >> 1;
    const int m0   = blockIdx.y * 128;
    const int n0   = blockIdx.x * 128;

    const uint32_t smem0 = smem_u32(smem);

    const int arow_l = (lane & 7) + ((lane >> 3) & 1) * 8;
    const uint32_t aoffL =
        (uint32_t)(arow_l * PROWB + wm * 64 + (lane >> 4) * 16);
    const int brow_l = ((lane >> 4) & 1) * 8 + (lane & 7);
    const uint32_t boffL =
        (uint32_t)(((wn & 1) * 32 + brow_l) * PROWB + (wn >> 1) * 64 +
                   ((lane >> 3) & 1) * 16);

    float acc[4][4][4];
#pragma unroll
    for (int i = 0; i < 4; i++)
#pragma unroll
        for (int j = 0; j < 4; j++)
#pragma unroll
            for (int c = 0; c < 4; c++) acc[i][j][c] = 0.f;

    const int S = K >> 6;      // BK = 64

    // per stage: 2 tensors x 128 rows x 8 chunks(16B) = 2048 -> 8/thread
    auto cp_stage = [&](int s, int b) {
        const int k0 = s << 6;
        char* base = smem + b * STAGEB;
#pragma unroll
        for (int i = 0; i < 8; i++) {
            const int sel   = i >> 2;                    // 0:A, 1:B
            const int inner = tid + (i & 3) * 256;       // 0..1023
            const int r     = inner >> 3;                // 0..127
            const int c     = inner & 7;                 // 0..7 (16B chunks)
            const int kh    = c >> 2;                    // k-half subtile
            const int c4    = c & 3;
            const h16* src = (sel ? B_g : A_g) +
                             (size_t)((sel ? n0 : m0) + r) * K + k0 + kh * 32 + c4 * 8;
            uint32_t dst = smem_u32(base + (sel * 2 + kh) * TILEB +
                                    ROWOFF(r) + c4 * 16);
            CP_ASYNC16(dst, src);
        }
    };

    auto compute = [&](int b) {
        const uint32_t base = smem0 + b * STAGEB;
#pragma unroll
        for (int sub = 0; sub < 2; sub++) {
            const uint32_t Aa = base + sub * TILEB + aoffL;
            const uint32_t Bb = base + (2 + sub) * TILEB + boffL;
#pragma unroll
            for (int ks = 0; ks < 2; ks++) {
                const uint32_t kb = ks * 32;
                uint32_t af[4][4], bf[2][4];
#pragma unroll
                for (int mt = 0; mt < 4; mt++)
                    LDSM_X4(af[mt], Aa + mt * (16 * PROWB) + kb);
#pragma unroll
                for (int j = 0; j < 2; j++)
                    LDSM_X4(bf[j], Bb + j * (16 * PROWB) + kb);
#pragma unroll
                for (int mt = 0; mt < 4; mt++)
#pragma unroll
                    for (int nt = 0; nt < 4; nt++)
                        mma_f16(acc[mt][nt], af[mt], &bf[nt >> 1][(nt & 1) * 2]);
            }
        }
    };

    cp_stage(0, 0);
    CP_COMMIT();
    if (S > 1) { cp_stage(1, 1); CP_COMMIT(); }

    for (int s = 0; s < S; s++) {
        if (s + 1 < S) CP_WAIT1();
        else           CP_WAIT0();
        __syncthreads();
        if (s + 2 < S) { cp_stage(s + 2, (s + 2) % NSTAGE); CP_COMMIT(); }
        compute(s % NSTAGE);
    }
    __syncthreads();

    float* stage = reinterpret_cast<float*>(smem);
#pragma unroll
    for (int mt = 0; mt < 4; mt++) {
#pragma unroll
        for (int nt = 0; nt < 4; nt++) {
            int row = wm * 64 + mt * 16 + g;
            int col = wn * 32 + nt * 8 + t * 2;
            *reinterpret_cast<float2*>(&stage[row * 132 + col]) =
                make_float2(acc[mt][nt][0], acc[mt][nt][1]);
            *reinterpret_cast<float2*>(&stage[(row + 8) * 132 + col]) =
                make_float2(acc[mt][nt][2], acc[mt][nt][3]);
        }
    }
    __syncthreads();

#pragma unroll
    for (int i = 0; i < 16; i++) {
        int f   = i * 256 + tid;
        int row = f >> 5;
        int c4  = f & 31;
        float4 v = *reinterpret_cast<float4*>(&stage[row * 132 + c4 * 4]);
        if (BIAS) {
            float4 bv = *reinterpret_cast<const float4*>(bias + n0 + c4 * 4);
            v.x += bv.x; v.y += bv.y; v.z += bv.z; v.w += bv.w;
        }
        if (RELU) {
            v.x = fmaxf(v.x, 0.f); v.y = fmaxf(v.y, 0.f);
            v.z = fmaxf(v.z, 0.f); v.w = fmaxf(v.w, 0.f);
        }
        size_t oidx = (size_t)(m0 + row) * N + n0 + c4 * 4;
        if (OUTHALF) {
            *reinterpret_cast<__half2*>(Ch + oidx)     = __floats2half2_rn(v.x, v.y);
            *reinterpret_cast<__half2*>(Ch + oidx + 2) = __floats2half2_rn(v.z, v.w);
        } else {
            *reinterpret_cast<float4*>(C + oidx) = v;
        }
    }
}

// ===========================================================================
// Flash attention via mma.sync (R13-proven) with Q / KV row strides so it
// can read fused QKV / KV buffers directly.
// ===========================================================================
#define AT_PITCH 72      // halves per smem row, 144 B

template <bool CAUSAL>
__global__ void __launch_bounds__(128)
attn_kernel(const h16* __restrict__ Qh, const h16* __restrict__ Kh,
            const h16* __restrict__ Vh, h16* __restrict__ Oh,
            int Lk, int qstr, int kvstr)
{
    __shared__ h16 sQ[64 * AT_PITCH];
    __shared__ h16 sK[3][32 * AT_PITCH];
    __shared__ h16 sV[3][32 * AT_PITCH];

    const int b    = blockIdx.z;
    const int h    = blockIdx.y;
    const int q0   = blockIdx.x * 64;
    const int tid  = threadIdx.x;
    const int lane = tid & 31;
    const int w    = tid >> 5;
    const int wr0  = w * 16;
    const int g    = lane >> 2;
    const int t    = lane & 3;

    const int nkt = CAUSAL ? ((q0 + 64) >> 5) : (Lk >> 5);

    auto cp_q = [&]() {
#pragma unroll
        for (int i = 0; i < 4; i++) {
            int idx = tid + i * 128;
            int r = idx >> 3, c = idx & 7;
            const h16* src = Qh + (size_t)(b * Sc + q0 + r) * qstr + h * 64 + c * 8;
            CP_ASYNC16(smem_u32(&sQ[r * AT_PITCH]) + c * 16, src);
        }
    };
    auto cp_kv = [&](int kt, int stg) {
        const int k0 = kt << 5;
#pragma unroll
        for (int i = 0; i < 4; i++) {
            int idx = tid + i * 128;
            int sel = idx >> 8;
            int rem = idx & 255;
            int r = rem >> 3, c = rem & 7;
            const h16* src = (sel ? Vh : Kh) +
                             (size_t)(b * Lk + k0 + r) * kvstr + h * 64 + c * 8;
            h16* dst = (sel ? sV[stg] : sK[stg]) + r * AT_PITCH;
            CP_ASYNC16(smem_u32(dst) + c * 16, src);
        }
    };

    cp_q();
    CP_COMMIT();
    cp_kv(0, 0);
    CP_COMMIT();
    if (nkt > 1) { cp_kv(1, 1); CP_COMMIT(); }
    if (nkt > 1) CP_WAIT2(); else CP_WAIT1();
    __syncthreads();

    uint32_t aq[4][4];
    {
        const int qrow = (lane & 7) + ((lane >> 3) & 1) * 8;
        const uint32_t qaddr = smem_u32(sQ) +
            (uint32_t)((wr0 + qrow) * (AT_PITCH * 2) + (lane >> 4) * 16);
#pragma unroll
        for (int ks = 0; ks < 4; ks++)
            LDSM_X4(aq[ks], qaddr + ks * 32);
    }

    const int kb_row = ((lane >> 4) & 1) * 8 + (lane & 7);
    const uint32_t kboff = (uint32_t)(kb_row * (AT_PITCH * 2) + ((lane >> 3) & 1) * 16);
    const int v_row = ((lane >> 3) & 1) * 8 + (lane & 7);
    const uint32_t vboff = (uint32_t)(v_row * (AT_PITCH * 2) + (lane >> 4) * 16);

    float oacc[8][4];
#pragma unroll
    for (int d = 0; d < 8; d++)
#pragma unroll
        for (int c = 0; c < 4; c++) oacc[d][c] = 0.f;
    float mrow0 = -1e30f, mrow1 = -1e30f, lrow0 = 0.f, lrow1 = 0.f;

    const int row0 = q0 + wr0 + g;
    const int row1 = row0 + 8;

    for (int kt = 0; kt < nkt; kt++) {
        if (kt + 1 < nkt) CP_WAIT1();
        else              CP_WAIT0();
        __syncthreads();
        if (kt + 2 < nkt) { cp_kv(kt + 2, (kt + 2) % 3); CP_COMMIT(); }

        const int stg = kt % 3;
        const int k0  = kt << 5;

        float s[4][4];
#pragma unroll
        for (int nt = 0; nt < 4; nt++)
#pragma unroll
            for (int c = 0; c < 4; c++) s[nt][c] = 0.f;
        const uint32_t Kb = smem_u32(sK[stg]) + kboff;
#pragma unroll
        for (int ks = 0; ks < 4; ks++) {
            uint32_t bk[2][4];
#pragma unroll
            for (int j = 0; j < 2; j++)
                LDSM_X4(bk[j], Kb + j * (16 * AT_PITCH * 2) + ks * 32);
#pragma unroll
            for (int nt = 0; nt < 4; nt++)
                mma_f16(s[nt], aq[ks], &bk[nt >> 1][(nt & 1) * 2]);
        }

#pragma unroll
        for (int nt = 0; nt < 4; nt++) {
            const int col0 = k0 + nt * 8 + 2 * t;
#pragma unroll
            for (int c = 0; c < 4; c++) s[nt][c] *= 0.125f;
            if (CAUSAL) {
                if (col0     > row0) s[nt][0] = -1e9f;
                if (col0 + 1 > row0) s[nt][1] = -1e9f;
                if (col0     > row1) s[nt][2] = -1e9f;
                if (col0 + 1 > row1) s[nt][3] = -1e9f;
            }
        }

        float ml0 = -1e30f, ml1 = -1e30f;
#pragma unroll
        for (int nt = 0; nt < 4; nt++) {
            ml0 = fmaxf(ml0, fmaxf(s[nt][0], s[nt][1]));
            ml1 = fmaxf(ml1, fmaxf(s[nt][2], s[nt][3]));
        }
        ml0 = fmaxf(ml0, __shfl_xor_sync(0xffffffffu, ml0, 1));
        ml0 = fmaxf(ml0, __shfl_xor_sync(0xffffffffu, ml0, 2));
        ml1 = fmaxf(ml1, __shfl_xor_sync(0xffffffffu, ml1, 1));
        ml1 = fmaxf(ml1, __shfl_xor_sync(0xffffffffu, ml1, 2));
        const float mn0 = fmaxf(mrow0, ml0);
        const float mn1 = fmaxf(mrow1, ml1);
        const float al0 = __expf(mrow0 - mn0);
        const float al1 = __expf(mrow1 - mn1);
        mrow0 = mn0; mrow1 = mn1;

        uint32_t pa[4][2];
        float ls0 = 0.f, ls1 = 0.f;
#pragma unroll
        for (int nt = 0; nt < 4; nt++) {
            float p0 = __expf(s[nt][0] - mn0);
            float p1 = __expf(s[nt][1] - mn0);
            float p2 = __expf(s[nt][2] - mn1);
            float p3 = __expf(s[nt][3] - mn1);
            ls0 += p0 + p1;
            ls1 += p2 + p3;
            __half2 h01 = __floats2half2_rn(p0, p1);
            __half2 h23 = __floats2half2_rn(p2, p3);
            pa[nt][0] = *reinterpret_cast<uint32_t*>(&h01);
            pa[nt][1] = *reinterpret_cast<uint32_t*>(&h23);
        }
        ls0 += __shfl_xor_sync(0xffffffffu, ls0, 1);
        ls0 += __shfl_xor_sync(0xffffffffu, ls0, 2);
        ls1 += __shfl_xor_sync(0xffffffffu, ls1, 1);
        ls1 += __shfl_xor_sync(0xffffffffu, ls1, 2);
        lrow0 = lrow0 * al0 + ls0;
        lrow1 = lrow1 * al1 + ls1;
#pragma unroll
        for (int d = 0; d < 8; d++) {
            oacc[d][0] *= al0; oacc[d][1] *= al0;
            oacc[d][2] *= al1; oacc[d][3] *= al1;
        }

        const uint32_t Vb = smem_u32(sV[stg]) + vboff;
#pragma unroll
        for (int ks2 = 0; ks2 < 2; ks2++) {
            uint32_t aP[4] = { pa[2 * ks2][0], pa[2 * ks2][1],
                               pa[2 * ks2 + 1][0], pa[2 * ks2 + 1][1] };
#pragma unroll
            for (int dp = 0; dp < 4; dp++) {
                uint32_t bv[4];
                LDSM_X4T(bv, Vb + ks2 * (16 * AT_PITCH * 2) + dp * 32);
                mma_f16(oacc[dp * 2 + 0], aP, &bv[0]);
                mma_f16(oacc[dp * 2 + 1], aP, &bv[2]);
            }
        }
    }

    const float inv0 = 1.f / lrow0;
    const float inv1 = 1.f / lrow1;
    h16* o0p = Oh + (size_t)(b * Sc + row0) * Dc + h * 64;
    h16* o1p = Oh + (size_t)(b * Sc + row1) * Dc + h * 64;
#pragma unroll
    for (int d = 0; d < 8; d++) {
        int col = d * 8 + 2 * t;
        *reinterpret_cast<__half2*>(o0p + col) =
            __floats2half2_rn(oacc[d][0] * inv0, oacc[d][1] * inv0);
        *reinterpret_cast<__half2*>(o1p + col) =
            __floats2half2_rn(oacc[d][2] * inv1, oacc[d][3] * inv1);
    }
}

// ---------------------------------------------------------------------------
// Residual + LayerNorm; writes fp32 + fp16 mirror
// ---------------------------------------------------------------------------
__global__ void __launch_bounds__(256)
ln_kernel(const float* __restrict__ x, const float* __restrict__ add,
          const float* __restrict__ s, const float* __restrict__ b,
          float* __restrict__ out, h16* __restrict__ oh)
{
    const int row = blockIdx.x;
    const int tid = threadIdx.x;
    const size_t base = (size_t)row * Dc;

    float v[4];
    float sum = 0.f, sq = 0.f;
#pragma unroll
    for (int i = 0; i < 4; i++) {
        int c = tid + i * 256;
        float val = x[base + c];
        if (add) val += add[base + c];
        v[i] = val;
        sum += val;
        sq  += val * val;
    }
#pragma unroll
    for (int off = 16; off > 0; off >>= 1) {
        sum += __shfl_xor_sync(0xffffffffu, sum, off);
        sq  += __shfl_xor_sync(0xffffffffu, sq, off);
    }
    __shared__ float s1[8], s2[8];
    __shared__ float mu_s, inv_s;
    int lane = tid & 31, wid = tid >> 5;
    if (lane == 0) { s1[wid] = sum; s2[wid] = sq; }
    __syncthreads();
    if (tid == 0) {
        float ts = 0.f, tq = 0.f;
#pragma unroll
        for (int i = 0; i < 8; i++) { ts += s1[i]; tq += s2[i]; }
        float mu  = ts * (1.f / Dc);
        float var = tq * (1.f / Dc) - mu * mu;
        mu_s  = mu;
        inv_s = rsqrtf(var + 1e-5f);
    }
    __syncthreads();
    float mu = mu_s, inv = inv_s;
#pragma unroll
    for (int i = 0; i < 4; i++) {
        int c = tid + i * 256;
        float r = (v[i] - mu) * inv * s[c] + b[c];
        out[base + c] = r;
        oh[base + c]  = __float2half(r);
    }
}

// ---------------------------------------------------------------------------
// Embedding gather + positional add; writes fp32 + fp16
// ---------------------------------------------------------------------------
__global__ void __launch_bounds__(256)
embed_kernel(const int* __restrict__ seq, const float* __restrict__ emb,
             const float* __restrict__ pos, float* __restrict__ x,
             h16* __restrict__ xh)
{
    const int row  = blockIdx.x;
    const int sidx = row & (Sc - 1);
    const int tok  = seq[row];
    const int tid  = threadIdx.x;
#pragma unroll
    for (int i = 0; i < 4; i++) {
        int c = tid + i * 256;
        float r = emb[(size_t)tok * Dc + c] + pos[(size_t)sidx * Dc + c];
        size_t o = (size_t)row * Dc + c;
        x[o]  = r;
        xh[o] = __float2half(r);
    }
}

// ---------------------------------------------------------------------------
// Host orchestration
// ---------------------------------------------------------------------------
template <bool BIAS, bool RELU, bool OUTHALF>
static void launch_gemm(const h16* a, const h16* b, const float* bias,
                        float* C, h16* ch, int M, int N, int K)
{
    cudaFuncSetAttribute(tc_gemm<BIAS, RELU, OUTHALF>,
                         cudaFuncAttributeMaxDynamicSharedMemorySize, GEMM_SMEM);
    dim3 grid(N / 128, M / 128);
    tc_gemm<BIAS, RELU, OUTHALF><<<grid, 256, GEMM_SMEM>>>(a, b, bias, C, ch, M, N, K);
}

extern "C" void kernel_launch(void* const* d_in, const int* in_sizes, int n_in,
                              void* d_out, int out_size)
{
    (void)in_sizes; (void)n_in; (void)out_size;

    const float* encoded      = (const float*)d_in[0];
    const int*   seq          = (const int*)  d_in[1];
    const float* input_embed  = (const float*)d_in[2];
    const float* output_embed = (const float*)d_in[3];
    const float* output_bias  = (const float*)d_in[4];
    const float* pos_embed    = (const float*)d_in[5];
    const float* Wq  = (const float*)d_in[6];
    const float* Wk  = (const float*)d_in[7];
    const float* Wv  = (const float*)d_in[8];
    const float* Wo  = (const float*)d_in[9];
    const float* Wqc = (const float*)d_in[10];
    const float* Wkc = (const float*)d_in[11];
    const float* Wvc = (const float*)d_in[12];
    const float* Woc = (const float*)d_in[13];
    const float* W1  = (const float*)d_in[14];
    const float* b1  = (const float*)d_in[15];
    const float* W2  = (const float*)d_in[16];
    const float* b2  = (const float*)d_in[17];
    const float* ln1s = (const float*)d_in[18];
    const float* ln1b = (const float*)d_in[19];
    const float* ln2s = (const float*)d_in[20];
    const float* ln2b = (const float*)d_in[21];
    const float* ln3s = (const float*)d_in[22];
    const float* ln3b = (const float*)d_in[23];
    const float* lnfs = (const float*)d_in[24];
    const float* lnfb = (const float*)d_in[25];

    float *x, *o;
    cudaGetSymbolAddress((void**)&x, g_x);
    cudaGetSymbolAddress((void**)&o, g_o);
    h16 *w, *xh, *qkvh, *qh, *kvh, *ah, *fh, *eh;
    cudaGetSymbolAddress((void**)&w,    g_w);
    cudaGetSymbolAddress((void**)&xh,   g_xh);
    cudaGetSymbolAddress((void**)&qkvh, g_qkvh);
    cudaGetSymbolAddress((void**)&qh,   g_qh);
    cudaGetSymbolAddress((void**)&kvh,  g_kvh);
    cudaGetSymbolAddress((void**)&ah,   g_ah);
    cudaGetSymbolAddress((void**)&fh,   g_fh);
    cudaGetSymbolAddress((void**)&eh,   g_eh);

    // ---- conversions: 2 launches ----
    convT_all<<<dim3(4096, 1, 60), dim3(32, 8)>>>(Wq, Wk, Wv, Wo, Wqc, Wkc, Wvc, Woc,
                                                  W1, W2, w);
    conv_all<<<dim3(Vc, 1, 2), 256>>>((const float4*)output_embed, (const float4*)encoded,
                                      (__half2*)(w + EOFF), (__half2*)eh);

    const int NR  = Bc * Sc;   // 4096
    const int NRE = Bc * Mc;   // 8192

    embed_kernel<<<NR, 256>>>(seq, input_embed, pos_embed, x, xh);

    const dim3 agrid(Sc / 64, Hc, Bc);   // (8, 16, 8)

    for (int i = 0; i < Lc; i++) {
        const size_t lb = (size_t)i * WOFF_LAYER;
        const h16* wl = w + lb;

        // ---- self attention: fused QKV (Wq,Wk,Wv contiguous -> N=3072) ----
        launch_gemm<false, false, true>(xh, wl, nullptr, nullptr, qkvh, NR, 3 * Dc, Dc);
        attn_kernel<true><<<agrid, 128>>>(qkvh, qkvh + Dc, qkvh + 2 * Dc, ah,
                                          Sc, 3 * Dc, 3 * Dc);
        launch_gemm<false, false, false>(ah, wl + 3 * 1048576, nullptr, o, nullptr, NR, Dc, Dc);
        ln_kernel<<<NR, 256>>>(x, o, ln1s + (size_t)i * Dc, ln1b + (size_t)i * Dc, x, xh);

        // ---- cross attention: Q alone; fused KV (Wkc,Wvc contiguous) ----
        launch_gemm<false, false, true>(xh, wl + 4 * 1048576, nullptr, nullptr, qh, NR, Dc, Dc);
        launch_gemm<false, false, true>(eh, wl + 5 * 1048576, nullptr, nullptr, kvh,
                                        NRE, 2 * Dc, Dc);
        attn_kernel<false><<<agrid, 128>>>(qh, kvh, kvh + Dc, ah, Mc, Dc, 2 * Dc);
        launch_gemm<false, false, false>(ah, wl + 7 * 1048576, nullptr, o, nullptr, NR, Dc, Dc);
        ln_kernel<<<NR, 256>>>(x, o, ln2s + (size_t)i * Dc, ln2b + (size_t)i * Dc, x, xh);

        // ---- FFN ----
        launch_gemm<true, true, true>(xh, wl + WOFF_W1, b1 + (size_t)i * DFc,
                                      nullptr, fh, NR, DFc, Dc);
        launch_gemm<true, false, false>(fh, wl + WOFF_W2, b2 + (size_t)i * Dc,
                                        o, nullptr, NR, Dc, DFc);
        ln_kernel<<<NR, 256>>>(x, o, ln3s + (size_t)i * Dc, ln3b + (size_t)i * Dc, x, xh);
    }

    // final norm + logits
    ln_kernel<<<NR, 256>>>(x, nullptr, lnfs, lnfb, x, xh);
    launch_gemm<true, false, false>(xh, w + EOFF, output_bias, (float*)d_out, nullptr,
                                    NR, Vc, Dc);
}

// round 15
// speedup vs baseline: 3.5775x; 1.1113x over previous
#include <cuda_runtime.h>
#include <cuda_fp16.h>
#include <math.h>
#include <stdint.h>

// Problem constants
#define Bc   8
#define Sc   512
#define Dc   1024
#define Hc   16
#define DHc  64
#define Mc   1024
#define DFc  4096
#define Vc   32000
#define Lc   6

typedef __half h16;

// ---------------------------------------------------------------------------
// Scratch (device globals)
// ---------------------------------------------------------------------------
__device__ float g_x[Bc * Sc * Dc];
__device__ float g_o[Bc * Sc * Dc];
__device__ h16 g_xh[Bc * Sc * Dc];
__device__ h16 g_qkvh[Bc * Sc * 3 * Dc];
__device__ h16 g_qh[Bc * Sc * Dc];
__device__ h16 g_kvh[Bc * Mc * 2 * Dc];
__device__ h16 g_ah[Bc * Sc * Dc];
__device__ h16 g_fh[Bc * Sc * DFc];
__device__ h16 g_eh[Bc * Mc * Dc];

#define WOFF_LAYER 16777216ull
#define WOFF_W1    8388608ull
#define WOFF_W2    12582912ull
#define EOFF       100663296ull
#define WTOTAL     133431296ull
__device__ h16 g_w[WTOTAL];

// ===========================================================================
// helpers
// ===========================================================================
__device__ __forceinline__ uint32_t smem_u32(const void* p) {
    uint32_t a;
    asm("{ .reg .u64 t; cvta.to.shared.u64 t, %1; cvt.u32.u64 %0, t; }"
        : "=r"(a) : "l"(p));
    return a;
}

__device__ __forceinline__ void mma_f16(float* d, const uint32_t* a, const uint32_t* b) {
    asm volatile(
        "mma.sync.aligned.m16n8k16.row.col.f32.f16.f16.f32 "
        "{%0,%1,%2,%3}, {%4,%5,%6,%7}, {%8,%9}, {%0,%1,%2,%3};"
        : "+f"(d[0]), "+f"(d[1]), "+f"(d[2]), "+f"(d[3])
        : "r"(a[0]), "r"(a[1]), "r"(a[2]), "r"(a[3]), "r"(b[0]), "r"(b[1]));
}

#define LDSM_X4(r, addr) \
    asm volatile("ldmatrix.sync.aligned.m8n8.x4.shared.b16 {%0,%1,%2,%3}, [%4];" \
        : "=r"((r)[0]), "=r"((r)[1]), "=r"((r)[2]), "=r"((r)[3]) : "r"(addr))

#define LDSM_X4T(r, addr) \
    asm volatile("ldmatrix.sync.aligned.m8n8.x4.trans.shared.b16 {%0,%1,%2,%3}, [%4];" \
        : "=r"((r)[0]), "=r"((r)[1]), "=r"((r)[2]), "=r"((r)[3]) : "r"(addr))

#define CP_ASYNC16(dst, src) \
    asm volatile("cp.async.cg.shared.global [%0], [%1], 16;" :: "r"(dst), "l"(src))
#define CP_COMMIT()  asm volatile("cp.async.commit_group;" ::: "memory")
#define CP_WAIT2()   asm volatile("cp.async.wait_group 2;" ::: "memory")
#define CP_WAIT1()   asm volatile("cp.async.wait_group 1;" ::: "memory")
#define CP_WAIT0()   asm volatile("cp.async.wait_group 0;" ::: "memory")

// ===========================================================================
// Conversion kernels — 2 launches total
// ===========================================================================
__global__ void convT_all(const float* __restrict__ Wq, const float* __restrict__ Wk,
                          const float* __restrict__ Wv, const float* __restrict__ Wo,
                          const float* __restrict__ Wqc, const float* __restrict__ Wkc,
                          const float* __restrict__ Wvc, const float* __restrict__ Woc,
                          const float* __restrict__ W1, const float* __restrict__ W2,
                          h16* __restrict__ dst)
{
    __shared__ float ts[32][33];
    const int z = blockIdx.z;
    const int t = blockIdx.x;

    const float* src;
    h16* out;
    int K, N, k0, n0;

    if (z < 48) {
        if (t >= 1024) return;
        const int layer = z >> 3;
        const int j     = z & 7;
        const float* srcs[8] = { Wq, Wk, Wv, Wo, Wqc, Wkc, Wvc, Woc };
        src = srcs[j] + (size_t)layer * Dc * Dc;
        out = dst + (size_t)layer * WOFF_LAYER + (size_t)j * 1048576;
        K = Dc; N = Dc;
        k0 = (t >> 5) * 32;
        n0 = (t & 31) * 32;
    } else if (z < 54) {
        const int layer = z - 48;
        src = W1 + (size_t)layer * Dc * DFc;
        out = dst + (size_t)layer * WOFF_LAYER + WOFF_W1;
        K = Dc; N = DFc;
        n0 = (t & 127) * 32;
        k0 = (t >> 7) * 32;
    } else {
        const int layer = z - 54;
        src = W2 + (size_t)layer * DFc * Dc;
        out = dst + (size_t)layer * WOFF_LAYER + WOFF_W2;
        K = DFc; N = Dc;
        n0 = (t & 31) * 32;
        k0 = (t >> 5) * 32;
    }

    const int tx = threadIdx.x, ty = threadIdx.y;
#pragma unroll
    for (int j = 0; j < 4; j++)
        ts[ty + j * 8][tx] = src[(size_t)(k0 + ty + j * 8) * N + n0 + tx];
    __syncthreads();
#pragma unroll
    for (int j = 0; j < 4; j++) {
        int n = ty + j * 8;
        out[(size_t)(n0 + n) * K + k0 + tx] = __float2half(ts[tx][n]);
    }
}

__global__ void conv_all(const float4* __restrict__ outemb, const float4* __restrict__ enc,
                         __half2* __restrict__ w_out, __half2* __restrict__ e_out)
{
    const int z = blockIdx.z;
    if (z == 1 && blockIdx.x >= (Bc * Mc)) return;
    const float4* src = (z == 0) ? outemb : enc;
    __half2* out = (z == 0) ? w_out : e_out;

    size_t i = (size_t)blockIdx.x * blockDim.x + threadIdx.x;
    float4 v = src[i];
    out[i * 2]     = __floats2half2_rn(v.x, v.y);
    out[i * 2 + 1] = __floats2half2_rn(v.z, v.w);
}

// ===========================================================================
// Tensor-core GEMM v7: fat-warp ILP. 128 threads (4 warps), warp tile 64x64,
// all-stage fragments preloaded, BK=32, NSTAGE=4, 2 CTAs/SM.
// ===========================================================================
#define PROWB  144
#define TILEB  (64 * PROWB)                // 9216 B: 128 rows x 32 halves
#define STAGEB (2 * TILEB)                 // 18432 B (A + B)
#define NSTAGE 4
#define GEMM_SMEM (NSTAGE * STAGEB)        // 73728 B (epilogue 67584 fits)
#define ROWOFF(r) (((r) & 63) * PROWB + ((r) >> 6) * 64)

template <bool BIAS, bool RELU, bool OUTHALF>
__global__ void __launch_bounds__(128, 2)
tc_gemm(const h16* __restrict__ A_g, const h16* __restrict__ B_g,
        const float* __restrict__ bias, float* __restrict__ C,
        h16* __restrict__ Ch, int M, int N, int K)
{
    extern __shared__ char smem[];
    const int tid  = threadIdx.x;
    const int wid  = tid >> 5;
    const int lane = tid & 31;
    const int g    = lane >> 2;
    const int t    = lane & 3;
    const int wm   = wid & 1;      // M half (64)
    const int wn   = wid >> 1;     // N half (64)
    const int m0   = blockIdx.y * 128;
    const int n0   = blockIdx.x * 128;

    const uint32_t smem0 = smem_u32(smem);

    // ldmatrix per-lane offsets (proven direct-operand ordering)
    const int arow_l = (lane & 7) + ((lane >> 3) & 1) * 8;
    const uint32_t aoffL =
        (uint32_t)(arow_l * PROWB + wm * 64 + (lane >> 4) * 16);
    const int brow_l = ((lane >> 4) & 1) * 8 + (lane & 7);
    const uint32_t boffL =
        (uint32_t)(brow_l * PROWB + wn * 64 + ((lane >> 3) & 1) * 16);

    float acc[4][8][4];
#pragma unroll
    for (int i = 0; i < 4; i++)
#pragma unroll
        for (int j = 0; j < 8; j++)
#pragma unroll
            for (int c = 0; c < 4; c++) acc[i][j][c] = 0.f;

    const int S = K >> 5;   // BK = 32

    // per stage: A 8KB + B 8KB = 1024 x 16B chunks -> 8 per thread
    auto cp_stage = [&](int s, int b) {
        const int k0 = s << 5;
        char* base = smem + b * STAGEB;
#pragma unroll
        for (int i = 0; i < 8; i++) {
            const int sel   = i >> 2;                    // 0:A, 1:B
            const int inner = tid + (i & 3) * 128;       // 0..511
            const int r     = inner >> 2;                // 0..127
            const int c     = inner & 3;                 // 16B chunk
            const h16* src = (sel ? B_g : A_g) +
                             (size_t)((sel ? n0 : m0) + r) * K + k0 + c * 8;
            uint32_t dst = smem_u32(base + sel * TILEB + ROWOFF(r) + c * 16);
            CP_ASYNC16(dst, src);
        }
    };

    auto compute = [&](int b) {
        const uint32_t base = smem0 + b * STAGEB;
        const uint32_t Aa = base + aoffL;
        const uint32_t Bb = base + TILEB + boffL;
        uint32_t af[2][4][4], bf[2][4][4];
        // preload both k16 blocks' fragments (independent LSU work up front)
#pragma unroll
        for (int ks = 0; ks < 2; ks++) {
#pragma unroll
            for (int mt = 0; mt < 4; mt++)
                LDSM_X4(af[ks][mt], Aa + mt * (16 * PROWB) + ks * 32);
#pragma unroll
            for (int j = 0; j < 4; j++)
                LDSM_X4(bf[ks][j], Bb + j * (16 * PROWB) + ks * 32);
        }
#pragma unroll
        for (int ks = 0; ks < 2; ks++)
#pragma unroll
            for (int mt = 0; mt < 4; mt++)
#pragma unroll
                for (int nt = 0; nt < 8; nt++)
                    mma_f16(acc[mt][nt], af[ks][mt], &bf[ks][nt >> 1][(nt & 1) * 2]);
    };

    // ---- 4-stage pipeline, up to 3 groups in flight ----
    cp_stage(0, 0); CP_COMMIT();
    if (S > 1) { cp_stage(1, 1); CP_COMMIT(); }
    if (S > 2) { cp_stage(2, 2); CP_COMMIT(); }

    for (int s = 0; s < S; s++) {
        if      (s + 2 < S) CP_WAIT2();
        else if (s + 1 < S) CP_WAIT1();
        else                CP_WAIT0();
        __syncthreads();
        if (s + 3 < S) { cp_stage(s + 3, (s + 3) % NSTAGE); CP_COMMIT(); }
        compute(s % NSTAGE);
    }
    __syncthreads();

    // ---- epilogue: regs -> smem -> coalesced out ----
    float* stage = reinterpret_cast<float*>(smem);   // 128 x pitch 132
#pragma unroll
    for (int mt = 0; mt < 4; mt++) {
#pragma unroll
        for (int nt = 0; nt < 8; nt++) {
            int row = wm * 64 + mt * 16 + g;
            int col = wn * 64 + nt * 8 + t * 2;
            *reinterpret_cast<float2*>(&stage[row * 132 + col]) =
                make_float2(acc[mt][nt][0], acc[mt][nt][1]);
            *reinterpret_cast<float2*>(&stage[(row + 8) * 132 + col]) =
                make_float2(acc[mt][nt][2], acc[mt][nt][3]);
        }
    }
    __syncthreads();

#pragma unroll
    for (int i = 0; i < 32; i++) {
        int f   = i * 128 + tid;
        int row = f >> 5;
        int c4  = f & 31;
        float4 v = *reinterpret_cast<float4*>(&stage[row * 132 + c4 * 4]);
        if (BIAS) {
            float4 bv = *reinterpret_cast<const float4*>(bias + n0 + c4 * 4);
            v.x += bv.x; v.y += bv.y; v.z += bv.z; v.w += bv.w;
        }
        if (RELU) {
            v.x = fmaxf(v.x, 0.f); v.y = fmaxf(v.y, 0.f);
            v.z = fmaxf(v.z, 0.f); v.w = fmaxf(v.w, 0.f);
        }
        size_t oidx = (size_t)(m0 + row) * N + n0 + c4 * 4;
        if (OUTHALF) {
            *reinterpret_cast<__half2*>(Ch + oidx)     = __floats2half2_rn(v.x, v.y);
            *reinterpret_cast<__half2*>(Ch + oidx + 2) = __floats2half2_rn(v.z, v.w);
        } else {
            *reinterpret_cast<float4*>(C + oidx) = v;
        }
    }
}

// ===========================================================================
// Flash attention via mma.sync (R13/R14-proven, strided Q/KV)
// ===========================================================================
#define AT_PITCH 72

template <bool CAUSAL>
__global__ void __launch_bounds__(128)
attn_kernel(const h16* __restrict__ Qh, const h16* __restrict__ Kh,
            const h16* __restrict__ Vh, h16* __restrict__ Oh,
            int Lk, int qstr, int kvstr)
{
    __shared__ h16 sQ[64 * AT_PITCH];
    __shared__ h16 sK[3][32 * AT_PITCH];
    __shared__ h16 sV[3][32 * AT_PITCH];

    const int b    = blockIdx.z;
    const int h    = blockIdx.y;
    const int q0   = blockIdx.x * 64;
    const int tid  = threadIdx.x;
    const int lane = tid & 31;
    const int w    = tid >> 5;
    const int wr0  = w * 16;
    const int g    = lane >> 2;
    const int t    = lane & 3;

    const int nkt = CAUSAL ? ((q0 + 64) >> 5) : (Lk >> 5);

    auto cp_q = [&]() {
#pragma unroll
        for (int i = 0; i < 4; i++) {
            int idx = tid + i * 128;
            int r = idx >> 3, c = idx & 7;
            const h16* src = Qh + (size_t)(b * Sc + q0 + r) * qstr + h * 64 + c * 8;
            CP_ASYNC16(smem_u32(&sQ[r * AT_PITCH]) + c * 16, src);
        }
    };
    auto cp_kv = [&](int kt, int stg) {
        const int k0 = kt << 5;
#pragma unroll
        for (int i = 0; i < 4; i++) {
            int idx = tid + i * 128;
            int sel = idx >> 8;
            int rem = idx & 255;
            int r = rem >> 3, c = rem & 7;
            const h16* src = (sel ? Vh : Kh) +
                             (size_t)(b * Lk + k0 + r) * kvstr + h * 64 + c * 8;
            h16* dst = (sel ? sV[stg] : sK[stg]) + r * AT_PITCH;
            CP_ASYNC16(smem_u32(dst) + c * 16, src);
        }
    };

    cp_q();
    CP_COMMIT();
    cp_kv(0, 0);
    CP_COMMIT();
    if (nkt > 1) { cp_kv(1, 1); CP_COMMIT(); }
    if (nkt > 1) CP_WAIT2(); else CP_WAIT1();
    __syncthreads();

    uint32_t aq[4][4];
    {
        const int qrow = (lane & 7) + ((lane >> 3) & 1) * 8;
        const uint32_t qaddr = smem_u32(sQ) +
            (uint32_t)((wr0 + qrow) * (AT_PITCH * 2) + (lane >> 4) * 16);
#pragma unroll
        for (int ks = 0; ks < 4; ks++)
            LDSM_X4(aq[ks], qaddr + ks * 32);
    }

    const int kb_row = ((lane >> 4) & 1) * 8 + (lane & 7);
    const uint32_t kboff = (uint32_t)(kb_row * (AT_PITCH * 2) + ((lane >> 3) & 1) * 16);
    const int v_row = ((lane >> 3) & 1) * 8 + (lane & 7);
    const uint32_t vboff = (uint32_t)(v_row * (AT_PITCH * 2) + (lane >> 4) * 16);

    float oacc[8][4];
#pragma unroll
    for (int d = 0; d < 8; d++)
#pragma unroll
        for (int c = 0; c < 4; c++) oacc[d][c] = 0.f;
    float mrow0 = -1e30f, mrow1 = -1e30f, lrow0 = 0.f, lrow1 = 0.f;

    const int row0 = q0 + wr0 + g;
    const int row1 = row0 + 8;

    for (int kt = 0; kt < nkt; kt++) {
        if (kt + 1 < nkt) CP_WAIT1();
        else              CP_WAIT0();
        __syncthreads();
        if (kt + 2 < nkt) { cp_kv(kt + 2, (kt + 2) % 3); CP_COMMIT(); }

        const int stg = kt % 3;
        const int k0  = kt << 5;

        float s[4][4];
#pragma unroll
        for (int nt = 0; nt < 4; nt++)
#pragma unroll
            for (int c = 0; c < 4; c++) s[nt][c] = 0.f;
        const uint32_t Kb = smem_u32(sK[stg]) + kboff;
#pragma unroll
        for (int ks = 0; ks < 4; ks++) {
            uint32_t bk[2][4];
#pragma unroll
            for (int j = 0; j < 2; j++)
                LDSM_X4(bk[j], Kb + j * (16 * AT_PITCH * 2) + ks * 32);
#pragma unroll
            for (int nt = 0; nt < 4; nt++)
                mma_f16(s[nt], aq[ks], &bk[nt >> 1][(nt & 1) * 2]);
        }

#pragma unroll
        for (int nt = 0; nt < 4; nt++) {
            const int col0 = k0 + nt * 8 + 2 * t;
#pragma unroll
            for (int c = 0; c < 4; c++) s[nt][c] *= 0.125f;
            if (CAUSAL) {
                if (col0     > row0) s[nt][0] = -1e9f;
                if (col0 + 1 > row0) s[nt][1] = -1e9f;
                if (col0     > row1) s[nt][2] = -1e9f;
                if (col0 + 1 > row1) s[nt][3] = -1e9f;
            }
        }

        float ml0 = -1e30f, ml1 = -1e30f;
#pragma unroll
        for (int nt = 0; nt < 4; nt++) {
            ml0 = fmaxf(ml0, fmaxf(s[nt][0], s[nt][1]));
            ml1 = fmaxf(ml1, fmaxf(s[nt][2], s[nt][3]));
        }
        ml0 = fmaxf(ml0, __shfl_xor_sync(0xffffffffu, ml0, 1));
        ml0 = fmaxf(ml0, __shfl_xor_sync(0xffffffffu, ml0, 2));
        ml1 = fmaxf(ml1, __shfl_xor_sync(0xffffffffu, ml1, 1));
        ml1 = fmaxf(ml1, __shfl_xor_sync(0xffffffffu, ml1, 2));
        const float mn0 = fmaxf(mrow0, ml0);
        const float mn1 = fmaxf(mrow1, ml1);
        const float al0 = __expf(mrow0 - mn0);
        const float al1 = __expf(mrow1 - mn1);
        mrow0 = mn0; mrow1 = mn1;

        uint32_t pa[4][2];
        float ls0 = 0.f, ls1 = 0.f;
#pragma unroll
        for (int nt = 0; nt < 4; nt++) {
            float p0 = __expf(s[nt][0] - mn0);
            float p1 = __expf(s[nt][1] - mn0);
            float p2 = __expf(s[nt][2] - mn1);
            float p3 = __expf(s[nt][3] - mn1);
            ls0 += p0 + p1;
            ls1 += p2 + p3;
            __half2 h01 = __floats2half2_rn(p0, p1);
            __half2 h23 = __floats2half2_rn(p2, p3);
            pa[nt][0] = *reinterpret_cast<uint32_t*>(&h01);
            pa[nt][1] = *reinterpret_cast<uint32_t*>(&h23);
        }
        ls0 += __shfl_xor_sync(0xffffffffu, ls0, 1);
        ls0 += __shfl_xor_sync(0xffffffffu, ls0, 2);
        ls1 += __shfl_xor_sync(0xffffffffu, ls1, 1);
        ls1 += __shfl_xor_sync(0xffffffffu, ls1, 2);
        lrow0 = lrow0 * al0 + ls0;
        lrow1 = lrow1 * al1 + ls1;
#pragma unroll
        for (int d = 0; d < 8; d++) {
            oacc[d][0] *= al0; oacc[d][1] *= al0;
            oacc[d][2] *= al1; oacc[d][3] *= al1;
        }

        const uint32_t Vb = smem_u32(sV[stg]) + vboff;
#pragma unroll
        for (int ks2 = 0; ks2 < 2; ks2++) {
            uint32_t aP[4] = { pa[2 * ks2][0], pa[2 * ks2][1],
                               pa[2 * ks2 + 1][0], pa[2 * ks2 + 1][1] };
#pragma unroll
            for (int dp = 0; dp < 4; dp++) {
                uint32_t bv[4];
                LDSM_X4T(bv, Vb + ks2 * (16 * AT_PITCH * 2) + dp * 32);
                mma_f16(oacc[dp * 2 + 0], aP, &bv[0]);
                mma_f16(oacc[dp * 2 + 1], aP, &bv[2]);
            }
        }
    }

    const float inv0 = 1.f / lrow0;
    const float inv1 = 1.f / lrow1;
    h16* o0p = Oh + (size_t)(b * Sc + row0) * Dc + h * 64;
    h16* o1p = Oh + (size_t)(b * Sc + row1) * Dc + h * 64;
#pragma unroll
    for (int d = 0; d < 8; d++) {
        int col = d * 8 + 2 * t;
        *reinterpret_cast<__half2*>(o0p + col) =
            __floats2half2_rn(oacc[d][0] * inv0, oacc[d][1] * inv0);
        *reinterpret_cast<__half2*>(o1p + col) =
            __floats2half2_rn(oacc[d][2] * inv1, oacc[d][3] * inv1);
    }
}

// ---------------------------------------------------------------------------
// Residual + LayerNorm; writes fp32 + fp16 mirror
// ---------------------------------------------------------------------------
__global__ void __launch_bounds__(256)
ln_kernel(const float* __restrict__ x, const float* __restrict__ add,
          const float* __restrict__ s, const float* __restrict__ b,
          float* __restrict__ out, h16* __restrict__ oh)
{
    const int row = blockIdx.x;
    const int tid = threadIdx.x;
    const size_t base = (size_t)row * Dc;

    float v[4];
    float sum = 0.f, sq = 0.f;
#pragma unroll
    for (int i = 0; i < 4; i++) {
        int c = tid + i * 256;
        float val = x[base + c];
        if (add) val += add[base + c];
        v[i] = val;
        sum += val;
        sq  += val * val;
    }
#pragma unroll
    for (int off = 16; off > 0; off >>= 1) {
        sum += __shfl_xor_sync(0xffffffffu, sum, off);
        sq  += __shfl_xor_sync(0xffffffffu, sq, off);
    }
    __shared__ float s1[8], s2[8];
    __shared__ float mu_s, inv_s;
    int lane = tid & 31, wid = tid >> 5;
    if (lane == 0) { s1[wid] = sum; s2[wid] = sq; }
    __syncthreads();
    if (tid == 0) {
        float ts = 0.f, tq = 0.f;
#pragma unroll
        for (int i = 0; i < 8; i++) { ts += s1[i]; tq += s2[i]; }
        float mu  = ts * (1.f / Dc);
        float var = tq * (1.f / Dc) - mu * mu;
        mu_s  = mu;
        inv_s = rsqrtf(var + 1e-5f);
    }
    __syncthreads();
    float mu = mu_s, inv = inv_s;
#pragma unroll
    for (int i = 0; i < 4; i++) {
        int c = tid + i * 256;
        float r = (v[i] - mu) * inv * s[c] + b[c];
        out[base + c] = r;
        oh[base + c]  = __float2half(r);
    }
}

// ---------------------------------------------------------------------------
// Embedding gather + positional add; writes fp32 + fp16
// ---------------------------------------------------------------------------
__global__ void __launch_bounds__(256)
embed_kernel(const int* __restrict__ seq, const float* __restrict__ emb,
             const float* __restrict__ pos, float* __restrict__ x,
             h16* __restrict__ xh)
{
    const int row  = blockIdx.x;
    const int sidx = row & (Sc - 1);
    const int tok  = seq[row];
    const int tid  = threadIdx.x;
#pragma unroll
    for (int i = 0; i < 4; i++) {
        int c = tid + i * 256;
        float r = emb[(size_t)tok * Dc + c] + pos[(size_t)sidx * Dc + c];
        size_t o = (size_t)row * Dc + c;
        x[o]  = r;
        xh[o] = __float2half(r);
    }
}

// ---------------------------------------------------------------------------
// Host orchestration
// ---------------------------------------------------------------------------
template <bool BIAS, bool RELU, bool OUTHALF>
static void launch_gemm(const h16* a, const h16* b, const float* bias,
                        float* C, h16* ch, int M, int N, int K)
{
    cudaFuncSetAttribute(tc_gemm<BIAS, RELU, OUTHALF>,
                         cudaFuncAttributeMaxDynamicSharedMemorySize, GEMM_SMEM);
    dim3 grid(N / 128, M / 128);
    tc_gemm<BIAS, RELU, OUTHALF><<<grid, 128, GEMM_SMEM>>>(a, b, bias, C, ch, M, N, K);
}

extern "C" void kernel_launch(void* const* d_in, const int* in_sizes, int n_in,
                              void* d_out, int out_size)
{
    (void)in_sizes; (void)n_in; (void)out_size;

    const float* encoded      = (const float*)d_in[0];
    const int*   seq          = (const int*)  d_in[1];
    const float* input_embed  = (const float*)d_in[2];
    const float* output_embed = (const float*)d_in[3];
    const float* output_bias  = (const float*)d_in[4];
    const float* pos_embed    = (const float*)d_in[5];
    const float* Wq  = (const float*)d_in[6];
    const float* Wk  = (const float*)d_in[7];
    const float* Wv  = (const float*)d_in[8];
    const float* Wo  = (const float*)d_in[9];
    const float* Wqc = (const float*)d_in[10];
    const float* Wkc = (const float*)d_in[11];
    const float* Wvc = (const float*)d_in[12];
    const float* Woc = (const float*)d_in[13];
    const float* W1  = (const float*)d_in[14];
    const float* b1  = (const float*)d_in[15];
    const float* W2  = (const float*)d_in[16];
    const float* b2  = (const float*)d_in[17];
    const float* ln1s = (const float*)d_in[18];
    const float* ln1b = (const float*)d_in[19];
    const float* ln2s = (const float*)d_in[20];
    const float* ln2b = (const float*)d_in[21];
    const float* ln3s = (const float*)d_in[22];
    const float* ln3b = (const float*)d_in[23];
    const float* lnfs = (const float*)d_in[24];
    const float* lnfb = (const float*)d_in[25];

    float *x, *o;
    cudaGetSymbolAddress((void**)&x, g_x);
    cudaGetSymbolAddress((void**)&o, g_o);
    h16 *w, *xh, *qkvh, *qh, *kvh, *ah, *fh, *eh;
    cudaGetSymbolAddress((void**)&w,    g_w);
    cudaGetSymbolAddress((void**)&xh,   g_xh);
    cudaGetSymbolAddress((void**)&qkvh, g_qkvh);
    cudaGetSymbolAddress((void**)&qh,   g_qh);
    cudaGetSymbolAddress((void**)&kvh,  g_kvh);
    cudaGetSymbolAddress((void**)&ah,   g_ah);
    cudaGetSymbolAddress((void**)&fh,   g_fh);
    cudaGetSymbolAddress((void**)&eh,   g_eh);

    // ---- conversions: 2 launches ----
    convT_all<<<dim3(4096, 1, 60), dim3(32, 8)>>>(Wq, Wk, Wv, Wo, Wqc, Wkc, Wvc, Woc,
                                                  W1, W2, w);
    conv_all<<<dim3(Vc, 1, 2), 256>>>((const float4*)output_embed, (const float4*)encoded,
                                      (__half2*)(w + EOFF), (__half2*)eh);

    const int NR  = Bc * Sc;   // 4096
    const int NRE = Bc * Mc;   // 8192

    embed_kernel<<<NR, 256>>>(seq, input_embed, pos_embed, x, xh);

    const dim3 agrid(Sc / 64, Hc, Bc);   // (8, 16, 8)

    for (int i = 0; i < Lc; i++) {
        const size_t lb = (size_t)i * WOFF_LAYER;
        const h16* wl = w + lb;

        // ---- self attention: fused QKV ----
        launch_gemm<false, false, true>(xh, wl, nullptr, nullptr, qkvh, NR, 3 * Dc, Dc);
        attn_kernel<true><<<agrid, 128>>>(qkvh, qkvh + Dc, qkvh + 2 * Dc, ah,
                                          Sc, 3 * Dc, 3 * Dc);
        launch_gemm<false, false, false>(ah, wl + 3 * 1048576, nullptr, o, nullptr, NR, Dc, Dc);
        ln_kernel<<<NR, 256>>>(x, o, ln1s + (size_t)i * Dc, ln1b + (size_t)i * Dc, x, xh);

        // ---- cross attention: Q alone; fused KV ----
        launch_gemm<false, false, true>(xh, wl + 4 * 1048576, nullptr, nullptr, qh, NR, Dc, Dc);
        launch_gemm<false, false, true>(eh, wl + 5 * 1048576, nullptr, nullptr, kvh,
                                        NRE, 2 * Dc, Dc);
        attn_kernel<false><<<agrid, 128>>>(qh, kvh, kvh + Dc, ah, Mc, Dc, 2 * Dc);
        launch_gemm<false, false, false>(ah, wl + 7 * 1048576, nullptr, o, nullptr, NR, Dc, Dc);
        ln_kernel<<<NR, 256>>>(x, o, ln2s + (size_t)i * Dc, ln2b + (size_t)i * Dc, x, xh);

        // ---- FFN ----
        launch_gemm<true, true, true>(xh, wl + WOFF_W1, b1 + (size_t)i * DFc,
                                      nullptr, fh, NR, DFc, Dc);
        launch_gemm<true, false, false>(fh, wl + WOFF_W2, b2 + (size_t)i * Dc,
                                        o, nullptr, NR, Dc, DFc);
        ln_kernel<<<NR, 256>>>(x, o, ln3s + (size_t)i * Dc, ln3b + (size_t)i * Dc, x, xh);
    }

    // final norm + logits
    ln_kernel<<<NR, 256>>>(x, nullptr, lnfs, lnfb, x, xh);
    launch_gemm<true, false, false>(xh, w + EOFF, output_bias, (float*)d_out, nullptr,
                                    NR, Vc, Dc);
}